// round 1
// baseline (speedup 1.0000x reference)
#include <cuda_runtime.h>
#include <math.h>

// Model dims (fixed by the problem)
#define MTOK 2048     // B*T
#define TT   1024     // T
#define DD   512      // D
#define DI_  1024     // DI
#define DS_  16
#define LYR  4
#define VOC  32000

// ---------------- scratch (device globals: allocation-free) ----------------
__device__ float g_x   [MTOK * DD];       // residual stream
__device__ float g_h   [MTOK * DD];       // layernorm output
__device__ float g_xz  [MTOK * 2048];     // W_in output (u | z); reused as FFN hidden
__device__ float g_u   [MTOK * DI_];      // conv+silu output
__device__ float g_xdbl[MTOK * 64];       // x projection (dt_r | B | C)
__device__ float g_dt  [MTOK * DI_];
__device__ float g_y   [MTOK * DI_];      // gated scan output

// ---------------- embed: x = tok_emb[idx] + pos_emb[t] ----------------
__global__ void embed_kernel(const int* __restrict__ idx,
                             const float* __restrict__ tok,
                             const float* __restrict__ pos) {
    int i = blockIdx.x * 256 + threadIdx.x;      // float4 index over MTOK*128
    int token = i >> 7;
    int c = i & 127;
    int t = token & (TT - 1);
    int row = idx[token];
    float4 a = ((const float4*)tok)[row * 128 + c];
    float4 p = ((const float4*)pos)[t * 128 + c];
    a.x += p.x; a.y += p.y; a.z += p.z; a.w += p.w;
    ((float4*)g_x)[i] = a;
}

// ---------------- layernorm over D=512, one token per block (128 thr) -----
__global__ void ln_kernel(const float* __restrict__ x,
                          const float* __restrict__ g,
                          const float* __restrict__ bta,
                          float* __restrict__ out) {
    int token = blockIdx.x;
    int tid = threadIdx.x;
    float4 v = ((const float4*)(x + token * DD))[tid];
    float s = v.x + v.y + v.z + v.w;
    __shared__ float red[8];
    #pragma unroll
    for (int o = 16; o > 0; o >>= 1) s += __shfl_xor_sync(0xffffffffu, s, o);
    if ((tid & 31) == 0) red[tid >> 5] = s;
    __syncthreads();
    float mean = (red[0] + red[1] + red[2] + red[3]) * (1.0f / 512.0f);
    float dx = v.x - mean, dy = v.y - mean, dz = v.z - mean, dw = v.w - mean;
    float q = dx * dx + dy * dy + dz * dz + dw * dw;
    #pragma unroll
    for (int o = 16; o > 0; o >>= 1) q += __shfl_xor_sync(0xffffffffu, q, o);
    if ((tid & 31) == 0) red[4 + (tid >> 5)] = q;
    __syncthreads();
    float var = (red[4] + red[5] + red[6] + red[7]) * (1.0f / 512.0f);
    float r = rsqrtf(var + 1e-5f);
    float4 gg = ((const float4*)g)[tid];
    float4 bb = ((const float4*)bta)[tid];
    float4 o4;
    o4.x = dx * r * gg.x + bb.x;
    o4.y = dy * r * gg.y + bb.y;
    o4.z = dz * r * gg.z + bb.z;
    o4.w = dw * r * gg.w + bb.w;
    ((float4*)(out + token * DD))[tid] = o4;
}

// ---------------- generic tiled SGEMM: C[M,N] = A[M,K] @ Bw[N,K]^T --------
#define EP_BIAS 1
#define EP_RELU 2
#define EP_SOFTPLUS 4
#define EP_RES 8

template <int BM, int BN, int BK, int TM, int TN, int EPI>
__global__ __launch_bounds__(256) void gemm_kernel(
    int M, int N, int K, int lda,
    const float* __restrict__ A, const float* __restrict__ Bw,
    const float* __restrict__ bias, const float* __restrict__ res,
    float* __restrict__ C) {
    __shared__ float As[BK][BM + 4];
    __shared__ float Bs[BK][BN + 4];
    const int bm = blockIdx.y * BM, bn = blockIdx.x * BN;
    const int tid = threadIdx.x;
    constexpr int TX = BN / TN;                 // threads along n
    const int tn = (tid % TX) * TN;
    const int tm = (tid / TX) * TM;

    float acc[TM][TN];
    #pragma unroll
    for (int i = 0; i < TM; i++)
        #pragma unroll
        for (int j = 0; j < TN; j++) acc[i][j] = 0.0f;

    const float* Ab = A + (long)bm * lda;
    const float* Bb = Bw + (long)bn * K;

    for (int kt = 0; kt < K; kt += BK) {
        #pragma unroll
        for (int idx = tid; idx < BM * BK; idx += 256) {
            int m = idx / BK, k = idx % BK;
            As[k][m] = Ab[m * lda + kt + k];
        }
        #pragma unroll
        for (int idx = tid; idx < BN * BK; idx += 256) {
            int n = idx / BK, k = idx % BK;
            Bs[k][n] = Bb[n * K + kt + k];
        }
        __syncthreads();
        #pragma unroll
        for (int k = 0; k < BK; k++) {
            float a[TM], b[TN];
            #pragma unroll
            for (int i = 0; i < TM; i++) a[i] = As[k][tm + i];
            #pragma unroll
            for (int j = 0; j < TN; j++) b[j] = Bs[k][tn + j];
            #pragma unroll
            for (int i = 0; i < TM; i++)
                #pragma unroll
                for (int j = 0; j < TN; j++)
                    acc[i][j] = fmaf(a[i], b[j], acc[i][j]);
        }
        __syncthreads();
    }

    #pragma unroll
    for (int i = 0; i < TM; i++) {
        int row = bm + tm + i;
        #pragma unroll
        for (int j = 0; j < TN; j++) {
            int col = bn + tn + j;
            float v = acc[i][j];
            if (EPI & EP_BIAS) v += bias[col];
            if (EPI & EP_RELU) v = v > 0.0f ? v : 0.0f;
            if (EPI & EP_SOFTPLUS) v = (v > 20.0f) ? v : log1pf(expf(v));
            if (EPI & EP_RES) v += res[(long)row * N + col];
            C[(long)row * N + col] = v;
        }
    }
}

// ---------------- causal depthwise conv (DC=4) + SiLU ---------------------
__global__ void conv_silu_kernel(const float* __restrict__ w,
                                 const float* __restrict__ cb) {
    int i = blockIdx.x * 256 + threadIdx.x;     // MTOK*DI
    int token = i >> 10;
    int d = i & (DI_ - 1);
    int t = token & (TT - 1);
    float acc = cb[d];
    #pragma unroll
    for (int j = 0; j < 4; j++) {
        int tt = t - 3 + j;
        if (tt >= 0) acc += g_xz[(token - 3 + j) * 2048 + d] * w[d * 4 + j];
    }
    float sg = 1.0f / (1.0f + __expf(-acc));
    g_u[i] = acc * sg;
}

// ---------------- selective scan: one thread per (b, d, s) ----------------
// half-warp (16 lanes) shfl reduction over DS; 4-step software pipeline.
__global__ void scan_kernel(const float* __restrict__ A_log,
                            const float* __restrict__ D_p) {
    int gid = blockIdx.x * 128 + threadIdx.x;   // 32768 threads
    int s = gid & 15;
    int bd = gid >> 4;                           // b*DI + d
    int d = bd & (DI_ - 1);
    int b = bd >> 10;

    float a = -expf(A_log[d * DS_ + s]);
    float Dp = D_p[d];
    float h = 0.0f;

    const int tok0 = b * TT;
    const float* pdt = g_dt + (long)tok0 * DI_ + d;
    const float* pu  = g_u  + (long)tok0 * DI_ + d;
    const float* pB  = g_xdbl + (long)tok0 * 64 + 32 + s;
    const float* pC  = g_xdbl + (long)tok0 * 64 + 48 + s;
    const float* pz  = g_xz + (long)tok0 * 2048 + DI_ + d;
    float* py = g_y + (long)tok0 * DI_ + d;

    float cd[4], cu[4], cB[4], cC[4], cz[4];
    #pragma unroll
    for (int j = 0; j < 4; j++) {
        cd[j] = pdt[j * DI_]; cu[j] = pu[j * DI_];
        cB[j] = pB[j * 64];   cC[j] = pC[j * 64];
        cz[j] = pz[j * 2048];
    }

    for (int tg = 0; tg < TT / 4; tg++) {
        float nd[4], nu[4], nB[4], nC[4], nz[4];
        if (tg < TT / 4 - 1) {
            int t1 = (tg + 1) * 4;
            #pragma unroll
            for (int j = 0; j < 4; j++) {
                nd[j] = pdt[(t1 + j) * DI_]; nu[j] = pu[(t1 + j) * DI_];
                nB[j] = pB[(t1 + j) * 64];   nC[j] = pC[(t1 + j) * 64];
                nz[j] = pz[(t1 + j) * 2048];
            }
        }
        #pragma unroll
        for (int j = 0; j < 4; j++) {
            int t = tg * 4 + j;
            float dtv = cd[j], uv = cu[j];
            h = __expf(dtv * a) * h + (dtv * uv) * cB[j];
            float yp = h * cC[j];
            yp += __shfl_xor_sync(0xffffffffu, yp, 8);
            yp += __shfl_xor_sync(0xffffffffu, yp, 4);
            yp += __shfl_xor_sync(0xffffffffu, yp, 2);
            yp += __shfl_xor_sync(0xffffffffu, yp, 1);
            if (s == 0) {
                float zv = cz[j];
                float yv = yp + uv * Dp;
                py[t * DI_] = yv * (zv / (1.0f + __expf(-zv)));
            }
        }
        if (tg < TT / 4 - 1) {
            #pragma unroll
            for (int j = 0; j < 4; j++) {
                cd[j] = nd[j]; cu[j] = nu[j];
                cB[j] = nB[j]; cC[j] = nC[j]; cz[j] = nz[j];
            }
        }
    }
}

// ---------------- host orchestration --------------------------------------
extern "C" void kernel_launch(void* const* d_in, const int* in_sizes, int n_in,
                              void* d_out, int out_size) {
    const int*   idx   = (const int*)d_in[0];
    const float* tok   = (const float*)d_in[1];
    const float* pos   = (const float*)d_in[2];
    const float* ln1g  = (const float*)d_in[3];
    const float* ln1b  = (const float*)d_in[4];
    const float* W_in  = (const float*)d_in[5];
    const float* convw = (const float*)d_in[6];
    const float* convb = (const float*)d_in[7];
    const float* W_xp  = (const float*)d_in[8];
    const float* W_dt  = (const float*)d_in[9];
    const float* b_dt  = (const float*)d_in[10];
    const float* A_log = (const float*)d_in[11];
    const float* D_p   = (const float*)d_in[12];
    const float* W_out = (const float*)d_in[13];
    const float* ln2g  = (const float*)d_in[14];
    const float* ln2b  = (const float*)d_in[15];
    const float* W_f1  = (const float*)d_in[16];
    const float* b_f1  = (const float*)d_in[17];
    const float* W_f2  = (const float*)d_in[18];
    const float* b_f2  = (const float*)d_in[19];
    const float* lm_w  = (const float*)d_in[20];
    const float* lm_b  = (const float*)d_in[21];
    float* out = (float*)d_out;

    float *px, *ph, *pxz, *pu, *pxd, *pdt, *py;
    cudaGetSymbolAddress((void**)&px,  g_x);
    cudaGetSymbolAddress((void**)&ph,  g_h);
    cudaGetSymbolAddress((void**)&pxz, g_xz);
    cudaGetSymbolAddress((void**)&pu,  g_u);
    cudaGetSymbolAddress((void**)&pxd, g_xdbl);
    cudaGetSymbolAddress((void**)&pdt, g_dt);
    cudaGetSymbolAddress((void**)&py,  g_y);

    embed_kernel<<<1024, 256>>>(idx, tok, pos);

    for (int l = 0; l < LYR; l++) {
        // h = LN1(x)
        ln_kernel<<<MTOK, 128>>>(px, ln1g + l * DD, ln1b + l * DD, ph);
        // xz = h @ W_in^T   [2048, 2048]
        gemm_kernel<128, 128, 8, 8, 8, 0><<<dim3(16, 16), 256>>>(
            MTOK, 2048, DD, DD, ph, W_in + (long)l * 2048 * DD,
            nullptr, nullptr, pxz);
        // u = silu(conv(xz[:, :DI]))
        conv_silu_kernel<<<MTOK * DI_ / 256, 256>>>(convw + l * DI_ * 4,
                                                    convb + l * DI_);
        // x_dbl = u @ W_xp^T   [2048, 64]
        gemm_kernel<64, 64, 8, 4, 4, 0><<<dim3(1, 32), 256>>>(
            MTOK, 64, DI_, DI_, pu, W_xp + (long)l * 64 * DI_,
            nullptr, nullptr, pxd);
        // dt = softplus(x_dbl[:, :32] @ W_dt^T + b_dt)   [2048, 1024]
        gemm_kernel<64, 64, 8, 4, 4, EP_BIAS | EP_SOFTPLUS><<<dim3(16, 32), 256>>>(
            MTOK, DI_, 32, 64, pxd, W_dt + (long)l * DI_ * 32,
            b_dt + l * DI_, nullptr, pdt);
        // selective scan -> gated y
        scan_kernel<<<256, 128>>>(A_log + (long)l * DI_ * DS_, D_p + l * DI_);
        // x += y @ W_out^T   [2048, 512]
        gemm_kernel<128, 128, 8, 8, 8, EP_RES><<<dim3(4, 16), 256>>>(
            MTOK, DD, DI_, DI_, py, W_out + (long)l * DD * DI_,
            nullptr, px, px);
        // h = LN2(x)
        ln_kernel<<<MTOK, 128>>>(px, ln2g + l * DD, ln2b + l * DD, ph);
        // ffn hidden = relu(h @ W_f1^T + b_f1)   [2048, 2048] (reuse g_xz)
        gemm_kernel<128, 128, 8, 8, 8, EP_BIAS | EP_RELU><<<dim3(16, 16), 256>>>(
            MTOK, 2048, DD, DD, ph, W_f1 + (long)l * 2048 * DD,
            b_f1 + l * 2048, nullptr, pxz);
        // x += hidden @ W_f2^T + b_f2   [2048, 512]
        gemm_kernel<128, 128, 8, 8, 8, EP_BIAS | EP_RES><<<dim3(4, 16), 256>>>(
            MTOK, DD, 2048, 2048, pxz, W_f2 + (long)l * DD * 2048,
            b_f2 + l * DD, px, px);
    }

    // logits = x @ lm_w^T + lm_b   [2048, 32000]
    gemm_kernel<128, 128, 8, 8, 8, EP_BIAS><<<dim3(VOC / 128, 16), 256>>>(
        MTOK, VOC, DD, DD, px, lm_w, lm_b, nullptr, out);
}

// round 5
// speedup vs baseline: 2.2880x; 2.2880x over previous
#include <cuda_runtime.h>
#include <cuda_bf16.h>
#include <math.h>
#include <stdint.h>

#define MTOK 2048
#define TT   1024
#define DD   512
#define DI_  1024
#define DS_  16
#define LYR  4
#define VOC  32000

// ===================== PTX helpers (plain sm_103-safe) =====================
__device__ __forceinline__ uint32_t smem_u32(const void* p) {
    uint32_t a;
    asm("{ .reg .u64 t; cvta.to.shared.u64 t, %1; cvt.u32.u64 %0, t; }"
        : "=r"(a) : "l"(p));
    return a;
}
#define CP16(dst, src) \
    asm volatile("cp.async.cg.shared.global [%0], [%1], 16;" \
                 :: "r"(dst), "l"(src) : "memory")
#define CP_COMMIT() asm volatile("cp.async.commit_group;" ::: "memory")
#define CP_WAIT0()  asm volatile("cp.async.wait_group 0;" ::: "memory")
#define CP_WAIT1()  asm volatile("cp.async.wait_group 1;" ::: "memory")

__device__ __forceinline__ void ldsm4(uint32_t* r, uint32_t addr) {
    asm volatile("ldmatrix.sync.aligned.m8n8.x4.shared.b16 {%0,%1,%2,%3}, [%4];"
                 : "=r"(r[0]), "=r"(r[1]), "=r"(r[2]), "=r"(r[3]) : "r"(addr));
}
__device__ __forceinline__ void mma16816(float* d, const uint32_t* a,
                                         const uint32_t* b) {
    asm volatile(
        "mma.sync.aligned.m16n8k16.row.col.f32.bf16.bf16.f32 "
        "{%0,%1,%2,%3}, {%4,%5,%6,%7}, {%8,%9}, {%0,%1,%2,%3};"
        : "+f"(d[0]), "+f"(d[1]), "+f"(d[2]), "+f"(d[3])
        : "r"(a[0]), "r"(a[1]), "r"(a[2]), "r"(a[3]), "r"(b[0]), "r"(b[1]));
}

__device__ __forceinline__ void split2(float v, __nv_bfloat16& h, __nv_bfloat16& l) {
    h = __float2bfloat16(v);
    l = __float2bfloat16(v - __bfloat162float(h));
}

// ===================== device-global scratch (16B-access aligned) =========
__device__ __align__(256) float g_x   [MTOK * DD];
__device__ __align__(256) float g_xz  [MTOK * 2048];
__device__ __align__(256) float g_u   [MTOK * DI_];
__device__ __align__(256) float g_xdbl[MTOK * 64];
__device__ __align__(256) float g_dt  [MTOK * DI_];

__device__ __align__(256) __nv_bfloat16 g_hh[MTOK * DD];
__device__ __align__(256) __nv_bfloat16 g_hl[MTOK * DD];
__device__ __align__(256) __nv_bfloat16 g_uh[MTOK * DI_];
__device__ __align__(256) __nv_bfloat16 g_ul[MTOK * DI_];
__device__ __align__(256) __nv_bfloat16 g_xdh[MTOK * 64];
__device__ __align__(256) __nv_bfloat16 g_xdl[MTOK * 64];
__device__ __align__(256) __nv_bfloat16 g_yh[MTOK * DI_];
__device__ __align__(256) __nv_bfloat16 g_yl[MTOK * DI_];
__device__ __align__(256) __nv_bfloat16 g_hidh[MTOK * 2048];
__device__ __align__(256) __nv_bfloat16 g_hidl[MTOK * 2048];
__device__ __align__(256) __nv_bfloat16 g_xh[MTOK * DD];
__device__ __align__(256) __nv_bfloat16 g_xl[MTOK * DD];

__device__ __align__(256) __nv_bfloat16 g_Winh [LYR * 2048 * DD];
__device__ __align__(256) __nv_bfloat16 g_Winl [LYR * 2048 * DD];
__device__ __align__(256) __nv_bfloat16 g_Wxph [LYR * 64 * DI_];
__device__ __align__(256) __nv_bfloat16 g_Wxpl [LYR * 64 * DI_];
__device__ __align__(256) __nv_bfloat16 g_Wdth [LYR * DI_ * 32];
__device__ __align__(256) __nv_bfloat16 g_Wdtl [LYR * DI_ * 32];
__device__ __align__(256) __nv_bfloat16 g_Wouth[LYR * DD * DI_];
__device__ __align__(256) __nv_bfloat16 g_Woutl[LYR * DD * DI_];
__device__ __align__(256) __nv_bfloat16 g_Wf1h [LYR * 2048 * DD];
__device__ __align__(256) __nv_bfloat16 g_Wf1l [LYR * 2048 * DD];
__device__ __align__(256) __nv_bfloat16 g_Wf2h [LYR * DD * 2048];
__device__ __align__(256) __nv_bfloat16 g_Wf2l [LYR * DD * 2048];
__device__ __align__(256) __nv_bfloat16 g_lmh  [VOC * DD];
__device__ __align__(256) __nv_bfloat16 g_lml  [VOC * DD];

// ===================== small kernels ======================================
__global__ void embed_kernel(const int* __restrict__ idx,
                             const float* __restrict__ tok,
                             const float* __restrict__ pos) {
    int i = blockIdx.x * 256 + threadIdx.x;
    int token = i >> 7;
    int c = i & 127;
    int t = token & (TT - 1);
    int row = idx[token];
    float4 a = ((const float4*)tok)[row * 128 + c];
    float4 p = ((const float4*)pos)[t * 128 + c];
    a.x += p.x; a.y += p.y; a.z += p.z; a.w += p.w;
    ((float4*)g_x)[i] = a;
}

__global__ void split_kernel(const float* __restrict__ in,
                             __nv_bfloat16* __restrict__ hi,
                             __nv_bfloat16* __restrict__ lo, int n4) {
    int i = blockIdx.x * 256 + threadIdx.x;
    if (i >= n4) return;
    float4 v = ((const float4*)in)[i];
    __nv_bfloat16 h0, h1, h2, h3, l0, l1, l2, l3;
    split2(v.x, h0, l0); split2(v.y, h1, l1);
    split2(v.z, h2, l2); split2(v.w, h3, l3);
    ((__nv_bfloat162*)hi)[i * 2 + 0] = __nv_bfloat162{h0, h1};
    ((__nv_bfloat162*)hi)[i * 2 + 1] = __nv_bfloat162{h2, h3};
    ((__nv_bfloat162*)lo)[i * 2 + 0] = __nv_bfloat162{l0, l1};
    ((__nv_bfloat162*)lo)[i * 2 + 1] = __nv_bfloat162{l2, l3};
}

__global__ void ln_kernel(const float* __restrict__ x,
                          const float* __restrict__ g,
                          const float* __restrict__ bta,
                          __nv_bfloat16* __restrict__ oh,
                          __nv_bfloat16* __restrict__ ol) {
    int token = blockIdx.x;
    int tid = threadIdx.x;
    float4 v = ((const float4*)(x + token * DD))[tid];
    float s = v.x + v.y + v.z + v.w;
    __shared__ float red[8];
    #pragma unroll
    for (int o = 16; o > 0; o >>= 1) s += __shfl_xor_sync(0xffffffffu, s, o);
    if ((tid & 31) == 0) red[tid >> 5] = s;
    __syncthreads();
    float mean = (red[0] + red[1] + red[2] + red[3]) * (1.0f / 512.0f);
    float dx = v.x - mean, dy = v.y - mean, dz = v.z - mean, dw = v.w - mean;
    float q = dx * dx + dy * dy + dz * dz + dw * dw;
    #pragma unroll
    for (int o = 16; o > 0; o >>= 1) q += __shfl_xor_sync(0xffffffffu, q, o);
    if ((tid & 31) == 0) red[4 + (tid >> 5)] = q;
    __syncthreads();
    float var = (red[4] + red[5] + red[6] + red[7]) * (1.0f / 512.0f);
    float r = rsqrtf(var + 1e-5f);
    float4 gg = ((const float4*)g)[tid];
    float4 bb = ((const float4*)bta)[tid];
    float o0 = dx * r * gg.x + bb.x, o1 = dy * r * gg.y + bb.y;
    float o2 = dz * r * gg.z + bb.z, o3 = dw * r * gg.w + bb.w;
    __nv_bfloat16 h0, h1, h2, h3, l0, l1, l2, l3;
    split2(o0, h0, l0); split2(o1, h1, l1); split2(o2, h2, l2); split2(o3, h3, l3);
    ((__nv_bfloat162*)(oh + token * DD))[tid * 2 + 0] = __nv_bfloat162{h0, h1};
    ((__nv_bfloat162*)(oh + token * DD))[tid * 2 + 1] = __nv_bfloat162{h2, h3};
    ((__nv_bfloat162*)(ol + token * DD))[tid * 2 + 0] = __nv_bfloat162{l0, l1};
    ((__nv_bfloat162*)(ol + token * DD))[tid * 2 + 1] = __nv_bfloat162{l2, l3};
}

__global__ void conv_silu_kernel(const float* __restrict__ w,
                                 const float* __restrict__ cb) {
    int i = blockIdx.x * 256 + threadIdx.x;
    int token = i >> 10;
    int d = i & (DI_ - 1);
    int t = token & (TT - 1);
    float acc = cb[d];
    #pragma unroll
    for (int j = 0; j < 4; j++) {
        int tt = t - 3 + j;
        if (tt >= 0) acc += g_xz[(token - 3 + j) * 2048 + d] * w[d * 4 + j];
    }
    float sg = 1.0f / (1.0f + __expf(-acc));
    float uv = acc * sg;
    g_u[i] = uv;
    __nv_bfloat16 h, l; split2(uv, h, l);
    g_uh[i] = h; g_ul[i] = l;
}

__global__ void scan_kernel(const float* __restrict__ A_log,
                            const float* __restrict__ D_p) {
    int gid = blockIdx.x * 128 + threadIdx.x;
    int s = gid & 15;
    int bd = gid >> 4;
    int d = bd & (DI_ - 1);
    int b = bd >> 10;

    float a = -expf(A_log[d * DS_ + s]);
    float Dp = D_p[d];
    float h = 0.0f;

    const int tok0 = b * TT;
    const float* pdt = g_dt + (long)tok0 * DI_ + d;
    const float* pu  = g_u  + (long)tok0 * DI_ + d;
    const float* pB  = g_xdbl + (long)tok0 * 64 + 32 + s;
    const float* pC  = g_xdbl + (long)tok0 * 64 + 48 + s;
    const float* pz  = g_xz + (long)tok0 * 2048 + DI_ + d;
    __nv_bfloat16* pyh = g_yh + (long)tok0 * DI_ + d;
    __nv_bfloat16* pyl = g_yl + (long)tok0 * DI_ + d;

    float cd[4], cu[4], cB[4], cC[4], cz[4];
    #pragma unroll
    for (int j = 0; j < 4; j++) {
        cd[j] = pdt[j * DI_]; cu[j] = pu[j * DI_];
        cB[j] = pB[j * 64];   cC[j] = pC[j * 64];
        cz[j] = pz[j * 2048];
    }

    for (int tg = 0; tg < TT / 4; tg++) {
        float nd[4], nu[4], nB[4], nC[4], nz[4];
        if (tg < TT / 4 - 1) {
            int t1 = (tg + 1) * 4;
            #pragma unroll
            for (int j = 0; j < 4; j++) {
                nd[j] = pdt[(t1 + j) * DI_]; nu[j] = pu[(t1 + j) * DI_];
                nB[j] = pB[(t1 + j) * 64];   nC[j] = pC[(t1 + j) * 64];
                nz[j] = pz[(t1 + j) * 2048];
            }
        }
        #pragma unroll
        for (int j = 0; j < 4; j++) {
            int t = tg * 4 + j;
            float dtv = cd[j], uv = cu[j];
            h = __expf(dtv * a) * h + (dtv * uv) * cB[j];
            float yp = h * cC[j];
            yp += __shfl_xor_sync(0xffffffffu, yp, 8);
            yp += __shfl_xor_sync(0xffffffffu, yp, 4);
            yp += __shfl_xor_sync(0xffffffffu, yp, 2);
            yp += __shfl_xor_sync(0xffffffffu, yp, 1);
            if (s == 0) {
                float zv = cz[j];
                float yv = yp + uv * Dp;
                float ov = yv * (zv / (1.0f + __expf(-zv)));
                __nv_bfloat16 hh, ll; split2(ov, hh, ll);
                pyh[t * DI_] = hh; pyl[t * DI_] = ll;
            }
        }
        if (tg < TT / 4 - 1) {
            #pragma unroll
            for (int j = 0; j < 4; j++) {
                cd[j] = nd[j]; cu[j] = nu[j];
                cB[j] = nB[j]; cC[j] = nC[j]; cz[j] = nz[j];
            }
        }
    }
}

// ===================== HMMA split-bf16 GEMM ===============================
// C[M,N] = A[M,K] @ B[N,K]^T via Ah*Bh + Ah*Bl + Al*Bh (fp32 accum)
#define F_BIAS 1
#define F_RELU 2
#define F_SOFT 4
#define F_RES  8
#define F_WF32 16
#define F_WPAIR 32

template <int BN, int FLAGS>
__global__ __launch_bounds__(256) void tgemm(
    int M, int N, int K, int lda, int ldb,
    const __nv_bfloat16* __restrict__ Ah, const __nv_bfloat16* __restrict__ Al,
    const __nv_bfloat16* __restrict__ Bh, const __nv_bfloat16* __restrict__ Bl,
    const float* __restrict__ bias, const float* __restrict__ res,
    float* __restrict__ Cf,
    __nv_bfloat16* __restrict__ Ch, __nv_bfloat16* __restrict__ Cl) {
    extern __shared__ char smem[];
    constexpr int PITCH = 80;                 // bytes/row of 32 bf16 (+8 pad)
    constexpr int ASZ = 128 * PITCH;          // one A tile (h or l)
    constexpr int BSZ = BN * PITCH;
    constexpr int STAGE = 2 * ASZ + 2 * BSZ;  // Ah | Al | Bh | Bl
    constexpr int NT = BN / 32;               // n-tiles (8 wide) per warp
    const int tid = threadIdx.x, lane = tid & 31, wid = tid >> 5;
    const int wm = wid >> 2, wn = wid & 3;    // 2 x 4 warp grid
    const int bm = blockIdx.y * 128, bn = blockIdx.x * BN;
    const uint32_t sb = smem_u32(smem);

    float acc[4][NT][4];
    #pragma unroll
    for (int i = 0; i < 4; i++)
        #pragma unroll
        for (int j = 0; j < NT; j++)
            #pragma unroll
            for (int q = 0; q < 4; q++) acc[i][j][q] = 0.0f;

    const int nc = K / 32;

    auto prefetch = [&](int c, int s) {
        const uint32_t sbase = sb + s * STAGE;
        const int k0 = c * 32;
        #pragma unroll
        for (int i = 0; i < 2; i++) {           // A: 512 16B chunks (h each)
            int ch = tid + i * 256;
            int row = ch >> 2, kc = ch & 3;
            uint32_t doff = row * PITCH + kc * 16;
            size_t goff = (size_t)(bm + row) * lda + k0 + kc * 8;
            CP16(sbase + doff, (const char*)(Ah + goff));
            CP16(sbase + ASZ + doff, (const char*)(Al + goff));
        }
        #pragma unroll
        for (int i = 0; i < BN / 64; i++) {     // B: BN*4 chunks
            int ch = tid + i * 256;
            int row = ch >> 2, kc = ch & 3;
            uint32_t doff = row * PITCH + kc * 16;
            size_t goff = (size_t)(bn + row) * ldb + k0 + kc * 8;
            CP16(sbase + 2 * ASZ + doff, (const char*)(Bh + goff));
            CP16(sbase + 2 * ASZ + BSZ + doff, (const char*)(Bl + goff));
        }
    };

    auto compute = [&](int s) {
        const uint32_t sbase = sb + s * STAGE;
        const uint32_t arow = (uint32_t)(lane & 15);
        const uint32_t asel = (uint32_t)((lane >> 4) * 16);
        #pragma unroll
        for (int kk = 0; kk < 2; kk++) {
            const uint32_t kb = kk * 32;        // byte offset of k half
            uint32_t ah[4][4], al[4][4];
            #pragma unroll
            for (int mi = 0; mi < 4; mi++) {
                uint32_t ad = sbase + (wm * 64 + mi * 16 + arow) * PITCH + kb + asel;
                ldsm4(ah[mi], ad);
                ldsm4(al[mi], ad + ASZ);
            }
            uint32_t bh[NT][2], bl[NT][2];
            #pragma unroll
            for (int p = 0; p < NT / 2; p++) {
                uint32_t bd = sbase + 2 * ASZ +
                              (wn * (BN / 4) + p * 16 + arow) * PITCH + kb + asel;
                uint32_t t4[4];
                ldsm4(t4, bd);
                bh[2*p][0] = t4[0]; bh[2*p][1] = t4[2];
                bh[2*p+1][0] = t4[1]; bh[2*p+1][1] = t4[3];
                ldsm4(t4, bd + BSZ);
                bl[2*p][0] = t4[0]; bl[2*p][1] = t4[2];
                bl[2*p+1][0] = t4[1]; bl[2*p+1][1] = t4[3];
            }
            #pragma unroll
            for (int mi = 0; mi < 4; mi++)
                #pragma unroll
                for (int ni = 0; ni < NT; ni++) {
                    mma16816(acc[mi][ni], ah[mi], bh[ni]);
                    mma16816(acc[mi][ni], ah[mi], bl[ni]);
                    mma16816(acc[mi][ni], al[mi], bh[ni]);
                }
        }
    };

    prefetch(0, 0);
    CP_COMMIT();
    for (int c = 0; c < nc; c++) {
        if (c + 1 < nc) {
            prefetch(c + 1, (c + 1) & 1);
            CP_COMMIT();
            CP_WAIT1();
        } else {
            CP_WAIT0();
        }
        __syncthreads();
        compute(c & 1);
        __syncthreads();
    }

    // ---- epilogue: direct fragment stores ----
    #pragma unroll
    for (int mi = 0; mi < 4; mi++) {
        #pragma unroll
        for (int ni = 0; ni < NT; ni++) {
            const int r0 = bm + wm * 64 + mi * 16 + (lane >> 2);
            const int c0 = bn + wn * (BN / 4) + ni * 8 + (lane & 3) * 2;
            #pragma unroll
            for (int hh = 0; hh < 2; hh++) {
                const int r = r0 + hh * 8;
                float v0 = acc[mi][ni][hh * 2 + 0];
                float v1 = acc[mi][ni][hh * 2 + 1];
                if (FLAGS & F_BIAS) { v0 += bias[c0]; v1 += bias[c0 + 1]; }
                if (FLAGS & F_RELU) { v0 = fmaxf(v0, 0.f); v1 = fmaxf(v1, 0.f); }
                if (FLAGS & F_SOFT) {
                    v0 = (v0 > 20.f) ? v0 : log1pf(expf(v0));
                    v1 = (v1 > 20.f) ? v1 : log1pf(expf(v1));
                }
                if (FLAGS & F_RES) {
                    float2 rr = *(const float2*)(res + (size_t)r * N + c0);
                    v0 += rr.x; v1 += rr.y;
                }
                if (FLAGS & F_WF32) {
                    float2 o2 = make_float2(v0, v1);
                    *(float2*)(Cf + (size_t)r * N + c0) = o2;
                }
                if (FLAGS & F_WPAIR) {
                    __nv_bfloat16 h0, h1, l0, l1;
                    split2(v0, h0, l0); split2(v1, h1, l1);
                    *(__nv_bfloat162*)(Ch + (size_t)r * N + c0) = __nv_bfloat162{h0, h1};
                    *(__nv_bfloat162*)(Cl + (size_t)r * N + c0) = __nv_bfloat162{l0, l1};
                }
            }
        }
    }
}

// ===================== host orchestration =================================
template <int BN, int FLAGS>
static void launch_tgemm(int M, int N, int K, int lda, int ldb,
                         const __nv_bfloat16* Ah, const __nv_bfloat16* Al,
                         const __nv_bfloat16* Bh, const __nv_bfloat16* Bl,
                         const float* bias, const float* res,
                         float* Cf, __nv_bfloat16* Ch, __nv_bfloat16* Cl) {
    constexpr int PITCH = 80;
    constexpr int STAGE = 2 * 128 * PITCH + 2 * BN * PITCH;
    const int smem_bytes = 2 * STAGE;
    cudaFuncSetAttribute(tgemm<BN, FLAGS>,
                         cudaFuncAttributeMaxDynamicSharedMemorySize, smem_bytes);
    dim3 grid(N / BN, M / 128);
    tgemm<BN, FLAGS><<<grid, 256, smem_bytes>>>(M, N, K, lda, ldb,
        Ah, Al, Bh, Bl, bias, res, Cf, Ch, Cl);
}

extern "C" void kernel_launch(void* const* d_in, const int* in_sizes, int n_in,
                              void* d_out, int out_size) {
    const int*   idx   = (const int*)d_in[0];
    const float* tok   = (const float*)d_in[1];
    const float* pos   = (const float*)d_in[2];
    const float* ln1g  = (const float*)d_in[3];
    const float* ln1b  = (const float*)d_in[4];
    const float* W_in  = (const float*)d_in[5];
    const float* convw = (const float*)d_in[6];
    const float* convb = (const float*)d_in[7];
    const float* W_xp  = (const float*)d_in[8];
    const float* W_dt  = (const float*)d_in[9];
    const float* b_dt  = (const float*)d_in[10];
    const float* A_log = (const float*)d_in[11];
    const float* D_p   = (const float*)d_in[12];
    const float* W_out = (const float*)d_in[13];
    const float* ln2g  = (const float*)d_in[14];
    const float* ln2b  = (const float*)d_in[15];
    const float* W_f1  = (const float*)d_in[16];
    const float* b_f1  = (const float*)d_in[17];
    const float* W_f2  = (const float*)d_in[18];
    const float* b_f2  = (const float*)d_in[19];
    const float* lm_w  = (const float*)d_in[20];
    const float* lm_b  = (const float*)d_in[21];
    float* out = (float*)d_out;

    float *px, *pxz, *pu, *pxd, *pdt;
    __nv_bfloat16 *phh, *phl, *puh, *pul, *pxdh, *pxdl, *pyh, *pyl;
    __nv_bfloat16 *phidh, *phidl, *pxh, *pxl;
    __nv_bfloat16 *wInh, *wInl, *wXph, *wXpl, *wDth, *wDtl, *wOuth, *wOutl;
    __nv_bfloat16 *wF1h, *wF1l, *wF2h, *wF2l, *wLmh, *wLml;

    cudaGetSymbolAddress((void**)&px,   g_x);
    cudaGetSymbolAddress((void**)&pxz,  g_xz);
    cudaGetSymbolAddress((void**)&pu,   g_u);
    cudaGetSymbolAddress((void**)&pxd,  g_xdbl);
    cudaGetSymbolAddress((void**)&pdt,  g_dt);
    cudaGetSymbolAddress((void**)&phh,  g_hh);  cudaGetSymbolAddress((void**)&phl,  g_hl);
    cudaGetSymbolAddress((void**)&puh,  g_uh);  cudaGetSymbolAddress((void**)&pul,  g_ul);
    cudaGetSymbolAddress((void**)&pxdh, g_xdh); cudaGetSymbolAddress((void**)&pxdl, g_xdl);
    cudaGetSymbolAddress((void**)&pyh,  g_yh);  cudaGetSymbolAddress((void**)&pyl,  g_yl);
    cudaGetSymbolAddress((void**)&phidh,g_hidh);cudaGetSymbolAddress((void**)&phidl,g_hidl);
    cudaGetSymbolAddress((void**)&pxh,  g_xh);  cudaGetSymbolAddress((void**)&pxl,  g_xl);
    cudaGetSymbolAddress((void**)&wInh, g_Winh); cudaGetSymbolAddress((void**)&wInl, g_Winl);
    cudaGetSymbolAddress((void**)&wXph, g_Wxph); cudaGetSymbolAddress((void**)&wXpl, g_Wxpl);
    cudaGetSymbolAddress((void**)&wDth, g_Wdth); cudaGetSymbolAddress((void**)&wDtl, g_Wdtl);
    cudaGetSymbolAddress((void**)&wOuth,g_Wouth);cudaGetSymbolAddress((void**)&wOutl,g_Woutl);
    cudaGetSymbolAddress((void**)&wF1h, g_Wf1h); cudaGetSymbolAddress((void**)&wF1l, g_Wf1l);
    cudaGetSymbolAddress((void**)&wF2h, g_Wf2h); cudaGetSymbolAddress((void**)&wF2l, g_Wf2l);
    cudaGetSymbolAddress((void**)&wLmh, g_lmh);  cudaGetSymbolAddress((void**)&wLml, g_lml);

    auto split = [&](const float* src, __nv_bfloat16* h, __nv_bfloat16* l, long n) {
        int n4 = (int)(n / 4);
        split_kernel<<<(n4 + 255) / 256, 256>>>(src, h, l, n4);
    };

    split(W_in,  wInh,  wInl,  (long)LYR * 2048 * DD);
    split(W_xp,  wXph,  wXpl,  (long)LYR * 64 * DI_);
    split(W_dt,  wDth,  wDtl,  (long)LYR * DI_ * 32);
    split(W_out, wOuth, wOutl, (long)LYR * DD * DI_);
    split(W_f1,  wF1h,  wF1l,  (long)LYR * 2048 * DD);
    split(W_f2,  wF2h,  wF2l,  (long)LYR * DD * 2048);
    split(lm_w,  wLmh,  wLml,  (long)VOC * DD);

    embed_kernel<<<1024, 256>>>(idx, tok, pos);

    for (int l = 0; l < LYR; l++) {
        ln_kernel<<<MTOK, 128>>>(px, ln1g + l * DD, ln1b + l * DD, phh, phl);
        launch_tgemm<128, F_WF32>(MTOK, 2048, DD, DD, DD,
            phh, phl, wInh + (long)l * 2048 * DD, wInl + (long)l * 2048 * DD,
            nullptr, nullptr, pxz, nullptr, nullptr);
        conv_silu_kernel<<<MTOK * DI_ / 256, 256>>>(convw + l * DI_ * 4, convb + l * DI_);
        launch_tgemm<64, F_WF32 | F_WPAIR>(MTOK, 64, DI_, DI_, DI_,
            puh, pul, wXph + (long)l * 64 * DI_, wXpl + (long)l * 64 * DI_,
            nullptr, nullptr, pxd, pxdh, pxdl);
        launch_tgemm<128, F_BIAS | F_SOFT | F_WF32>(MTOK, DI_, 32, 64, 32,
            pxdh, pxdl, wDth + (long)l * DI_ * 32, wDtl + (long)l * DI_ * 32,
            b_dt + l * DI_, nullptr, pdt, nullptr, nullptr);
        scan_kernel<<<256, 128>>>(A_log + (long)l * DI_ * DS_, D_p + l * DI_);
        launch_tgemm<128, F_RES | F_WF32>(MTOK, DD, DI_, DI_, DI_,
            pyh, pyl, wOuth + (long)l * DD * DI_, wOutl + (long)l * DD * DI_,
            nullptr, px, px, nullptr, nullptr);
        ln_kernel<<<MTOK, 128>>>(px, ln2g + l * DD, ln2b + l * DD, phh, phl);
        launch_tgemm<128, F_BIAS | F_RELU | F_WPAIR>(MTOK, 2048, DD, DD, DD,
            phh, phl, wF1h + (long)l * 2048 * DD, wF1l + (long)l * 2048 * DD,
            b_f1 + l * 2048, nullptr, nullptr, phidh, phidl);
        launch_tgemm<128, F_BIAS | F_RES | F_WF32 | F_WPAIR>(MTOK, DD, 2048, 2048, 2048,
            phidh, phidl, wF2h + (long)l * DD * 2048, wF2l + (long)l * DD * 2048,
            b_f2 + l * DD, px, px, pxh, pxl);
    }

    launch_tgemm<128, F_BIAS | F_WF32>(MTOK, VOC, DD, DD, DD,
        pxh, pxl, wLmh, wLml, lm_b, nullptr, out, nullptr, nullptr);
}

// round 7
// speedup vs baseline: 3.2589x; 1.4243x over previous
#include <cuda_runtime.h>
#include <cuda_bf16.h>
#include <math.h>
#include <stdint.h>

#define MTOK 2048
#define TT   1024
#define DD   512
#define DI_  1024
#define DS_  16
#define LYR  4
#define VOC  32000
#define TC   64
#define NCH  16

// ===================== PTX helpers (plain sm_103-safe) =====================
__device__ __forceinline__ uint32_t smem_u32(const void* p) {
    uint32_t a;
    asm("{ .reg .u64 t; cvta.to.shared.u64 t, %1; cvt.u32.u64 %0, t; }"
        : "=r"(a) : "l"(p));
    return a;
}
#define CP16(dst, src) \
    asm volatile("cp.async.cg.shared.global [%0], [%1], 16;" \
                 :: "r"(dst), "l"(src) : "memory")
#define CP_COMMIT() asm volatile("cp.async.commit_group;" ::: "memory")
#define CP_WAIT0()  asm volatile("cp.async.wait_group 0;" ::: "memory")
#define CP_WAIT2()  asm volatile("cp.async.wait_group 2;" ::: "memory")

__device__ __forceinline__ void ldsm4(uint32_t* r, uint32_t addr) {
    asm volatile("ldmatrix.sync.aligned.m8n8.x4.shared.b16 {%0,%1,%2,%3}, [%4];"
                 : "=r"(r[0]), "=r"(r[1]), "=r"(r[2]), "=r"(r[3]) : "r"(addr));
}
__device__ __forceinline__ void mma16816(float* d, const uint32_t* a,
                                         const uint32_t* b) {
    asm volatile(
        "mma.sync.aligned.m16n8k16.row.col.f32.bf16.bf16.f32 "
        "{%0,%1,%2,%3}, {%4,%5,%6,%7}, {%8,%9}, {%0,%1,%2,%3};"
        : "+f"(d[0]), "+f"(d[1]), "+f"(d[2]), "+f"(d[3])
        : "r"(a[0]), "r"(a[1]), "r"(a[2]), "r"(a[3]), "r"(b[0]), "r"(b[1]));
}

__device__ __forceinline__ void split2(float v, __nv_bfloat16& h, __nv_bfloat16& l) {
    h = __float2bfloat16(v);
    l = __float2bfloat16(v - __bfloat162float(h));
}

// ===================== device-global scratch ==============================
__device__ __align__(256) float g_x   [MTOK * DD];
__device__ __align__(256) float g_xz  [MTOK * 2048];
__device__ __align__(256) float g_u   [MTOK * DI_];
__device__ __align__(256) float g_xdbl[MTOK * 64];
__device__ __align__(256) float g_dt  [MTOK * DI_];

__device__ __align__(256) float g_sD [2 * NCH * DI_ * DS_];
__device__ __align__(256) float g_sV [2 * NCH * DI_ * DS_];
__device__ __align__(256) float g_hin[2 * NCH * DI_ * DS_];

__device__ __align__(256) __nv_bfloat16 g_hh[MTOK * DD];
__device__ __align__(256) __nv_bfloat16 g_hl[MTOK * DD];
__device__ __align__(256) __nv_bfloat16 g_uh[MTOK * DI_];
__device__ __align__(256) __nv_bfloat16 g_ul[MTOK * DI_];
__device__ __align__(256) __nv_bfloat16 g_xdh[MTOK * 64];
__device__ __align__(256) __nv_bfloat16 g_xdl[MTOK * 64];
__device__ __align__(256) __nv_bfloat16 g_yh[MTOK * DI_];
__device__ __align__(256) __nv_bfloat16 g_yl[MTOK * DI_];
__device__ __align__(256) __nv_bfloat16 g_hidh[MTOK * 2048];
__device__ __align__(256) __nv_bfloat16 g_hidl[MTOK * 2048];
__device__ __align__(256) __nv_bfloat16 g_xh[MTOK * DD];
__device__ __align__(256) __nv_bfloat16 g_xl[MTOK * DD];

__device__ __align__(256) __nv_bfloat16 g_Winh [LYR * 2048 * DD];
__device__ __align__(256) __nv_bfloat16 g_Winl [LYR * 2048 * DD];
__device__ __align__(256) __nv_bfloat16 g_Wxph [LYR * 64 * DI_];
__device__ __align__(256) __nv_bfloat16 g_Wxpl [LYR * 64 * DI_];
__device__ __align__(256) __nv_bfloat16 g_Wdth [LYR * DI_ * 32];
__device__ __align__(256) __nv_bfloat16 g_Wdtl [LYR * DI_ * 32];
__device__ __align__(256) __nv_bfloat16 g_Wouth[LYR * DD * DI_];
__device__ __align__(256) __nv_bfloat16 g_Woutl[LYR * DD * DI_];
__device__ __align__(256) __nv_bfloat16 g_Wf1h [LYR * 2048 * DD];
__device__ __align__(256) __nv_bfloat16 g_Wf1l [LYR * 2048 * DD];
__device__ __align__(256) __nv_bfloat16 g_Wf2h [LYR * DD * 2048];
__device__ __align__(256) __nv_bfloat16 g_Wf2l [LYR * DD * 2048];
__device__ __align__(256) __nv_bfloat16 g_lmh  [VOC * DD];
__device__ __align__(256) __nv_bfloat16 g_lml  [VOC * DD];

// ===================== small kernels ======================================
__global__ void embed_kernel(const int* __restrict__ idx,
                             const float* __restrict__ tok,
                             const float* __restrict__ pos) {
    int i = blockIdx.x * 256 + threadIdx.x;
    int token = i >> 7;
    int c = i & 127;
    int t = token & (TT - 1);
    int row = idx[token];
    float4 a = ((const float4*)tok)[row * 128 + c];
    float4 p = ((const float4*)pos)[t * 128 + c];
    a.x += p.x; a.y += p.y; a.z += p.z; a.w += p.w;
    ((float4*)g_x)[i] = a;
}

__global__ void split_kernel(const float* __restrict__ in,
                             __nv_bfloat16* __restrict__ hi,
                             __nv_bfloat16* __restrict__ lo, int n4) {
    int i = blockIdx.x * 256 + threadIdx.x;
    if (i >= n4) return;
    float4 v = ((const float4*)in)[i];
    __nv_bfloat16 h0, h1, h2, h3, l0, l1, l2, l3;
    split2(v.x, h0, l0); split2(v.y, h1, l1);
    split2(v.z, h2, l2); split2(v.w, h3, l3);
    ((__nv_bfloat162*)hi)[i * 2 + 0] = __nv_bfloat162{h0, h1};
    ((__nv_bfloat162*)hi)[i * 2 + 1] = __nv_bfloat162{h2, h3};
    ((__nv_bfloat162*)lo)[i * 2 + 0] = __nv_bfloat162{l0, l1};
    ((__nv_bfloat162*)lo)[i * 2 + 1] = __nv_bfloat162{l2, l3};
}

__global__ void ln_kernel(const float* __restrict__ x,
                          const float* __restrict__ g,
                          const float* __restrict__ bta,
                          __nv_bfloat16* __restrict__ oh,
                          __nv_bfloat16* __restrict__ ol) {
    int token = blockIdx.x;
    int tid = threadIdx.x;
    float4 v = ((const float4*)(x + token * DD))[tid];
    float s = v.x + v.y + v.z + v.w;
    __shared__ float red[8];
    #pragma unroll
    for (int o = 16; o > 0; o >>= 1) s += __shfl_xor_sync(0xffffffffu, s, o);
    if ((tid & 31) == 0) red[tid >> 5] = s;
    __syncthreads();
    float mean = (red[0] + red[1] + red[2] + red[3]) * (1.0f / 512.0f);
    float dx = v.x - mean, dy = v.y - mean, dz = v.z - mean, dw = v.w - mean;
    float q = dx * dx + dy * dy + dz * dz + dw * dw;
    #pragma unroll
    for (int o = 16; o > 0; o >>= 1) q += __shfl_xor_sync(0xffffffffu, q, o);
    if ((tid & 31) == 0) red[4 + (tid >> 5)] = q;
    __syncthreads();
    float var = (red[4] + red[5] + red[6] + red[7]) * (1.0f / 512.0f);
    float r = rsqrtf(var + 1e-5f);
    float4 gg = ((const float4*)g)[tid];
    float4 bb = ((const float4*)bta)[tid];
    float o0 = dx * r * gg.x + bb.x, o1 = dy * r * gg.y + bb.y;
    float o2 = dz * r * gg.z + bb.z, o3 = dw * r * gg.w + bb.w;
    __nv_bfloat16 h0, h1, h2, h3, l0, l1, l2, l3;
    split2(o0, h0, l0); split2(o1, h1, l1); split2(o2, h2, l2); split2(o3, h3, l3);
    ((__nv_bfloat162*)(oh + token * DD))[tid * 2 + 0] = __nv_bfloat162{h0, h1};
    ((__nv_bfloat162*)(oh + token * DD))[tid * 2 + 1] = __nv_bfloat162{h2, h3};
    ((__nv_bfloat162*)(ol + token * DD))[tid * 2 + 0] = __nv_bfloat162{l0, l1};
    ((__nv_bfloat162*)(ol + token * DD))[tid * 2 + 1] = __nv_bfloat162{l2, l3};
}

__global__ void conv_silu_kernel(const float* __restrict__ w,
                                 const float* __restrict__ cb) {
    int i = blockIdx.x * 256 + threadIdx.x;
    int token = i >> 10;
    int d = i & (DI_ - 1);
    int t = token & (TT - 1);
    float acc = cb[d];
    #pragma unroll
    for (int j = 0; j < 4; j++) {
        int tt = t - 3 + j;
        if (tt >= 0) acc += g_xz[(token - 3 + j) * 2048 + d] * w[d * 4 + j];
    }
    float sg = 1.0f / (1.0f + __expf(-acc));
    float uv = acc * sg;
    g_u[i] = uv;
    __nv_bfloat16 h, l; split2(uv, h, l);
    g_uh[i] = h; g_ul[i] = l;
}

// ======== chunked selective scan (3 phases) ===============================
// dA_s(t) = exp(dt_t * A_s), A_s = -exp(A_log_s).  Since A_log = log(1..16),
// dA_s = r^(s+1) with r = exp(-dt) (runtime-verified; exp fallback otherwise).

__device__ __forceinline__ void powers16(float r, float* p) {
    float r2 = r * r, r4 = r2 * r2, r8 = r4 * r4;
    p[0] = r;        p[1] = r2;       p[2] = r2 * r;   p[3] = r4;
    p[4] = r4 * r;   p[5] = r4 * r2;  p[6] = r4 * p[2]; p[7] = r8;
    p[8] = r8 * r;   p[9] = r8 * r2;  p[10] = r8 * p[2]; p[11] = r8 * r4;
    p[12] = r8 * p[4]; p[13] = r8 * p[5]; p[14] = r8 * p[6]; p[15] = r8 * r8;
}

__global__ void scan_p1(const float* __restrict__ A_log) {
    __shared__ float sB[TC][16];
    const int d = blockIdx.x * 128 + threadIdx.x;
    const int ch = blockIdx.y, b = blockIdx.z;
    const int t0 = ch * TC;
    for (int i = threadIdx.x; i < TC * 16; i += 128) {
        int tt = i >> 4, s = i & 15;
        sB[tt][s] = g_xdbl[(size_t)(b * TT + t0 + tt) * 64 + 32 + s];
    }
    __syncthreads();
    float es[16]; bool fast = true;
    #pragma unroll
    for (int s = 0; s < 16; s++) {
        es[s] = expf(A_log[d * 16 + s]);
        fast = fast && (fabsf(es[s] - (float)(s + 1)) < 1e-3f);
    }
    float h[16];
    #pragma unroll
    for (int s = 0; s < 16; s++) h[s] = 0.0f;
    float S = 0.0f;
    const float* pdt = g_dt + (size_t)(b * TT + t0) * DI_ + d;
    const float* pu  = g_u  + (size_t)(b * TT + t0) * DI_ + d;
    if (fast) {
        for (int t = 0; t < TC; t++) {
            float dt = pdt[t * DI_], u = pu[t * DI_];
            S += dt;
            float x = dt * u;
            float p[16]; powers16(__expf(-dt), p);
            #pragma unroll
            for (int s = 0; s < 16; s++) h[s] = p[s] * h[s] + x * sB[t][s];
        }
    } else {
        for (int t = 0; t < TC; t++) {
            float dt = pdt[t * DI_], u = pu[t * DI_];
            S += dt;
            float x = dt * u;
            #pragma unroll
            for (int s = 0; s < 16; s++)
                h[s] = __expf(-dt * es[s]) * h[s] + x * sB[t][s];
        }
    }
    size_t o = (((size_t)b * NCH + ch) * DI_ + d) * 16;
    #pragma unroll
    for (int s = 0; s < 16; s++) {
        g_sV[o + s] = h[s];
        g_sD[o + s] = __expf(-S * es[s]);
    }
}

__global__ void scan_p2() {
    const int d = blockIdx.x * 128 + threadIdx.x;
    const int b = blockIdx.y;
    float h[16];
    #pragma unroll
    for (int s = 0; s < 16; s++) h[s] = 0.0f;
    for (int ch = 0; ch < NCH; ch++) {
        size_t o = (((size_t)b * NCH + ch) * DI_ + d) * 16;
        #pragma unroll
        for (int s = 0; s < 16; s++) g_hin[o + s] = h[s];
        #pragma unroll
        for (int s = 0; s < 16; s++) h[s] = g_sD[o + s] * h[s] + g_sV[o + s];
    }
}

__global__ void scan_p3(const float* __restrict__ A_log,
                        const float* __restrict__ D_p) {
    __shared__ float sB[TC][16], sC[TC][16];
    const int d = blockIdx.x * 128 + threadIdx.x;
    const int ch = blockIdx.y, b = blockIdx.z;
    const int t0 = ch * TC;
    for (int i = threadIdx.x; i < TC * 16; i += 128) {
        int tt = i >> 4, s = i & 15;
        size_t base = (size_t)(b * TT + t0 + tt) * 64;
        sB[tt][s] = g_xdbl[base + 32 + s];
        sC[tt][s] = g_xdbl[base + 48 + s];
    }
    __syncthreads();
    float es[16]; bool fast = true;
    #pragma unroll
    for (int s = 0; s < 16; s++) {
        es[s] = expf(A_log[d * 16 + s]);
        fast = fast && (fabsf(es[s] - (float)(s + 1)) < 1e-3f);
    }
    float h[16];
    {
        size_t o = (((size_t)b * NCH + ch) * DI_ + d) * 16;
        #pragma unroll
        for (int s = 0; s < 16; s++) h[s] = g_hin[o + s];
    }
    const float Dp = D_p[d];
    const float* pdt = g_dt + (size_t)(b * TT + t0) * DI_ + d;
    const float* pu  = g_u  + (size_t)(b * TT + t0) * DI_ + d;
    const float* pz  = g_xz + (size_t)(b * TT + t0) * 2048 + DI_ + d;
    __nv_bfloat16* pyh = g_yh + (size_t)(b * TT + t0) * DI_ + d;
    __nv_bfloat16* pyl = g_yl + (size_t)(b * TT + t0) * DI_ + d;
    for (int t = 0; t < TC; t++) {
        float dt = pdt[t * DI_], u = pu[t * DI_], z = pz[t * 2048];
        float x = dt * u;
        float p[16];
        if (fast) powers16(__expf(-dt), p);
        else {
            #pragma unroll
            for (int s = 0; s < 16; s++) p[s] = __expf(-dt * es[s]);
        }
        #pragma unroll
        for (int s = 0; s < 16; s++) h[s] = p[s] * h[s] + x * sB[t][s];
        float q[8];
        #pragma unroll
        for (int i = 0; i < 8; i++)
            q[i] = fmaf(h[2 * i], sC[t][2 * i], h[2 * i + 1] * sC[t][2 * i + 1]);
        float yp = ((q[0] + q[1]) + (q[2] + q[3])) + ((q[4] + q[5]) + (q[6] + q[7]));
        float yv = yp + u * Dp;
        float ov = yv * (z / (1.0f + __expf(-z)));
        __nv_bfloat16 hh, ll; split2(ov, hh, ll);
        pyh[t * DI_] = hh; pyl[t * DI_] = ll;
    }
}

// ===================== HMMA split-bf16 GEMM (4-stage) =====================
#define F_BIAS 1
#define F_RELU 2
#define F_SOFT 4
#define F_RES  8
#define F_WF32 16
#define F_WPAIR 32

template <int BM, int BN, int WGM, int WGN, int FLAGS>
__global__ __launch_bounds__(512) void tgemm(
    int M, int N, int K, int lda, int ldb,
    const __nv_bfloat16* __restrict__ Ah, const __nv_bfloat16* __restrict__ Al,
    const __nv_bfloat16* __restrict__ Bh, const __nv_bfloat16* __restrict__ Bl,
    const float* __restrict__ bias, const float* __restrict__ res,
    float* __restrict__ Cf,
    __nv_bfloat16* __restrict__ Ch, __nv_bfloat16* __restrict__ Cl) {
    extern __shared__ char smem[];
    constexpr int PITCH = 80;
    constexpr int ASZ = BM * PITCH;
    constexpr int BSZ = BN * PITCH;
    constexpr int STAGE = 2 * ASZ + 2 * BSZ;
    constexpr int WROWS = BM / WGM, WCOLS = BN / WGN;
    constexpr int MI = WROWS / 16, NI = WCOLS / 8, NP = NI / 2;
    const int tid = threadIdx.x, lane = tid & 31, wid = tid >> 5;
    const int wm = wid / WGN, wn = wid % WGN;
    const int bm = blockIdx.y * BM, bn = blockIdx.x * BN;
    const uint32_t sb = smem_u32(smem);
    const int nc = K / 32;

    float acc[MI][NI][4];
    #pragma unroll
    for (int i = 0; i < MI; i++)
        #pragma unroll
        for (int j = 0; j < NI; j++)
            #pragma unroll
            for (int q = 0; q < 4; q++) acc[i][j][q] = 0.0f;

    auto prefetch = [&](int c) {
        if (c >= nc) return;
        const uint32_t sbase = sb + (c & 3) * STAGE;
        const int k0 = c * 32;
        #pragma unroll
        for (int i = 0; i < (BM * 4 + 511) / 512; i++) {
            int ch = tid + i * 512;
            if ((BM * 4 % 512 == 0) || ch < BM * 4) {
                int row = ch >> 2, kc = ch & 3;
                uint32_t doff = row * PITCH + kc * 16;
                size_t goff = (size_t)(bm + row) * lda + k0 + kc * 8;
                CP16(sbase + doff, (const char*)(Ah + goff));
                CP16(sbase + ASZ + doff, (const char*)(Al + goff));
            }
        }
        #pragma unroll
        for (int i = 0; i < (BN * 4 + 511) / 512; i++) {
            int ch = tid + i * 512;
            if ((BN * 4 % 512 == 0) || ch < BN * 4) {
                int row = ch >> 2, kc = ch & 3;
                uint32_t doff = row * PITCH + kc * 16;
                size_t goff = (size_t)(bn + row) * ldb + k0 + kc * 8;
                CP16(sbase + 2 * ASZ + doff, (const char*)(Bh + goff));
                CP16(sbase + 2 * ASZ + BSZ + doff, (const char*)(Bl + goff));
            }
        }
    };

    auto compute = [&](int s) {
        const uint32_t sbase = sb + s * STAGE;
        const uint32_t arow = (uint32_t)(lane & 15);
        const uint32_t asel = (uint32_t)((lane >> 4) * 16);
        #pragma unroll
        for (int kk = 0; kk < 2; kk++) {
            const uint32_t kb = kk * 32;
            uint32_t ah[MI][4], al[MI][4];
            #pragma unroll
            for (int mi = 0; mi < MI; mi++) {
                uint32_t ad = sbase + (wm * WROWS + mi * 16 + arow) * PITCH + kb + asel;
                ldsm4(ah[mi], ad);
                ldsm4(al[mi], ad + ASZ);
            }
            uint32_t bh[NI][2], bl[NI][2];
            #pragma unroll
            for (int p = 0; p < NP; p++) {
                uint32_t bd = sbase + 2 * ASZ +
                              (wn * WCOLS + p * 16 + arow) * PITCH + kb + asel;
                uint32_t t4[4];
                ldsm4(t4, bd);
                bh[2 * p][0] = t4[0]; bh[2 * p][1] = t4[2];
                bh[2 * p + 1][0] = t4[1]; bh[2 * p + 1][1] = t4[3];
                ldsm4(t4, bd + BSZ);
                bl[2 * p][0] = t4[0]; bl[2 * p][1] = t4[2];
                bl[2 * p + 1][0] = t4[1]; bl[2 * p + 1][1] = t4[3];
            }
            #pragma unroll
            for (int mi = 0; mi < MI; mi++)
                #pragma unroll
                for (int ni = 0; ni < NI; ni++) {
                    mma16816(acc[mi][ni], ah[mi], bh[ni]);
                    mma16816(acc[mi][ni], ah[mi], bl[ni]);
                    mma16816(acc[mi][ni], al[mi], bh[ni]);
                }
        }
    };

    prefetch(0); CP_COMMIT();
    prefetch(1); CP_COMMIT();
    prefetch(2); CP_COMMIT();
    for (int c = 0; c < nc; c++) {
        CP_WAIT2();
        __syncthreads();
        prefetch(c + 3); CP_COMMIT();
        compute(c & 3);
    }

    // ---- epilogue: direct fragment stores ----
    #pragma unroll
    for (int mi = 0; mi < MI; mi++) {
        #pragma unroll
        for (int ni = 0; ni < NI; ni++) {
            const int r0 = bm + wm * WROWS + mi * 16 + (lane >> 2);
            const int c0 = bn + wn * WCOLS + ni * 8 + (lane & 3) * 2;
            #pragma unroll
            for (int hh = 0; hh < 2; hh++) {
                const int r = r0 + hh * 8;
                float v0 = acc[mi][ni][hh * 2 + 0];
                float v1 = acc[mi][ni][hh * 2 + 1];
                if (FLAGS & F_BIAS) { v0 += bias[c0]; v1 += bias[c0 + 1]; }
                if (FLAGS & F_RELU) { v0 = fmaxf(v0, 0.f); v1 = fmaxf(v1, 0.f); }
                if (FLAGS & F_SOFT) {
                    v0 = (v0 > 20.f) ? v0 : log1pf(expf(v0));
                    v1 = (v1 > 20.f) ? v1 : log1pf(expf(v1));
                }
                if (FLAGS & F_RES) {
                    float2 rr = *(const float2*)(res + (size_t)r * N + c0);
                    v0 += rr.x; v1 += rr.y;
                }
                if (FLAGS & F_WF32) {
                    *(float2*)(Cf + (size_t)r * N + c0) = make_float2(v0, v1);
                }
                if (FLAGS & F_WPAIR) {
                    __nv_bfloat16 h0, h1, l0, l1;
                    split2(v0, h0, l0); split2(v1, h1, l1);
                    *(__nv_bfloat162*)(Ch + (size_t)r * N + c0) = __nv_bfloat162{h0, h1};
                    *(__nv_bfloat162*)(Cl + (size_t)r * N + c0) = __nv_bfloat162{l0, l1};
                }
            }
        }
    }
}

// ===================== host orchestration =================================
template <int BM, int BN, int WGM, int WGN, int FLAGS>
static void launch_tgemm(int M, int N, int K, int lda, int ldb,
                         const __nv_bfloat16* Ah, const __nv_bfloat16* Al,
                         const __nv_bfloat16* Bh, const __nv_bfloat16* Bl,
                         const float* bias, const float* res,
                         float* Cf, __nv_bfloat16* Ch, __nv_bfloat16* Cl) {
    constexpr int PITCH = 80;
    constexpr int STAGE = 2 * BM * PITCH + 2 * BN * PITCH;
    const int smem_bytes = 4 * STAGE;
    cudaFuncSetAttribute(tgemm<BM, BN, WGM, WGN, FLAGS>,
                         cudaFuncAttributeMaxDynamicSharedMemorySize, smem_bytes);
    dim3 grid(N / BN, M / BM);
    tgemm<BM, BN, WGM, WGN, FLAGS><<<grid, 512, smem_bytes>>>(M, N, K, lda, ldb,
        Ah, Al, Bh, Bl, bias, res, Cf, Ch, Cl);
}

extern "C" void kernel_launch(void* const* d_in, const int* in_sizes, int n_in,
                              void* d_out, int out_size) {
    const int*   idx   = (const int*)d_in[0];
    const float* tok   = (const float*)d_in[1];
    const float* pos   = (const float*)d_in[2];
    const float* ln1g  = (const float*)d_in[3];
    const float* ln1b  = (const float*)d_in[4];
    const float* W_in  = (const float*)d_in[5];
    const float* convw = (const float*)d_in[6];
    const float* convb = (const float*)d_in[7];
    const float* W_xp  = (const float*)d_in[8];
    const float* W_dt  = (const float*)d_in[9];
    const float* b_dt  = (const float*)d_in[10];
    const float* A_log = (const float*)d_in[11];
    const float* D_p   = (const float*)d_in[12];
    const float* W_out = (const float*)d_in[13];
    const float* ln2g  = (const float*)d_in[14];
    const float* ln2b  = (const float*)d_in[15];
    const float* W_f1  = (const float*)d_in[16];
    const float* b_f1  = (const float*)d_in[17];
    const float* W_f2  = (const float*)d_in[18];
    const float* b_f2  = (const float*)d_in[19];
    const float* lm_w  = (const float*)d_in[20];
    const float* lm_b  = (const float*)d_in[21];
    float* out = (float*)d_out;

    float *px, *pxz, *pu, *pxd, *pdt;
    __nv_bfloat16 *phh, *phl, *puh, *pul, *pxdh, *pxdl, *pyh, *pyl;
    __nv_bfloat16 *phidh, *phidl, *pxh, *pxl;
    __nv_bfloat16 *wInh, *wInl, *wXph, *wXpl, *wDth, *wDtl, *wOuth, *wOutl;
    __nv_bfloat16 *wF1h, *wF1l, *wF2h, *wF2l, *wLmh, *wLml;

    cudaGetSymbolAddress((void**)&px,   g_x);
    cudaGetSymbolAddress((void**)&pxz,  g_xz);
    cudaGetSymbolAddress((void**)&pu,   g_u);
    cudaGetSymbolAddress((void**)&pxd,  g_xdbl);
    cudaGetSymbolAddress((void**)&pdt,  g_dt);
    cudaGetSymbolAddress((void**)&phh,  g_hh);  cudaGetSymbolAddress((void**)&phl,  g_hl);
    cudaGetSymbolAddress((void**)&puh,  g_uh);  cudaGetSymbolAddress((void**)&pul,  g_ul);
    cudaGetSymbolAddress((void**)&pxdh, g_xdh); cudaGetSymbolAddress((void**)&pxdl, g_xdl);
    cudaGetSymbolAddress((void**)&pyh,  g_yh);  cudaGetSymbolAddress((void**)&pyl,  g_yl);
    cudaGetSymbolAddress((void**)&phidh,g_hidh);cudaGetSymbolAddress((void**)&phidl,g_hidl);
    cudaGetSymbolAddress((void**)&pxh,  g_xh);  cudaGetSymbolAddress((void**)&pxl,  g_xl);
    cudaGetSymbolAddress((void**)&wInh, g_Winh); cudaGetSymbolAddress((void**)&wInl, g_Winl);
    cudaGetSymbolAddress((void**)&wXph, g_Wxph); cudaGetSymbolAddress((void**)&wXpl, g_Wxpl);
    cudaGetSymbolAddress((void**)&wDth, g_Wdth); cudaGetSymbolAddress((void**)&wDtl, g_Wdtl);
    cudaGetSymbolAddress((void**)&wOuth,g_Wouth);cudaGetSymbolAddress((void**)&wOutl,g_Woutl);
    cudaGetSymbolAddress((void**)&wF1h, g_Wf1h); cudaGetSymbolAddress((void**)&wF1l, g_Wf1l);
    cudaGetSymbolAddress((void**)&wF2h, g_Wf2h); cudaGetSymbolAddress((void**)&wF2l, g_Wf2l);
    cudaGetSymbolAddress((void**)&wLmh, g_lmh);  cudaGetSymbolAddress((void**)&wLml, g_lml);

    auto split = [&](const float* src, __nv_bfloat16* h, __nv_bfloat16* l, long n) {
        int n4 = (int)(n / 4);
        split_kernel<<<(n4 + 255) / 256, 256>>>(src, h, l, n4);
    };

    split(W_in,  wInh,  wInl,  (long)LYR * 2048 * DD);
    split(W_xp,  wXph,  wXpl,  (long)LYR * 64 * DI_);
    split(W_dt,  wDth,  wDtl,  (long)LYR * DI_ * 32);
    split(W_out, wOuth, wOutl, (long)LYR * DD * DI_);
    split(W_f1,  wF1h,  wF1l,  (long)LYR * 2048 * DD);
    split(W_f2,  wF2h,  wF2l,  (long)LYR * DD * 2048);
    split(lm_w,  wLmh,  wLml,  (long)VOC * DD);

    embed_kernel<<<1024, 256>>>(idx, tok, pos);

    for (int l = 0; l < LYR; l++) {
        ln_kernel<<<MTOK, 128>>>(px, ln1g + l * DD, ln1b + l * DD, phh, phl);
        launch_tgemm<128, 128, 4, 4, F_WF32>(MTOK, 2048, DD, DD, DD,
            phh, phl, wInh + (long)l * 2048 * DD, wInl + (long)l * 2048 * DD,
            nullptr, nullptr, pxz, nullptr, nullptr);
        conv_silu_kernel<<<MTOK * DI_ / 256, 256>>>(convw + l * DI_ * 4, convb + l * DI_);
        launch_tgemm<64, 64, 4, 4, F_WF32 | F_WPAIR>(MTOK, 64, DI_, DI_, DI_,
            puh, pul, wXph + (long)l * 64 * DI_, wXpl + (long)l * 64 * DI_,
            nullptr, nullptr, pxd, pxdh, pxdl);
        launch_tgemm<128, 128, 4, 4, F_BIAS | F_SOFT | F_WF32>(MTOK, DI_, 32, 64, 32,
            pxdh, pxdl, wDth + (long)l * DI_ * 32, wDtl + (long)l * DI_ * 32,
            b_dt + l * DI_, nullptr, pdt, nullptr, nullptr);
        scan_p1<<<dim3(8, NCH, 2), 128>>>(A_log + (long)l * DI_ * DS_);
        scan_p2<<<dim3(8, 2), 128>>>();
        scan_p3<<<dim3(8, NCH, 2), 128>>>(A_log + (long)l * DI_ * DS_, D_p + l * DI_);
        launch_tgemm<64, 128, 2, 8, F_RES | F_WF32>(MTOK, DD, DI_, DI_, DI_,
            pyh, pyl, wOuth + (long)l * DD * DI_, wOutl + (long)l * DD * DI_,
            nullptr, px, px, nullptr, nullptr);
        ln_kernel<<<MTOK, 128>>>(px, ln2g + l * DD, ln2b + l * DD, phh, phl);
        launch_tgemm<128, 128, 4, 4, F_BIAS | F_RELU | F_WPAIR>(MTOK, 2048, DD, DD, DD,
            phh, phl, wF1h + (long)l * 2048 * DD, wF1l + (long)l * 2048 * DD,
            b_f1 + l * 2048, nullptr, nullptr, phidh, phidl);
        launch_tgemm<64, 128, 2, 8, F_BIAS | F_RES | F_WF32 | F_WPAIR>(
            MTOK, DD, 2048, 2048, 2048,
            phidh, phidl, wF2h + (long)l * DD * 2048, wF2l + (long)l * DD * 2048,
            b_f2 + l * DD, px, px, pxh, pxl);
    }

    launch_tgemm<128, 128, 4, 4, F_BIAS | F_WF32>(MTOK, VOC, DD, DD, DD,
        pxh, pxl, wLmh, wLml, lm_b, nullptr, out, nullptr, nullptr);
}

// round 8
// speedup vs baseline: 3.3816x; 1.0377x over previous
#include <cuda_runtime.h>
#include <cuda_bf16.h>
#include <math.h>
#include <stdint.h>

#define MTOK 2048
#define TT   1024
#define DD   512
#define DI_  1024
#define DS_  16
#define LYR  4
#define VOC  32000
#define TC   64
#define NCH  16

// ===================== PTX helpers (plain sm_103-safe) =====================
__device__ __forceinline__ uint32_t smem_u32(const void* p) {
    uint32_t a;
    asm("{ .reg .u64 t; cvta.to.shared.u64 t, %1; cvt.u32.u64 %0, t; }"
        : "=r"(a) : "l"(p));
    return a;
}
#define CP16(dst, src) \
    asm volatile("cp.async.cg.shared.global [%0], [%1], 16;" \
                 :: "r"(dst), "l"(src) : "memory")
#define CP_COMMIT() asm volatile("cp.async.commit_group;" ::: "memory")
template <int n>
__device__ __forceinline__ void cp_wait() {
    asm volatile("cp.async.wait_group %0;" :: "n"(n) : "memory");
}

__device__ __forceinline__ void ldsm4(uint32_t* r, uint32_t addr) {
    asm volatile("ldmatrix.sync.aligned.m8n8.x4.shared.b16 {%0,%1,%2,%3}, [%4];"
                 : "=r"(r[0]), "=r"(r[1]), "=r"(r[2]), "=r"(r[3]) : "r"(addr));
}
__device__ __forceinline__ void mma16816(float* d, const uint32_t* a,
                                         const uint32_t* b) {
    asm volatile(
        "mma.sync.aligned.m16n8k16.row.col.f32.bf16.bf16.f32 "
        "{%0,%1,%2,%3}, {%4,%5,%6,%7}, {%8,%9}, {%0,%1,%2,%3};"
        : "+f"(d[0]), "+f"(d[1]), "+f"(d[2]), "+f"(d[3])
        : "r"(a[0]), "r"(a[1]), "r"(a[2]), "r"(a[3]), "r"(b[0]), "r"(b[1]));
}

__device__ __forceinline__ void split2(float v, __nv_bfloat16& h, __nv_bfloat16& l) {
    h = __float2bfloat16(v);
    l = __float2bfloat16(v - __bfloat162float(h));
}

// ===================== device-global scratch ==============================
__device__ __align__(256) float g_x   [MTOK * DD];
__device__ __align__(256) float g_xz  [MTOK * 2048];
__device__ __align__(256) float g_u   [MTOK * DI_];
__device__ __align__(256) float g_xdbl[MTOK * 64];
__device__ __align__(256) float g_dt  [MTOK * DI_];

__device__ __align__(256) float g_sD [2 * NCH * DI_ * DS_];
__device__ __align__(256) float g_sV [2 * NCH * DI_ * DS_];
__device__ __align__(256) float g_hin[2 * NCH * DI_ * DS_];

__device__ __align__(256) __nv_bfloat16 g_hh[MTOK * DD];
__device__ __align__(256) __nv_bfloat16 g_hl[MTOK * DD];
__device__ __align__(256) __nv_bfloat16 g_uh[MTOK * DI_];
__device__ __align__(256) __nv_bfloat16 g_ul[MTOK * DI_];
__device__ __align__(256) __nv_bfloat16 g_xdh[MTOK * 64];
__device__ __align__(256) __nv_bfloat16 g_xdl[MTOK * 64];
__device__ __align__(256) __nv_bfloat16 g_yh[MTOK * DI_];
__device__ __align__(256) __nv_bfloat16 g_yl[MTOK * DI_];
__device__ __align__(256) __nv_bfloat16 g_hidh[MTOK * 2048];
__device__ __align__(256) __nv_bfloat16 g_hidl[MTOK * 2048];
__device__ __align__(256) __nv_bfloat16 g_xh[MTOK * DD];
__device__ __align__(256) __nv_bfloat16 g_xl[MTOK * DD];

__device__ __align__(256) __nv_bfloat16 g_Winh [LYR * 2048 * DD];
__device__ __align__(256) __nv_bfloat16 g_Winl [LYR * 2048 * DD];
__device__ __align__(256) __nv_bfloat16 g_Wxph [LYR * 64 * DI_];
__device__ __align__(256) __nv_bfloat16 g_Wxpl [LYR * 64 * DI_];
__device__ __align__(256) __nv_bfloat16 g_Wdth [LYR * DI_ * 32];
__device__ __align__(256) __nv_bfloat16 g_Wdtl [LYR * DI_ * 32];
__device__ __align__(256) __nv_bfloat16 g_Wouth[LYR * DD * DI_];
__device__ __align__(256) __nv_bfloat16 g_Woutl[LYR * DD * DI_];
__device__ __align__(256) __nv_bfloat16 g_Wf1h [LYR * 2048 * DD];
__device__ __align__(256) __nv_bfloat16 g_Wf1l [LYR * 2048 * DD];
__device__ __align__(256) __nv_bfloat16 g_Wf2h [LYR * DD * 2048];
__device__ __align__(256) __nv_bfloat16 g_Wf2l [LYR * DD * 2048];
__device__ __align__(256) __nv_bfloat16 g_lmh  [VOC * DD];
__device__ __align__(256) __nv_bfloat16 g_lml  [VOC * DD];

// ===================== small kernels ======================================
__global__ void embed_kernel(const int* __restrict__ idx,
                             const float* __restrict__ tok,
                             const float* __restrict__ pos) {
    int i = blockIdx.x * 256 + threadIdx.x;
    int token = i >> 7;
    int c = i & 127;
    int t = token & (TT - 1);
    int row = idx[token];
    float4 a = ((const float4*)tok)[row * 128 + c];
    float4 p = ((const float4*)pos)[t * 128 + c];
    a.x += p.x; a.y += p.y; a.z += p.z; a.w += p.w;
    ((float4*)g_x)[i] = a;
}

__global__ void split_kernel(const float* __restrict__ in,
                             __nv_bfloat16* __restrict__ hi,
                             __nv_bfloat16* __restrict__ lo, int n4) {
    int i = blockIdx.x * 256 + threadIdx.x;
    if (i >= n4) return;
    float4 v = ((const float4*)in)[i];
    __nv_bfloat16 h0, h1, h2, h3, l0, l1, l2, l3;
    split2(v.x, h0, l0); split2(v.y, h1, l1);
    split2(v.z, h2, l2); split2(v.w, h3, l3);
    ((__nv_bfloat162*)hi)[i * 2 + 0] = __nv_bfloat162{h0, h1};
    ((__nv_bfloat162*)hi)[i * 2 + 1] = __nv_bfloat162{h2, h3};
    ((__nv_bfloat162*)lo)[i * 2 + 0] = __nv_bfloat162{l0, l1};
    ((__nv_bfloat162*)lo)[i * 2 + 1] = __nv_bfloat162{l2, l3};
}

__global__ void ln_kernel(const float* __restrict__ x,
                          const float* __restrict__ g,
                          const float* __restrict__ bta,
                          __nv_bfloat16* __restrict__ oh,
                          __nv_bfloat16* __restrict__ ol) {
    int token = blockIdx.x;
    int tid = threadIdx.x;
    float4 v = ((const float4*)(x + token * DD))[tid];
    float s = v.x + v.y + v.z + v.w;
    __shared__ float red[8];
    #pragma unroll
    for (int o = 16; o > 0; o >>= 1) s += __shfl_xor_sync(0xffffffffu, s, o);
    if ((tid & 31) == 0) red[tid >> 5] = s;
    __syncthreads();
    float mean = (red[0] + red[1] + red[2] + red[3]) * (1.0f / 512.0f);
    float dx = v.x - mean, dy = v.y - mean, dz = v.z - mean, dw = v.w - mean;
    float q = dx * dx + dy * dy + dz * dz + dw * dw;
    #pragma unroll
    for (int o = 16; o > 0; o >>= 1) q += __shfl_xor_sync(0xffffffffu, q, o);
    if ((tid & 31) == 0) red[4 + (tid >> 5)] = q;
    __syncthreads();
    float var = (red[4] + red[5] + red[6] + red[7]) * (1.0f / 512.0f);
    float r = rsqrtf(var + 1e-5f);
    float4 gg = ((const float4*)g)[tid];
    float4 bb = ((const float4*)bta)[tid];
    float o0 = dx * r * gg.x + bb.x, o1 = dy * r * gg.y + bb.y;
    float o2 = dz * r * gg.z + bb.z, o3 = dw * r * gg.w + bb.w;
    __nv_bfloat16 h0, h1, h2, h3, l0, l1, l2, l3;
    split2(o0, h0, l0); split2(o1, h1, l1); split2(o2, h2, l2); split2(o3, h3, l3);
    ((__nv_bfloat162*)(oh + token * DD))[tid * 2 + 0] = __nv_bfloat162{h0, h1};
    ((__nv_bfloat162*)(oh + token * DD))[tid * 2 + 1] = __nv_bfloat162{h2, h3};
    ((__nv_bfloat162*)(ol + token * DD))[tid * 2 + 0] = __nv_bfloat162{l0, l1};
    ((__nv_bfloat162*)(ol + token * DD))[tid * 2 + 1] = __nv_bfloat162{l2, l3};
}

__global__ void conv_silu_kernel(const float* __restrict__ w,
                                 const float* __restrict__ cb) {
    int i = blockIdx.x * 256 + threadIdx.x;
    int token = i >> 10;
    int d = i & (DI_ - 1);
    int t = token & (TT - 1);
    float acc = cb[d];
    #pragma unroll
    for (int j = 0; j < 4; j++) {
        int tt = t - 3 + j;
        if (tt >= 0) acc += g_xz[(token - 3 + j) * 2048 + d] * w[d * 4 + j];
    }
    float sg = 1.0f / (1.0f + __expf(-acc));
    float uv = acc * sg;
    g_u[i] = uv;
    __nv_bfloat16 h, l; split2(uv, h, l);
    g_uh[i] = h; g_ul[i] = l;
}

// ======== chunked selective scan (3 phases) ===============================
__device__ __forceinline__ void powers16(float r, float* p) {
    float r2 = r * r, r4 = r2 * r2, r8 = r4 * r4;
    p[0] = r;        p[1] = r2;       p[2] = r2 * r;   p[3] = r4;
    p[4] = r4 * r;   p[5] = r4 * r2;  p[6] = r4 * p[2]; p[7] = r8;
    p[8] = r8 * r;   p[9] = r8 * r2;  p[10] = r8 * p[2]; p[11] = r8 * r4;
    p[12] = r8 * p[4]; p[13] = r8 * p[5]; p[14] = r8 * p[6]; p[15] = r8 * r8;
}

__global__ void scan_p1(const float* __restrict__ A_log) {
    __shared__ float sB[TC][16];
    const int d = blockIdx.x * 128 + threadIdx.x;
    const int ch = blockIdx.y, b = blockIdx.z;
    const int t0 = ch * TC;
    for (int i = threadIdx.x; i < TC * 16; i += 128) {
        int tt = i >> 4, s = i & 15;
        sB[tt][s] = g_xdbl[(size_t)(b * TT + t0 + tt) * 64 + 32 + s];
    }
    __syncthreads();
    float es[16]; bool fast = true;
    #pragma unroll
    for (int s = 0; s < 16; s++) {
        es[s] = expf(A_log[d * 16 + s]);
        fast = fast && (fabsf(es[s] - (float)(s + 1)) < 1e-3f);
    }
    float h[16];
    #pragma unroll
    for (int s = 0; s < 16; s++) h[s] = 0.0f;
    float S = 0.0f;
    const float* pdt = g_dt + (size_t)(b * TT + t0) * DI_ + d;
    const float* pu  = g_u  + (size_t)(b * TT + t0) * DI_ + d;
    if (fast) {
        for (int t = 0; t < TC; t++) {
            float dt = pdt[t * DI_], u = pu[t * DI_];
            S += dt;
            float x = dt * u;
            float p[16]; powers16(__expf(-dt), p);
            #pragma unroll
            for (int s = 0; s < 16; s++) h[s] = p[s] * h[s] + x * sB[t][s];
        }
    } else {
        for (int t = 0; t < TC; t++) {
            float dt = pdt[t * DI_], u = pu[t * DI_];
            S += dt;
            float x = dt * u;
            #pragma unroll
            for (int s = 0; s < 16; s++)
                h[s] = __expf(-dt * es[s]) * h[s] + x * sB[t][s];
        }
    }
    size_t o = (((size_t)b * NCH + ch) * DI_ + d) * 16;
    #pragma unroll
    for (int s = 0; s < 16; s++) {
        g_sV[o + s] = h[s];
        g_sD[o + s] = __expf(-S * es[s]);
    }
}

__global__ void scan_p2() {
    const int d = blockIdx.x * 128 + threadIdx.x;
    const int b = blockIdx.y;
    float h[16];
    #pragma unroll
    for (int s = 0; s < 16; s++) h[s] = 0.0f;
    for (int ch = 0; ch < NCH; ch++) {
        size_t o = (((size_t)b * NCH + ch) * DI_ + d) * 16;
        #pragma unroll
        for (int s = 0; s < 16; s++) g_hin[o + s] = h[s];
        #pragma unroll
        for (int s = 0; s < 16; s++) h[s] = g_sD[o + s] * h[s] + g_sV[o + s];
    }
}

__global__ void scan_p3(const float* __restrict__ A_log,
                        const float* __restrict__ D_p) {
    __shared__ float sB[TC][16], sC[TC][16];
    const int d = blockIdx.x * 128 + threadIdx.x;
    const int ch = blockIdx.y, b = blockIdx.z;
    const int t0 = ch * TC;
    for (int i = threadIdx.x; i < TC * 16; i += 128) {
        int tt = i >> 4, s = i & 15;
        size_t base = (size_t)(b * TT + t0 + tt) * 64;
        sB[tt][s] = g_xdbl[base + 32 + s];
        sC[tt][s] = g_xdbl[base + 48 + s];
    }
    __syncthreads();
    float es[16]; bool fast = true;
    #pragma unroll
    for (int s = 0; s < 16; s++) {
        es[s] = expf(A_log[d * 16 + s]);
        fast = fast && (fabsf(es[s] - (float)(s + 1)) < 1e-3f);
    }
    float h[16];
    {
        size_t o = (((size_t)b * NCH + ch) * DI_ + d) * 16;
        #pragma unroll
        for (int s = 0; s < 16; s++) h[s] = g_hin[o + s];
    }
    const float Dp = D_p[d];
    const float* pdt = g_dt + (size_t)(b * TT + t0) * DI_ + d;
    const float* pu  = g_u  + (size_t)(b * TT + t0) * DI_ + d;
    const float* pz  = g_xz + (size_t)(b * TT + t0) * 2048 + DI_ + d;
    __nv_bfloat16* pyh = g_yh + (size_t)(b * TT + t0) * DI_ + d;
    __nv_bfloat16* pyl = g_yl + (size_t)(b * TT + t0) * DI_ + d;
    for (int t = 0; t < TC; t++) {
        float dt = pdt[t * DI_], u = pu[t * DI_], z = pz[t * 2048];
        float x = dt * u;
        float p[16];
        if (fast) powers16(__expf(-dt), p);
        else {
            #pragma unroll
            for (int s = 0; s < 16; s++) p[s] = __expf(-dt * es[s]);
        }
        #pragma unroll
        for (int s = 0; s < 16; s++) h[s] = p[s] * h[s] + x * sB[t][s];
        float q[8];
        #pragma unroll
        for (int i = 0; i < 8; i++)
            q[i] = fmaf(h[2 * i], sC[t][2 * i], h[2 * i + 1] * sC[t][2 * i + 1]);
        float yp = ((q[0] + q[1]) + (q[2] + q[3])) + ((q[4] + q[5]) + (q[6] + q[7]));
        float yv = yp + u * Dp;
        float ov = yv * (z / (1.0f + __expf(-z)));
        __nv_bfloat16 hh, ll; split2(ov, hh, ll);
        pyh[t * DI_] = hh; pyl[t * DI_] = ll;
    }
}

// ===================== HMMA split-bf16 GEMM (multi-stage) =================
#define F_BIAS 1
#define F_RELU 2
#define F_SOFT 4
#define F_RES  8
#define F_WF32 16
#define F_WPAIR 32

template <int BM, int BN, int WGM, int WGN, int NWARP, int STAGES, int FLAGS>
__global__ __launch_bounds__(NWARP * 32) void tgemm(
    int M, int N, int K, int lda, int ldb,
    const __nv_bfloat16* __restrict__ Ah, const __nv_bfloat16* __restrict__ Al,
    const __nv_bfloat16* __restrict__ Bh, const __nv_bfloat16* __restrict__ Bl,
    const float* __restrict__ bias, const float* __restrict__ res,
    float* __restrict__ Cf,
    __nv_bfloat16* __restrict__ Ch, __nv_bfloat16* __restrict__ Cl) {
    extern __shared__ char smem[];
    constexpr int NT = NWARP * 32;
    constexpr int PITCH = 80;
    constexpr int ASZ = BM * PITCH;
    constexpr int BSZ = BN * PITCH;
    constexpr int STAGE = 2 * ASZ + 2 * BSZ;
    constexpr int WROWS = BM / WGM, WCOLS = BN / WGN;
    constexpr int MI = WROWS / 16, NI = WCOLS / 8, NP = NI / 2;
    const int tid = threadIdx.x, lane = tid & 31, wid = tid >> 5;
    const int wm = wid / WGN, wn = wid % WGN;
    const int bm = blockIdx.y * BM, bn = blockIdx.x * BN;
    const uint32_t sb = smem_u32(smem);
    const int nc = K / 32;

    float acc[MI][NI][4];
    #pragma unroll
    for (int i = 0; i < MI; i++)
        #pragma unroll
        for (int j = 0; j < NI; j++)
            #pragma unroll
            for (int q = 0; q < 4; q++) acc[i][j][q] = 0.0f;

    auto prefetch = [&](int c, int slot) {
        if (c >= nc) return;
        const uint32_t sbase = sb + slot * STAGE;
        const int k0 = c * 32;
        #pragma unroll
        for (int i = 0; i < (BM * 4 + NT - 1) / NT; i++) {
            int ch = tid + i * NT;
            if ((BM * 4 % NT == 0) || ch < BM * 4) {
                int row = ch >> 2, kc = ch & 3;
                uint32_t doff = row * PITCH + kc * 16;
                size_t goff = (size_t)(bm + row) * lda + k0 + kc * 8;
                CP16(sbase + doff, (const char*)(Ah + goff));
                CP16(sbase + ASZ + doff, (const char*)(Al + goff));
            }
        }
        #pragma unroll
        for (int i = 0; i < (BN * 4 + NT - 1) / NT; i++) {
            int ch = tid + i * NT;
            if ((BN * 4 % NT == 0) || ch < BN * 4) {
                int row = ch >> 2, kc = ch & 3;
                uint32_t doff = row * PITCH + kc * 16;
                size_t goff = (size_t)(bn + row) * ldb + k0 + kc * 8;
                CP16(sbase + 2 * ASZ + doff, (const char*)(Bh + goff));
                CP16(sbase + 2 * ASZ + BSZ + doff, (const char*)(Bl + goff));
            }
        }
    };

    auto compute = [&](int s) {
        const uint32_t sbase = sb + s * STAGE;
        const uint32_t arow = (uint32_t)(lane & 15);
        const uint32_t asel = (uint32_t)((lane >> 4) * 16);
        #pragma unroll
        for (int kk = 0; kk < 2; kk++) {
            const uint32_t kb = kk * 32;
            uint32_t ah[MI][4], al[MI][4];
            #pragma unroll
            for (int mi = 0; mi < MI; mi++) {
                uint32_t ad = sbase + (wm * WROWS + mi * 16 + arow) * PITCH + kb + asel;
                ldsm4(ah[mi], ad);
                ldsm4(al[mi], ad + ASZ);
            }
            #pragma unroll
            for (int p = 0; p < NP; p++) {
                uint32_t bd = sbase + 2 * ASZ +
                              (wn * WCOLS + p * 16 + arow) * PITCH + kb + asel;
                uint32_t th[4], tl[4];
                ldsm4(th, bd);
                ldsm4(tl, bd + BSZ);
                uint32_t bh0[2] = {th[0], th[2]}, bh1[2] = {th[1], th[3]};
                uint32_t bl0[2] = {tl[0], tl[2]}, bl1[2] = {tl[1], tl[3]};
                #pragma unroll
                for (int mi = 0; mi < MI; mi++) {
                    mma16816(acc[mi][2 * p], ah[mi], bh0);
                    mma16816(acc[mi][2 * p], ah[mi], bl0);
                    mma16816(acc[mi][2 * p], al[mi], bh0);
                    mma16816(acc[mi][2 * p + 1], ah[mi], bh1);
                    mma16816(acc[mi][2 * p + 1], ah[mi], bl1);
                    mma16816(acc[mi][2 * p + 1], al[mi], bh1);
                }
            }
        }
    };

    #pragma unroll
    for (int c = 0; c < STAGES - 1; c++) { prefetch(c, c); CP_COMMIT(); }
    int ps = (STAGES - 1) % STAGES, cs = 0;
    for (int c = 0; c < nc; c++) {
        cp_wait<STAGES - 2>();
        __syncthreads();
        prefetch(c + STAGES - 1, ps); CP_COMMIT();
        compute(cs);
        ps = (ps + 1 == STAGES) ? 0 : ps + 1;
        cs = (cs + 1 == STAGES) ? 0 : cs + 1;
    }

    // ---- epilogue: direct fragment stores ----
    #pragma unroll
    for (int mi = 0; mi < MI; mi++) {
        #pragma unroll
        for (int ni = 0; ni < NI; ni++) {
            const int r0 = bm + wm * WROWS + mi * 16 + (lane >> 2);
            const int c0 = bn + wn * WCOLS + ni * 8 + (lane & 3) * 2;
            #pragma unroll
            for (int hh = 0; hh < 2; hh++) {
                const int r = r0 + hh * 8;
                float v0 = acc[mi][ni][hh * 2 + 0];
                float v1 = acc[mi][ni][hh * 2 + 1];
                if (FLAGS & F_BIAS) { v0 += bias[c0]; v1 += bias[c0 + 1]; }
                if (FLAGS & F_RELU) { v0 = fmaxf(v0, 0.f); v1 = fmaxf(v1, 0.f); }
                if (FLAGS & F_SOFT) {
                    v0 = (v0 > 20.f) ? v0 : log1pf(expf(v0));
                    v1 = (v1 > 20.f) ? v1 : log1pf(expf(v1));
                }
                if (FLAGS & F_RES) {
                    float2 rr = *(const float2*)(res + (size_t)r * N + c0);
                    v0 += rr.x; v1 += rr.y;
                }
                if (FLAGS & F_WF32) {
                    *(float2*)(Cf + (size_t)r * N + c0) = make_float2(v0, v1);
                }
                if (FLAGS & F_WPAIR) {
                    __nv_bfloat16 h0, h1, l0, l1;
                    split2(v0, h0, l0); split2(v1, h1, l1);
                    *(__nv_bfloat162*)(Ch + (size_t)r * N + c0) = __nv_bfloat162{h0, h1};
                    *(__nv_bfloat162*)(Cl + (size_t)r * N + c0) = __nv_bfloat162{l0, l1};
                }
            }
        }
    }
}

// ===================== host orchestration =================================
template <int BM, int BN, int WGM, int WGN, int NWARP, int STAGES, int FLAGS>
static void launch_tgemm(int M, int N, int K, int lda, int ldb,
                         const __nv_bfloat16* Ah, const __nv_bfloat16* Al,
                         const __nv_bfloat16* Bh, const __nv_bfloat16* Bl,
                         const float* bias, const float* res,
                         float* Cf, __nv_bfloat16* Ch, __nv_bfloat16* Cl) {
    constexpr int PITCH = 80;
    constexpr int STAGE = 2 * BM * PITCH + 2 * BN * PITCH;
    const int smem_bytes = STAGES * STAGE;
    cudaFuncSetAttribute(tgemm<BM, BN, WGM, WGN, NWARP, STAGES, FLAGS>,
                         cudaFuncAttributeMaxDynamicSharedMemorySize, smem_bytes);
    dim3 grid(N / BN, M / BM);
    tgemm<BM, BN, WGM, WGN, NWARP, STAGES, FLAGS>
        <<<grid, NWARP * 32, smem_bytes>>>(M, N, K, lda, ldb,
        Ah, Al, Bh, Bl, bias, res, Cf, Ch, Cl);
}

extern "C" void kernel_launch(void* const* d_in, const int* in_sizes, int n_in,
                              void* d_out, int out_size) {
    const int*   idx   = (const int*)d_in[0];
    const float* tok   = (const float*)d_in[1];
    const float* pos   = (const float*)d_in[2];
    const float* ln1g  = (const float*)d_in[3];
    const float* ln1b  = (const float*)d_in[4];
    const float* W_in  = (const float*)d_in[5];
    const float* convw = (const float*)d_in[6];
    const float* convb = (const float*)d_in[7];
    const float* W_xp  = (const float*)d_in[8];
    const float* W_dt  = (const float*)d_in[9];
    const float* b_dt  = (const float*)d_in[10];
    const float* A_log = (const float*)d_in[11];
    const float* D_p   = (const float*)d_in[12];
    const float* W_out = (const float*)d_in[13];
    const float* ln2g  = (const float*)d_in[14];
    const float* ln2b  = (const float*)d_in[15];
    const float* W_f1  = (const float*)d_in[16];
    const float* b_f1  = (const float*)d_in[17];
    const float* W_f2  = (const float*)d_in[18];
    const float* b_f2  = (const float*)d_in[19];
    const float* lm_w  = (const float*)d_in[20];
    const float* lm_b  = (const float*)d_in[21];
    float* out = (float*)d_out;

    float *px, *pxz, *pu, *pxd, *pdt;
    __nv_bfloat16 *phh, *phl, *puh, *pul, *pxdh, *pxdl, *pyh, *pyl;
    __nv_bfloat16 *phidh, *phidl, *pxh, *pxl;
    __nv_bfloat16 *wInh, *wInl, *wXph, *wXpl, *wDth, *wDtl, *wOuth, *wOutl;
    __nv_bfloat16 *wF1h, *wF1l, *wF2h, *wF2l, *wLmh, *wLml;

    cudaGetSymbolAddress((void**)&px,   g_x);
    cudaGetSymbolAddress((void**)&pxz,  g_xz);
    cudaGetSymbolAddress((void**)&pu,   g_u);
    cudaGetSymbolAddress((void**)&pxd,  g_xdbl);
    cudaGetSymbolAddress((void**)&pdt,  g_dt);
    cudaGetSymbolAddress((void**)&phh,  g_hh);  cudaGetSymbolAddress((void**)&phl,  g_hl);
    cudaGetSymbolAddress((void**)&puh,  g_uh);  cudaGetSymbolAddress((void**)&pul,  g_ul);
    cudaGetSymbolAddress((void**)&pxdh, g_xdh); cudaGetSymbolAddress((void**)&pxdl, g_xdl);
    cudaGetSymbolAddress((void**)&pyh,  g_yh);  cudaGetSymbolAddress((void**)&pyl,  g_yl);
    cudaGetSymbolAddress((void**)&phidh,g_hidh);cudaGetSymbolAddress((void**)&phidl,g_hidl);
    cudaGetSymbolAddress((void**)&pxh,  g_xh);  cudaGetSymbolAddress((void**)&pxl,  g_xl);
    cudaGetSymbolAddress((void**)&wInh, g_Winh); cudaGetSymbolAddress((void**)&wInl, g_Winl);
    cudaGetSymbolAddress((void**)&wXph, g_Wxph); cudaGetSymbolAddress((void**)&wXpl, g_Wxpl);
    cudaGetSymbolAddress((void**)&wDth, g_Wdth); cudaGetSymbolAddress((void**)&wDtl, g_Wdtl);
    cudaGetSymbolAddress((void**)&wOuth,g_Wouth);cudaGetSymbolAddress((void**)&wOutl,g_Woutl);
    cudaGetSymbolAddress((void**)&wF1h, g_Wf1h); cudaGetSymbolAddress((void**)&wF1l, g_Wf1l);
    cudaGetSymbolAddress((void**)&wF2h, g_Wf2h); cudaGetSymbolAddress((void**)&wF2l, g_Wf2l);
    cudaGetSymbolAddress((void**)&wLmh, g_lmh);  cudaGetSymbolAddress((void**)&wLml, g_lml);

    auto split = [&](const float* src, __nv_bfloat16* h, __nv_bfloat16* l, long n) {
        int n4 = (int)(n / 4);
        split_kernel<<<(n4 + 255) / 256, 256>>>(src, h, l, n4);
    };

    split(W_in,  wInh,  wInl,  (long)LYR * 2048 * DD);
    split(W_xp,  wXph,  wXpl,  (long)LYR * 64 * DI_);
    split(W_dt,  wDth,  wDtl,  (long)LYR * DI_ * 32);
    split(W_out, wOuth, wOutl, (long)LYR * DD * DI_);
    split(W_f1,  wF1h,  wF1l,  (long)LYR * 2048 * DD);
    split(W_f2,  wF2h,  wF2l,  (long)LYR * DD * 2048);
    split(lm_w,  wLmh,  wLml,  (long)VOC * DD);

    embed_kernel<<<1024, 256>>>(idx, tok, pos);

    for (int l = 0; l < LYR; l++) {
        ln_kernel<<<MTOK, 128>>>(px, ln1g + l * DD, ln1b + l * DD, phh, phl);
        // xz = h @ W_in^T  [2048,2048]  — big-tile config
        launch_tgemm<128, 256, 2, 4, 8, 3, F_WF32>(MTOK, 2048, DD, DD, DD,
            phh, phl, wInh + (long)l * 2048 * DD, wInl + (long)l * 2048 * DD,
            nullptr, nullptr, pxz, nullptr, nullptr);
        conv_silu_kernel<<<MTOK * DI_ / 256, 256>>>(convw + l * DI_ * 4, convb + l * DI_);
        launch_tgemm<64, 64, 4, 4, 16, 4, F_WF32 | F_WPAIR>(MTOK, 64, DI_, DI_, DI_,
            puh, pul, wXph + (long)l * 64 * DI_, wXpl + (long)l * 64 * DI_,
            nullptr, nullptr, pxd, pxdh, pxdl);
        launch_tgemm<128, 128, 4, 4, 16, 4, F_BIAS | F_SOFT | F_WF32>(
            MTOK, DI_, 32, 64, 32,
            pxdh, pxdl, wDth + (long)l * DI_ * 32, wDtl + (long)l * DI_ * 32,
            b_dt + l * DI_, nullptr, pdt, nullptr, nullptr);
        scan_p1<<<dim3(8, NCH, 2), 128>>>(A_log + (long)l * DI_ * DS_);
        scan_p2<<<dim3(8, 2), 128>>>();
        scan_p3<<<dim3(8, NCH, 2), 128>>>(A_log + (long)l * DI_ * DS_, D_p + l * DI_);
        launch_tgemm<64, 128, 2, 8, 16, 4, F_RES | F_WF32>(MTOK, DD, DI_, DI_, DI_,
            pyh, pyl, wOuth + (long)l * DD * DI_, wOutl + (long)l * DD * DI_,
            nullptr, px, px, nullptr, nullptr);
        ln_kernel<<<MTOK, 128>>>(px, ln2g + l * DD, ln2b + l * DD, phh, phl);
        // hidden = relu(h @ W_f1^T + b_f1)  [2048,2048] — big-tile config
        launch_tgemm<128, 256, 2, 4, 8, 3, F_BIAS | F_RELU | F_WPAIR>(
            MTOK, 2048, DD, DD, DD,
            phh, phl, wF1h + (long)l * 2048 * DD, wF1l + (long)l * 2048 * DD,
            b_f1 + l * 2048, nullptr, nullptr, phidh, phidl);
        launch_tgemm<64, 128, 2, 8, 16, 4, F_BIAS | F_RES | F_WF32 | F_WPAIR>(
            MTOK, DD, 2048, 2048, 2048,
            phidh, phidl, wF2h + (long)l * DD * 2048, wF2l + (long)l * DD * 2048,
            b_f2 + l * DD, px, px, pxh, pxl);
    }

    // logits = x @ lm_w^T + lm_b  [2048,32000] — big-tile config
    launch_tgemm<128, 256, 2, 4, 8, 3, F_BIAS | F_WF32>(MTOK, VOC, DD, DD, DD,
        pxh, pxl, wLmh, wLml, lm_b, nullptr, out, nullptr, nullptr);
}

// round 9
// speedup vs baseline: 3.4411x; 1.0176x over previous
#include <cuda_runtime.h>
#include <cuda_bf16.h>
#include <math.h>
#include <stdint.h>

#define MTOK 2048
#define TT   1024
#define DD   512
#define DI_  1024
#define DS_  16
#define LYR  4
#define VOC  32000
#define TC   64
#define NCH  16

// ===================== PTX helpers (plain sm_103-safe) =====================
__device__ __forceinline__ uint32_t smem_u32(const void* p) {
    uint32_t a;
    asm("{ .reg .u64 t; cvta.to.shared.u64 t, %1; cvt.u32.u64 %0, t; }"
        : "=r"(a) : "l"(p));
    return a;
}
#define CP16(dst, src) \
    asm volatile("cp.async.cg.shared.global [%0], [%1], 16;" \
                 :: "r"(dst), "l"(src) : "memory")
#define CP_COMMIT() asm volatile("cp.async.commit_group;" ::: "memory")
template <int n>
__device__ __forceinline__ void cp_wait() {
    asm volatile("cp.async.wait_group %0;" :: "n"(n) : "memory");
}

__device__ __forceinline__ void ldsm4(uint32_t* r, uint32_t addr) {
    asm volatile("ldmatrix.sync.aligned.m8n8.x4.shared.b16 {%0,%1,%2,%3}, [%4];"
                 : "=r"(r[0]), "=r"(r[1]), "=r"(r[2]), "=r"(r[3]) : "r"(addr));
}
__device__ __forceinline__ void mma16816(float* d, const uint32_t* a,
                                         const uint32_t* b) {
    asm volatile(
        "mma.sync.aligned.m16n8k16.row.col.f32.bf16.bf16.f32 "
        "{%0,%1,%2,%3}, {%4,%5,%6,%7}, {%8,%9}, {%0,%1,%2,%3};"
        : "+f"(d[0]), "+f"(d[1]), "+f"(d[2]), "+f"(d[3])
        : "r"(a[0]), "r"(a[1]), "r"(a[2]), "r"(a[3]), "r"(b[0]), "r"(b[1]));
}

__device__ __forceinline__ void split2(float v, __nv_bfloat16& h, __nv_bfloat16& l) {
    h = __float2bfloat16(v);
    l = __float2bfloat16(v - __bfloat162float(h));
}

// ===================== device-global scratch ==============================
__device__ __align__(256) float g_x   [MTOK * DD];
__device__ __align__(256) float g_xz  [MTOK * 2048];
__device__ __align__(256) float g_u   [MTOK * DI_];
__device__ __align__(256) float g_xdbl[MTOK * 64];
__device__ __align__(256) float g_dt  [MTOK * DI_];

__device__ __align__(256) float g_sD [2 * NCH * DI_ * DS_];
__device__ __align__(256) float g_sV [2 * NCH * DI_ * DS_];
__device__ __align__(256) float g_hin[2 * NCH * DI_ * DS_];

__device__ __align__(256) __nv_bfloat16 g_hh[MTOK * DD];
__device__ __align__(256) __nv_bfloat16 g_hl[MTOK * DD];
__device__ __align__(256) __nv_bfloat16 g_uh[MTOK * DI_];
__device__ __align__(256) __nv_bfloat16 g_ul[MTOK * DI_];
__device__ __align__(256) __nv_bfloat16 g_xdh[MTOK * 64];
__device__ __align__(256) __nv_bfloat16 g_xdl[MTOK * 64];
__device__ __align__(256) __nv_bfloat16 g_yh[MTOK * DI_];
__device__ __align__(256) __nv_bfloat16 g_yl[MTOK * DI_];
__device__ __align__(256) __nv_bfloat16 g_hidh[MTOK * 2048];
__device__ __align__(256) __nv_bfloat16 g_hidl[MTOK * 2048];
__device__ __align__(256) __nv_bfloat16 g_xh[MTOK * DD];
__device__ __align__(256) __nv_bfloat16 g_xl[MTOK * DD];

__device__ __align__(256) __nv_bfloat16 g_Winh [LYR * 2048 * DD];
__device__ __align__(256) __nv_bfloat16 g_Winl [LYR * 2048 * DD];
__device__ __align__(256) __nv_bfloat16 g_Wxph [LYR * 64 * DI_];
__device__ __align__(256) __nv_bfloat16 g_Wxpl [LYR * 64 * DI_];
__device__ __align__(256) __nv_bfloat16 g_Wdth [LYR * DI_ * 32];
__device__ __align__(256) __nv_bfloat16 g_Wdtl [LYR * DI_ * 32];
__device__ __align__(256) __nv_bfloat16 g_Wouth[LYR * DD * DI_];
__device__ __align__(256) __nv_bfloat16 g_Woutl[LYR * DD * DI_];
__device__ __align__(256) __nv_bfloat16 g_Wf1h [LYR * 2048 * DD];
__device__ __align__(256) __nv_bfloat16 g_Wf1l [LYR * 2048 * DD];
__device__ __align__(256) __nv_bfloat16 g_Wf2h [LYR * DD * 2048];
__device__ __align__(256) __nv_bfloat16 g_Wf2l [LYR * DD * 2048];
__device__ __align__(256) __nv_bfloat16 g_lmh  [VOC * DD];
__device__ __align__(256) __nv_bfloat16 g_lml  [VOC * DD];

// ===================== small kernels ======================================
__global__ void embed_kernel(const int* __restrict__ idx,
                             const float* __restrict__ tok,
                             const float* __restrict__ pos) {
    int i = blockIdx.x * 256 + threadIdx.x;
    int token = i >> 7;
    int c = i & 127;
    int t = token & (TT - 1);
    int row = idx[token];
    float4 a = ((const float4*)tok)[row * 128 + c];
    float4 p = ((const float4*)pos)[t * 128 + c];
    a.x += p.x; a.y += p.y; a.z += p.z; a.w += p.w;
    ((float4*)g_x)[i] = a;
}

__global__ void split_kernel(const float* __restrict__ in,
                             __nv_bfloat16* __restrict__ hi,
                             __nv_bfloat16* __restrict__ lo, int n4) {
    int i = blockIdx.x * 256 + threadIdx.x;
    if (i >= n4) return;
    float4 v = ((const float4*)in)[i];
    __nv_bfloat16 h0, h1, h2, h3, l0, l1, l2, l3;
    split2(v.x, h0, l0); split2(v.y, h1, l1);
    split2(v.z, h2, l2); split2(v.w, h3, l3);
    ((__nv_bfloat162*)hi)[i * 2 + 0] = __nv_bfloat162{h0, h1};
    ((__nv_bfloat162*)hi)[i * 2 + 1] = __nv_bfloat162{h2, h3};
    ((__nv_bfloat162*)lo)[i * 2 + 0] = __nv_bfloat162{l0, l1};
    ((__nv_bfloat162*)lo)[i * 2 + 1] = __nv_bfloat162{l2, l3};
}

__global__ void ln_kernel(const float* __restrict__ x,
                          const float* __restrict__ g,
                          const float* __restrict__ bta,
                          __nv_bfloat16* __restrict__ oh,
                          __nv_bfloat16* __restrict__ ol) {
    int token = blockIdx.x;
    int tid = threadIdx.x;
    float4 v = ((const float4*)(x + token * DD))[tid];
    float s = v.x + v.y + v.z + v.w;
    __shared__ float red[8];
    #pragma unroll
    for (int o = 16; o > 0; o >>= 1) s += __shfl_xor_sync(0xffffffffu, s, o);
    if ((tid & 31) == 0) red[tid >> 5] = s;
    __syncthreads();
    float mean = (red[0] + red[1] + red[2] + red[3]) * (1.0f / 512.0f);
    float dx = v.x - mean, dy = v.y - mean, dz = v.z - mean, dw = v.w - mean;
    float q = dx * dx + dy * dy + dz * dz + dw * dw;
    #pragma unroll
    for (int o = 16; o > 0; o >>= 1) q += __shfl_xor_sync(0xffffffffu, q, o);
    if ((tid & 31) == 0) red[4 + (tid >> 5)] = q;
    __syncthreads();
    float var = (red[4] + red[5] + red[6] + red[7]) * (1.0f / 512.0f);
    float r = rsqrtf(var + 1e-5f);
    float4 gg = ((const float4*)g)[tid];
    float4 bb = ((const float4*)bta)[tid];
    float o0 = dx * r * gg.x + bb.x, o1 = dy * r * gg.y + bb.y;
    float o2 = dz * r * gg.z + bb.z, o3 = dw * r * gg.w + bb.w;
    __nv_bfloat16 h0, h1, h2, h3, l0, l1, l2, l3;
    split2(o0, h0, l0); split2(o1, h1, l1); split2(o2, h2, l2); split2(o3, h3, l3);
    ((__nv_bfloat162*)(oh + token * DD))[tid * 2 + 0] = __nv_bfloat162{h0, h1};
    ((__nv_bfloat162*)(oh + token * DD))[tid * 2 + 1] = __nv_bfloat162{h2, h3};
    ((__nv_bfloat162*)(ol + token * DD))[tid * 2 + 0] = __nv_bfloat162{l0, l1};
    ((__nv_bfloat162*)(ol + token * DD))[tid * 2 + 1] = __nv_bfloat162{l2, l3};
}

__global__ void conv_silu_kernel(const float* __restrict__ w,
                                 const float* __restrict__ cb) {
    int i = blockIdx.x * 256 + threadIdx.x;
    int token = i >> 10;
    int d = i & (DI_ - 1);
    int t = token & (TT - 1);
    float acc = cb[d];
    #pragma unroll
    for (int j = 0; j < 4; j++) {
        int tt = t - 3 + j;
        if (tt >= 0) acc += g_xz[(token - 3 + j) * 2048 + d] * w[d * 4 + j];
    }
    float sg = 1.0f / (1.0f + __expf(-acc));
    float uv = acc * sg;
    g_u[i] = uv;
    __nv_bfloat16 h, l; split2(uv, h, l);
    g_uh[i] = h; g_ul[i] = l;
}

// ======== chunked selective scan (3 phases) ===============================
__device__ __forceinline__ void powers16(float r, float* p) {
    float r2 = r * r, r4 = r2 * r2, r8 = r4 * r4;
    p[0] = r;        p[1] = r2;       p[2] = r2 * r;   p[3] = r4;
    p[4] = r4 * r;   p[5] = r4 * r2;  p[6] = r4 * p[2]; p[7] = r8;
    p[8] = r8 * r;   p[9] = r8 * r2;  p[10] = r8 * p[2]; p[11] = r8 * r4;
    p[12] = r8 * p[4]; p[13] = r8 * p[5]; p[14] = r8 * p[6]; p[15] = r8 * r8;
}

__global__ void scan_p1(const float* __restrict__ A_log) {
    __shared__ float sB[TC][16];
    const int d = blockIdx.x * 128 + threadIdx.x;
    const int ch = blockIdx.y, b = blockIdx.z;
    const int t0 = ch * TC;
    for (int i = threadIdx.x; i < TC * 16; i += 128) {
        int tt = i >> 4, s = i & 15;
        sB[tt][s] = g_xdbl[(size_t)(b * TT + t0 + tt) * 64 + 32 + s];
    }
    __syncthreads();
    float es[16]; bool fast = true;
    #pragma unroll
    for (int s = 0; s < 16; s++) {
        es[s] = expf(A_log[d * 16 + s]);
        fast = fast && (fabsf(es[s] - (float)(s + 1)) < 1e-3f);
    }
    float h[16];
    #pragma unroll
    for (int s = 0; s < 16; s++) h[s] = 0.0f;
    float S = 0.0f;
    const float* pdt = g_dt + (size_t)(b * TT + t0) * DI_ + d;
    const float* pu  = g_u  + (size_t)(b * TT + t0) * DI_ + d;
    if (fast) {
        for (int t = 0; t < TC; t++) {
            float dt = pdt[t * DI_], u = pu[t * DI_];
            S += dt;
            float x = dt * u;
            float p[16]; powers16(__expf(-dt), p);
            #pragma unroll
            for (int s = 0; s < 16; s++) h[s] = p[s] * h[s] + x * sB[t][s];
        }
    } else {
        for (int t = 0; t < TC; t++) {
            float dt = pdt[t * DI_], u = pu[t * DI_];
            S += dt;
            float x = dt * u;
            #pragma unroll
            for (int s = 0; s < 16; s++)
                h[s] = __expf(-dt * es[s]) * h[s] + x * sB[t][s];
        }
    }
    size_t o = (((size_t)b * NCH + ch) * DI_ + d) * 16;
    #pragma unroll
    for (int s = 0; s < 16; s++) {
        g_sV[o + s] = h[s];
        g_sD[o + s] = __expf(-S * es[s]);
    }
}

__global__ void scan_p2() {
    const int d = blockIdx.x * 128 + threadIdx.x;
    const int b = blockIdx.y;
    float h[16];
    #pragma unroll
    for (int s = 0; s < 16; s++) h[s] = 0.0f;
    for (int ch = 0; ch < NCH; ch++) {
        size_t o = (((size_t)b * NCH + ch) * DI_ + d) * 16;
        #pragma unroll
        for (int s = 0; s < 16; s++) g_hin[o + s] = h[s];
        #pragma unroll
        for (int s = 0; s < 16; s++) h[s] = g_sD[o + s] * h[s] + g_sV[o + s];
    }
}

__global__ void scan_p3(const float* __restrict__ A_log,
                        const float* __restrict__ D_p) {
    __shared__ float sB[TC][16], sC[TC][16];
    const int d = blockIdx.x * 128 + threadIdx.x;
    const int ch = blockIdx.y, b = blockIdx.z;
    const int t0 = ch * TC;
    for (int i = threadIdx.x; i < TC * 16; i += 128) {
        int tt = i >> 4, s = i & 15;
        size_t base = (size_t)(b * TT + t0 + tt) * 64;
        sB[tt][s] = g_xdbl[base + 32 + s];
        sC[tt][s] = g_xdbl[base + 48 + s];
    }
    __syncthreads();
    float es[16]; bool fast = true;
    #pragma unroll
    for (int s = 0; s < 16; s++) {
        es[s] = expf(A_log[d * 16 + s]);
        fast = fast && (fabsf(es[s] - (float)(s + 1)) < 1e-3f);
    }
    float h[16];
    {
        size_t o = (((size_t)b * NCH + ch) * DI_ + d) * 16;
        #pragma unroll
        for (int s = 0; s < 16; s++) h[s] = g_hin[o + s];
    }
    const float Dp = D_p[d];
    const float* pdt = g_dt + (size_t)(b * TT + t0) * DI_ + d;
    const float* pu  = g_u  + (size_t)(b * TT + t0) * DI_ + d;
    const float* pz  = g_xz + (size_t)(b * TT + t0) * 2048 + DI_ + d;
    __nv_bfloat16* pyh = g_yh + (size_t)(b * TT + t0) * DI_ + d;
    __nv_bfloat16* pyl = g_yl + (size_t)(b * TT + t0) * DI_ + d;
    for (int t = 0; t < TC; t++) {
        float dt = pdt[t * DI_], u = pu[t * DI_], z = pz[t * 2048];
        float x = dt * u;
        float p[16];
        if (fast) powers16(__expf(-dt), p);
        else {
            #pragma unroll
            for (int s = 0; s < 16; s++) p[s] = __expf(-dt * es[s]);
        }
        #pragma unroll
        for (int s = 0; s < 16; s++) h[s] = p[s] * h[s] + x * sB[t][s];
        float q[8];
        #pragma unroll
        for (int i = 0; i < 8; i++)
            q[i] = fmaf(h[2 * i], sC[t][2 * i], h[2 * i + 1] * sC[t][2 * i + 1]);
        float yp = ((q[0] + q[1]) + (q[2] + q[3])) + ((q[4] + q[5]) + (q[6] + q[7]));
        float yv = yp + u * Dp;
        float ov = yv * (z / (1.0f + __expf(-z)));
        __nv_bfloat16 hh, ll; split2(ov, hh, ll);
        pyh[t * DI_] = hh; pyl[t * DI_] = ll;
    }
}

// ===================== HMMA split-bf16 GEMM (multi-stage) =================
#define F_BIAS 1
#define F_RELU 2
#define F_SOFT 4
#define F_RES  8
#define F_WF32 16
#define F_WPAIR 32

template <int BM, int BN, int WGM, int WGN, int NWARP, int STAGES, int FLAGS>
__global__ __launch_bounds__(NWARP * 32) void tgemm(
    int M, int N, int K, int lda, int ldb,
    const __nv_bfloat16* __restrict__ Ah, const __nv_bfloat16* __restrict__ Al,
    const __nv_bfloat16* __restrict__ Bh, const __nv_bfloat16* __restrict__ Bl,
    const float* __restrict__ bias, const float* __restrict__ res,
    float* __restrict__ Cf,
    __nv_bfloat16* __restrict__ Ch, __nv_bfloat16* __restrict__ Cl) {
    extern __shared__ char smem[];
    constexpr int NT = NWARP * 32;
    constexpr int PITCH = 80;
    constexpr int ASZ = BM * PITCH;
    constexpr int BSZ = BN * PITCH;
    constexpr int STAGE = 2 * ASZ + 2 * BSZ;
    constexpr int WROWS = BM / WGM, WCOLS = BN / WGN;
    constexpr int MI = WROWS / 16, NI = WCOLS / 8, NP = NI / 2;
    const int tid = threadIdx.x, lane = tid & 31, wid = tid >> 5;
    const int wm = wid / WGN, wn = wid % WGN;
    const int bm = blockIdx.y * BM, bn = blockIdx.x * BN;
    const uint32_t sb = smem_u32(smem);
    const int nc = K / 32;

    float acc[MI][NI][4];
    #pragma unroll
    for (int i = 0; i < MI; i++)
        #pragma unroll
        for (int j = 0; j < NI; j++)
            #pragma unroll
            for (int q = 0; q < 4; q++) acc[i][j][q] = 0.0f;

    auto prefetch = [&](int c, int slot) {
        if (c >= nc) return;
        const uint32_t sbase = sb + slot * STAGE;
        const int k0 = c * 32;
        #pragma unroll
        for (int i = 0; i < (BM * 4 + NT - 1) / NT; i++) {
            int ch = tid + i * NT;
            if ((BM * 4 % NT == 0) || ch < BM * 4) {
                int row = ch >> 2, kc = ch & 3;
                uint32_t doff = row * PITCH + kc * 16;
                size_t goff = (size_t)(bm + row) * lda + k0 + kc * 8;
                CP16(sbase + doff, (const char*)(Ah + goff));
                CP16(sbase + ASZ + doff, (const char*)(Al + goff));
            }
        }
        #pragma unroll
        for (int i = 0; i < (BN * 4 + NT - 1) / NT; i++) {
            int ch = tid + i * NT;
            if ((BN * 4 % NT == 0) || ch < BN * 4) {
                int row = ch >> 2, kc = ch & 3;
                uint32_t doff = row * PITCH + kc * 16;
                size_t goff = (size_t)(bn + row) * ldb + k0 + kc * 8;
                CP16(sbase + 2 * ASZ + doff, (const char*)(Bh + goff));
                CP16(sbase + 2 * ASZ + BSZ + doff, (const char*)(Bl + goff));
            }
        }
    };

    auto compute = [&](int s) {
        const uint32_t sbase = sb + s * STAGE;
        const uint32_t arow = (uint32_t)(lane & 15);
        const uint32_t asel = (uint32_t)((lane >> 4) * 16);
        #pragma unroll
        for (int kk = 0; kk < 2; kk++) {
            const uint32_t kb = kk * 32;
            uint32_t ah[MI][4], al[MI][4];
            #pragma unroll
            for (int mi = 0; mi < MI; mi++) {
                uint32_t ad = sbase + (wm * WROWS + mi * 16 + arow) * PITCH + kb + asel;
                ldsm4(ah[mi], ad);
                ldsm4(al[mi], ad + ASZ);
            }
            #pragma unroll
            for (int p = 0; p < NP; p++) {
                uint32_t bd = sbase + 2 * ASZ +
                              (wn * WCOLS + p * 16 + arow) * PITCH + kb + asel;
                uint32_t th[4], tl[4];
                ldsm4(th, bd);
                ldsm4(tl, bd + BSZ);
                uint32_t bh0[2] = {th[0], th[2]}, bh1[2] = {th[1], th[3]};
                uint32_t bl0[2] = {tl[0], tl[2]}, bl1[2] = {tl[1], tl[3]};
                #pragma unroll
                for (int mi = 0; mi < MI; mi++) {
                    mma16816(acc[mi][2 * p], ah[mi], bh0);
                    mma16816(acc[mi][2 * p], ah[mi], bl0);
                    mma16816(acc[mi][2 * p], al[mi], bh0);
                    mma16816(acc[mi][2 * p + 1], ah[mi], bh1);
                    mma16816(acc[mi][2 * p + 1], ah[mi], bl1);
                    mma16816(acc[mi][2 * p + 1], al[mi], bh1);
                }
            }
        }
    };

    #pragma unroll
    for (int c = 0; c < STAGES - 1; c++) { prefetch(c, c); CP_COMMIT(); }
    int ps = (STAGES - 1) % STAGES, cs = 0;
    for (int c = 0; c < nc; c++) {
        cp_wait<STAGES - 2>();
        __syncthreads();
        prefetch(c + STAGES - 1, ps); CP_COMMIT();
        compute(cs);
        ps = (ps + 1 == STAGES) ? 0 : ps + 1;
        cs = (cs + 1 == STAGES) ? 0 : cs + 1;
    }

    // ---- epilogue: direct fragment stores ----
    #pragma unroll
    for (int mi = 0; mi < MI; mi++) {
        #pragma unroll
        for (int ni = 0; ni < NI; ni++) {
            const int r0 = bm + wm * WROWS + mi * 16 + (lane >> 2);
            const int c0 = bn + wn * WCOLS + ni * 8 + (lane & 3) * 2;
            #pragma unroll
            for (int hh = 0; hh < 2; hh++) {
                const int r = r0 + hh * 8;
                float v0 = acc[mi][ni][hh * 2 + 0];
                float v1 = acc[mi][ni][hh * 2 + 1];
                if (FLAGS & F_BIAS) { v0 += bias[c0]; v1 += bias[c0 + 1]; }
                if (FLAGS & F_RELU) { v0 = fmaxf(v0, 0.f); v1 = fmaxf(v1, 0.f); }
                if (FLAGS & F_SOFT) {
                    v0 = (v0 > 20.f) ? v0 : log1pf(expf(v0));
                    v1 = (v1 > 20.f) ? v1 : log1pf(expf(v1));
                }
                if (FLAGS & F_RES) {
                    float2 rr = *(const float2*)(res + (size_t)r * N + c0);
                    v0 += rr.x; v1 += rr.y;
                }
                if (FLAGS & F_WF32) {
                    *(float2*)(Cf + (size_t)r * N + c0) = make_float2(v0, v1);
                }
                if (FLAGS & F_WPAIR) {
                    __nv_bfloat16 h0, h1, l0, l1;
                    split2(v0, h0, l0); split2(v1, h1, l1);
                    *(__nv_bfloat162*)(Ch + (size_t)r * N + c0) = __nv_bfloat162{h0, h1};
                    *(__nv_bfloat162*)(Cl + (size_t)r * N + c0) = __nv_bfloat162{l0, l1};
                }
            }
        }
    }
}

// ===================== host orchestration =================================
template <int BM, int BN, int WGM, int WGN, int NWARP, int STAGES, int FLAGS>
static void launch_tgemm(int M, int N, int K, int lda, int ldb,
                         const __nv_bfloat16* Ah, const __nv_bfloat16* Al,
                         const __nv_bfloat16* Bh, const __nv_bfloat16* Bl,
                         const float* bias, const float* res,
                         float* Cf, __nv_bfloat16* Ch, __nv_bfloat16* Cl) {
    constexpr int PITCH = 80;
    constexpr int STAGE = 2 * BM * PITCH + 2 * BN * PITCH;
    const int smem_bytes = STAGES * STAGE;
    cudaFuncSetAttribute(tgemm<BM, BN, WGM, WGN, NWARP, STAGES, FLAGS>,
                         cudaFuncAttributeMaxDynamicSharedMemorySize, smem_bytes);
    dim3 grid(N / BN, M / BM);
    tgemm<BM, BN, WGM, WGN, NWARP, STAGES, FLAGS>
        <<<grid, NWARP * 32, smem_bytes>>>(M, N, K, lda, ldb,
        Ah, Al, Bh, Bl, bias, res, Cf, Ch, Cl);
}

extern "C" void kernel_launch(void* const* d_in, const int* in_sizes, int n_in,
                              void* d_out, int out_size) {
    const int*   idx   = (const int*)d_in[0];
    const float* tok   = (const float*)d_in[1];
    const float* pos   = (const float*)d_in[2];
    const float* ln1g  = (const float*)d_in[3];
    const float* ln1b  = (const float*)d_in[4];
    const float* W_in  = (const float*)d_in[5];
    const float* convw = (const float*)d_in[6];
    const float* convb = (const float*)d_in[7];
    const float* W_xp  = (const float*)d_in[8];
    const float* W_dt  = (const float*)d_in[9];
    const float* b_dt  = (const float*)d_in[10];
    const float* A_log = (const float*)d_in[11];
    const float* D_p   = (const float*)d_in[12];
    const float* W_out = (const float*)d_in[13];
    const float* ln2g  = (const float*)d_in[14];
    const float* ln2b  = (const float*)d_in[15];
    const float* W_f1  = (const float*)d_in[16];
    const float* b_f1  = (const float*)d_in[17];
    const float* W_f2  = (const float*)d_in[18];
    const float* b_f2  = (const float*)d_in[19];
    const float* lm_w  = (const float*)d_in[20];
    const float* lm_b  = (const float*)d_in[21];
    float* out = (float*)d_out;

    float *px, *pxz, *pu, *pxd, *pdt;
    __nv_bfloat16 *phh, *phl, *puh, *pul, *pxdh, *pxdl, *pyh, *pyl;
    __nv_bfloat16 *phidh, *phidl, *pxh, *pxl;
    __nv_bfloat16 *wInh, *wInl, *wXph, *wXpl, *wDth, *wDtl, *wOuth, *wOutl;
    __nv_bfloat16 *wF1h, *wF1l, *wF2h, *wF2l, *wLmh, *wLml;

    cudaGetSymbolAddress((void**)&px,   g_x);
    cudaGetSymbolAddress((void**)&pxz,  g_xz);
    cudaGetSymbolAddress((void**)&pu,   g_u);
    cudaGetSymbolAddress((void**)&pxd,  g_xdbl);
    cudaGetSymbolAddress((void**)&pdt,  g_dt);
    cudaGetSymbolAddress((void**)&phh,  g_hh);  cudaGetSymbolAddress((void**)&phl,  g_hl);
    cudaGetSymbolAddress((void**)&puh,  g_uh);  cudaGetSymbolAddress((void**)&pul,  g_ul);
    cudaGetSymbolAddress((void**)&pxdh, g_xdh); cudaGetSymbolAddress((void**)&pxdl, g_xdl);
    cudaGetSymbolAddress((void**)&pyh,  g_yh);  cudaGetSymbolAddress((void**)&pyl,  g_yl);
    cudaGetSymbolAddress((void**)&phidh,g_hidh);cudaGetSymbolAddress((void**)&phidl,g_hidl);
    cudaGetSymbolAddress((void**)&pxh,  g_xh);  cudaGetSymbolAddress((void**)&pxl,  g_xl);
    cudaGetSymbolAddress((void**)&wInh, g_Winh); cudaGetSymbolAddress((void**)&wInl, g_Winl);
    cudaGetSymbolAddress((void**)&wXph, g_Wxph); cudaGetSymbolAddress((void**)&wXpl, g_Wxpl);
    cudaGetSymbolAddress((void**)&wDth, g_Wdth); cudaGetSymbolAddress((void**)&wDtl, g_Wdtl);
    cudaGetSymbolAddress((void**)&wOuth,g_Wouth);cudaGetSymbolAddress((void**)&wOutl,g_Woutl);
    cudaGetSymbolAddress((void**)&wF1h, g_Wf1h); cudaGetSymbolAddress((void**)&wF1l, g_Wf1l);
    cudaGetSymbolAddress((void**)&wF2h, g_Wf2h); cudaGetSymbolAddress((void**)&wF2l, g_Wf2l);
    cudaGetSymbolAddress((void**)&wLmh, g_lmh);  cudaGetSymbolAddress((void**)&wLml, g_lml);

    auto split = [&](const float* src, __nv_bfloat16* h, __nv_bfloat16* l, long n) {
        int n4 = (int)(n / 4);
        split_kernel<<<(n4 + 255) / 256, 256>>>(src, h, l, n4);
    };

    split(W_in,  wInh,  wInl,  (long)LYR * 2048 * DD);
    split(W_xp,  wXph,  wXpl,  (long)LYR * 64 * DI_);
    split(W_dt,  wDth,  wDtl,  (long)LYR * DI_ * 32);
    split(W_out, wOuth, wOutl, (long)LYR * DD * DI_);
    split(W_f1,  wF1h,  wF1l,  (long)LYR * 2048 * DD);
    split(W_f2,  wF2h,  wF2l,  (long)LYR * DD * 2048);
    split(lm_w,  wLmh,  wLml,  (long)VOC * DD);

    embed_kernel<<<1024, 256>>>(idx, tok, pos);

    for (int l = 0; l < LYR; l++) {
        ln_kernel<<<MTOK, 128>>>(px, ln1g + l * DD, ln1b + l * DD, phh, phl);
        // xz = h @ W_in^T  [2048,2048]  — big tile, 16 warps
        launch_tgemm<128, 256, 4, 4, 16, 3, F_WF32>(MTOK, 2048, DD, DD, DD,
            phh, phl, wInh + (long)l * 2048 * DD, wInl + (long)l * 2048 * DD,
            nullptr, nullptr, pxz, nullptr, nullptr);
        conv_silu_kernel<<<MTOK * DI_ / 256, 256>>>(convw + l * DI_ * 4, convb + l * DI_);
        launch_tgemm<64, 64, 4, 4, 16, 4, F_WF32 | F_WPAIR>(MTOK, 64, DI_, DI_, DI_,
            puh, pul, wXph + (long)l * 64 * DI_, wXpl + (long)l * 64 * DI_,
            nullptr, nullptr, pxd, pxdh, pxdl);
        launch_tgemm<128, 128, 4, 4, 16, 4, F_BIAS | F_SOFT | F_WF32>(
            MTOK, DI_, 32, 64, 32,
            pxdh, pxdl, wDth + (long)l * DI_ * 32, wDtl + (long)l * DI_ * 32,
            b_dt + l * DI_, nullptr, pdt, nullptr, nullptr);
        scan_p1<<<dim3(8, NCH, 2), 128>>>(A_log + (long)l * DI_ * DS_);
        scan_p2<<<dim3(8, 2), 128>>>();
        scan_p3<<<dim3(8, NCH, 2), 128>>>(A_log + (long)l * DI_ * DS_, D_p + l * DI_);
        launch_tgemm<64, 128, 2, 8, 16, 4, F_RES | F_WF32>(MTOK, DD, DI_, DI_, DI_,
            pyh, pyl, wOuth + (long)l * DD * DI_, wOutl + (long)l * DD * DI_,
            nullptr, px, px, nullptr, nullptr);
        ln_kernel<<<MTOK, 128>>>(px, ln2g + l * DD, ln2b + l * DD, phh, phl);
        // hidden = relu(h @ W_f1^T + b_f1)  [2048,2048] — big tile, 16 warps
        launch_tgemm<128, 256, 4, 4, 16, 3, F_BIAS | F_RELU | F_WPAIR>(
            MTOK, 2048, DD, DD, DD,
            phh, phl, wF1h + (long)l * 2048 * DD, wF1l + (long)l * 2048 * DD,
            b_f1 + l * 2048, nullptr, nullptr, phidh, phidl);
        launch_tgemm<64, 128, 2, 8, 16, 4, F_BIAS | F_RES | F_WF32 | F_WPAIR>(
            MTOK, DD, 2048, 2048, 2048,
            phidh, phidl, wF2h + (long)l * DD * 2048, wF2l + (long)l * DD * 2048,
            b_f2 + l * DD, px, px, pxh, pxl);
    }

    // logits = x @ lm_w^T + lm_b  [2048,32000] — big tile, 16 warps
    launch_tgemm<128, 256, 4, 4, 16, 3, F_BIAS | F_WF32>(MTOK, VOC, DD, DD, DD,
        pxh, pxl, wLmh, wLml, lm_b, nullptr, out, nullptr, nullptr);
}

// round 10
// speedup vs baseline: 4.4502x; 1.2932x over previous
#include <cuda_runtime.h>
#include <cuda_fp16.h>
#include <math.h>
#include <stdint.h>

#define MTOK 2048
#define TT   1024
#define DD   512
#define DI_  1024
#define DS_  16
#define LYR  4
#define VOC  32000
#define TC   64
#define NCH  16

// Weights are stored pre-scaled by 32 so the lo half stays in fp16 normal
// range; the GEMM epilogue multiplies the accumulator by 1/32.
#define WSCALE 32.0f
#define WSCALE_INV 0.03125f

// ===================== PTX helpers (plain sm_103-safe) =====================
__device__ __forceinline__ uint32_t smem_u32(const void* p) {
    uint32_t a;
    asm("{ .reg .u64 t; cvta.to.shared.u64 t, %1; cvt.u32.u64 %0, t; }"
        : "=r"(a) : "l"(p));
    return a;
}
#define CP16(dst, src) \
    asm volatile("cp.async.cg.shared.global [%0], [%1], 16;" \
                 :: "r"(dst), "l"(src) : "memory")
#define CP_COMMIT() asm volatile("cp.async.commit_group;" ::: "memory")
template <int n>
__device__ __forceinline__ void cp_wait() {
    asm volatile("cp.async.wait_group %0;" :: "n"(n) : "memory");
}

__device__ __forceinline__ void ldsm4(uint32_t* r, uint32_t addr) {
    asm volatile("ldmatrix.sync.aligned.m8n8.x4.shared.b16 {%0,%1,%2,%3}, [%4];"
                 : "=r"(r[0]), "=r"(r[1]), "=r"(r[2]), "=r"(r[3]) : "r"(addr));
}
__device__ __forceinline__ void mma16816(float* d, const uint32_t* a,
                                         const uint32_t* b) {
    asm volatile(
        "mma.sync.aligned.m16n8k16.row.col.f32.f16.f16.f32 "
        "{%0,%1,%2,%3}, {%4,%5,%6,%7}, {%8,%9}, {%0,%1,%2,%3};"
        : "+f"(d[0]), "+f"(d[1]), "+f"(d[2]), "+f"(d[3])
        : "r"(a[0]), "r"(a[1]), "r"(a[2]), "r"(a[3]), "r"(b[0]), "r"(b[1]));
}

__device__ __forceinline__ void wsplit2(float v, __half& h, __half& l) {
    float sv = v * WSCALE;
    h = __float2half_rn(sv);
    l = __float2half_rn(sv - __half2float(h));
}

// ===================== device-global scratch ==============================
__device__ __align__(256) float g_x   [MTOK * DD];
__device__ __align__(256) float g_xz  [MTOK * 2048];
__device__ __align__(256) float g_u   [MTOK * DI_];
__device__ __align__(256) float g_xdbl[MTOK * 64];
__device__ __align__(256) float g_dt  [MTOK * DI_];

__device__ __align__(256) float g_sD [2 * NCH * DI_ * DS_];
__device__ __align__(256) float g_sV [2 * NCH * DI_ * DS_];
__device__ __align__(256) float g_hin[2 * NCH * DI_ * DS_];

// fp16 activations (single precision copy for GEMM A operands)
__device__ __align__(256) __half g_hh  [MTOK * DD];
__device__ __align__(256) __half g_uh  [MTOK * DI_];
__device__ __align__(256) __half g_xdh [MTOK * 64];
__device__ __align__(256) __half g_yh  [MTOK * DI_];
__device__ __align__(256) __half g_hidh[MTOK * 2048];
__device__ __align__(256) __half g_xh  [MTOK * DD];

// fp16 hi/lo weights (pre-scaled by 32)
__device__ __align__(256) __half g_Winh [LYR * 2048 * DD];
__device__ __align__(256) __half g_Winl [LYR * 2048 * DD];
__device__ __align__(256) __half g_Wxph [LYR * 64 * DI_];
__device__ __align__(256) __half g_Wxpl [LYR * 64 * DI_];
__device__ __align__(256) __half g_Wdth [LYR * DI_ * 32];
__device__ __align__(256) __half g_Wdtl [LYR * DI_ * 32];
__device__ __align__(256) __half g_Wouth[LYR * DD * DI_];
__device__ __align__(256) __half g_Woutl[LYR * DD * DI_];
__device__ __align__(256) __half g_Wf1h [LYR * 2048 * DD];
__device__ __align__(256) __half g_Wf1l [LYR * 2048 * DD];
__device__ __align__(256) __half g_Wf2h [LYR * DD * 2048];
__device__ __align__(256) __half g_Wf2l [LYR * DD * 2048];
__device__ __align__(256) __half g_lmh  [VOC * DD];
__device__ __align__(256) __half g_lml  [VOC * DD];

// ===================== small kernels ======================================
__global__ void embed_kernel(const int* __restrict__ idx,
                             const float* __restrict__ tok,
                             const float* __restrict__ pos) {
    int i = blockIdx.x * 256 + threadIdx.x;
    int token = i >> 7;
    int c = i & 127;
    int t = token & (TT - 1);
    int row = idx[token];
    float4 a = ((const float4*)tok)[row * 128 + c];
    float4 p = ((const float4*)pos)[t * 128 + c];
    a.x += p.x; a.y += p.y; a.z += p.z; a.w += p.w;
    ((float4*)g_x)[i] = a;
}

__global__ void wsplit_kernel(const float* __restrict__ in,
                              __half* __restrict__ hi,
                              __half* __restrict__ lo, int n4) {
    int i = blockIdx.x * 256 + threadIdx.x;
    if (i >= n4) return;
    float4 v = ((const float4*)in)[i];
    __half h0, h1, h2, h3, l0, l1, l2, l3;
    wsplit2(v.x, h0, l0); wsplit2(v.y, h1, l1);
    wsplit2(v.z, h2, l2); wsplit2(v.w, h3, l3);
    ((__half2*)hi)[i * 2 + 0] = __half2{h0, h1};
    ((__half2*)hi)[i * 2 + 1] = __half2{h2, h3};
    ((__half2*)lo)[i * 2 + 0] = __half2{l0, l1};
    ((__half2*)lo)[i * 2 + 1] = __half2{l2, l3};
}

__global__ void ln_kernel(const float* __restrict__ x,
                          const float* __restrict__ g,
                          const float* __restrict__ bta,
                          __half* __restrict__ oh) {
    int token = blockIdx.x;
    int tid = threadIdx.x;
    float4 v = ((const float4*)(x + token * DD))[tid];
    float s = v.x + v.y + v.z + v.w;
    __shared__ float red[8];
    #pragma unroll
    for (int o = 16; o > 0; o >>= 1) s += __shfl_xor_sync(0xffffffffu, s, o);
    if ((tid & 31) == 0) red[tid >> 5] = s;
    __syncthreads();
    float mean = (red[0] + red[1] + red[2] + red[3]) * (1.0f / 512.0f);
    float dx = v.x - mean, dy = v.y - mean, dz = v.z - mean, dw = v.w - mean;
    float q = dx * dx + dy * dy + dz * dz + dw * dw;
    #pragma unroll
    for (int o = 16; o > 0; o >>= 1) q += __shfl_xor_sync(0xffffffffu, q, o);
    if ((tid & 31) == 0) red[4 + (tid >> 5)] = q;
    __syncthreads();
    float var = (red[4] + red[5] + red[6] + red[7]) * (1.0f / 512.0f);
    float r = rsqrtf(var + 1e-5f);
    float4 gg = ((const float4*)g)[tid];
    float4 bb = ((const float4*)bta)[tid];
    float o0 = dx * r * gg.x + bb.x, o1 = dy * r * gg.y + bb.y;
    float o2 = dz * r * gg.z + bb.z, o3 = dw * r * gg.w + bb.w;
    ((__half2*)(oh + token * DD))[tid * 2 + 0] =
        __half2{__float2half_rn(o0), __float2half_rn(o1)};
    ((__half2*)(oh + token * DD))[tid * 2 + 1] =
        __half2{__float2half_rn(o2), __float2half_rn(o3)};
}

__global__ void conv_silu_kernel(const float* __restrict__ w,
                                 const float* __restrict__ cb) {
    int i = blockIdx.x * 256 + threadIdx.x;
    int token = i >> 10;
    int d = i & (DI_ - 1);
    int t = token & (TT - 1);
    float acc = cb[d];
    #pragma unroll
    for (int j = 0; j < 4; j++) {
        int tt = t - 3 + j;
        if (tt >= 0) acc += g_xz[(token - 3 + j) * 2048 + d] * w[d * 4 + j];
    }
    float sg = 1.0f / (1.0f + __expf(-acc));
    float uv = acc * sg;
    g_u[i] = uv;
    g_uh[i] = __float2half_rn(uv);
}

// ======== chunked selective scan (3 phases) ===============================
__device__ __forceinline__ void powers16(float r, float* p) {
    float r2 = r * r, r4 = r2 * r2, r8 = r4 * r4;
    p[0] = r;        p[1] = r2;       p[2] = r2 * r;   p[3] = r4;
    p[4] = r4 * r;   p[5] = r4 * r2;  p[6] = r4 * p[2]; p[7] = r8;
    p[8] = r8 * r;   p[9] = r8 * r2;  p[10] = r8 * p[2]; p[11] = r8 * r4;
    p[12] = r8 * p[4]; p[13] = r8 * p[5]; p[14] = r8 * p[6]; p[15] = r8 * r8;
}

__global__ void scan_p1(const float* __restrict__ A_log) {
    __shared__ float sB[TC][16];
    const int d = blockIdx.x * 128 + threadIdx.x;
    const int ch = blockIdx.y, b = blockIdx.z;
    const int t0 = ch * TC;
    for (int i = threadIdx.x; i < TC * 16; i += 128) {
        int tt = i >> 4, s = i & 15;
        sB[tt][s] = g_xdbl[(size_t)(b * TT + t0 + tt) * 64 + 32 + s];
    }
    __syncthreads();
    float es[16]; bool fast = true;
    #pragma unroll
    for (int s = 0; s < 16; s++) {
        es[s] = expf(A_log[d * 16 + s]);
        fast = fast && (fabsf(es[s] - (float)(s + 1)) < 1e-3f);
    }
    float h[16];
    #pragma unroll
    for (int s = 0; s < 16; s++) h[s] = 0.0f;
    float S = 0.0f;
    const float* pdt = g_dt + (size_t)(b * TT + t0) * DI_ + d;
    const float* pu  = g_u  + (size_t)(b * TT + t0) * DI_ + d;
    if (fast) {
        for (int t = 0; t < TC; t++) {
            float dt = pdt[t * DI_], u = pu[t * DI_];
            S += dt;
            float x = dt * u;
            float p[16]; powers16(__expf(-dt), p);
            #pragma unroll
            for (int s = 0; s < 16; s++) h[s] = p[s] * h[s] + x * sB[t][s];
        }
    } else {
        for (int t = 0; t < TC; t++) {
            float dt = pdt[t * DI_], u = pu[t * DI_];
            S += dt;
            float x = dt * u;
            #pragma unroll
            for (int s = 0; s < 16; s++)
                h[s] = __expf(-dt * es[s]) * h[s] + x * sB[t][s];
        }
    }
    size_t o = (((size_t)b * NCH + ch) * DI_ + d) * 16;
    #pragma unroll
    for (int s = 0; s < 16; s++) {
        g_sV[o + s] = h[s];
        g_sD[o + s] = __expf(-S * es[s]);
    }
}

__global__ void scan_p2() {
    const int d = blockIdx.x * 128 + threadIdx.x;
    const int b = blockIdx.y;
    float h[16];
    #pragma unroll
    for (int s = 0; s < 16; s++) h[s] = 0.0f;
    for (int ch = 0; ch < NCH; ch++) {
        size_t o = (((size_t)b * NCH + ch) * DI_ + d) * 16;
        #pragma unroll
        for (int s = 0; s < 16; s++) g_hin[o + s] = h[s];
        #pragma unroll
        for (int s = 0; s < 16; s++) h[s] = g_sD[o + s] * h[s] + g_sV[o + s];
    }
}

__global__ void scan_p3(const float* __restrict__ A_log,
                        const float* __restrict__ D_p) {
    __shared__ float sB[TC][16], sC[TC][16];
    const int d = blockIdx.x * 128 + threadIdx.x;
    const int ch = blockIdx.y, b = blockIdx.z;
    const int t0 = ch * TC;
    for (int i = threadIdx.x; i < TC * 16; i += 128) {
        int tt = i >> 4, s = i & 15;
        size_t base = (size_t)(b * TT + t0 + tt) * 64;
        sB[tt][s] = g_xdbl[base + 32 + s];
        sC[tt][s] = g_xdbl[base + 48 + s];
    }
    __syncthreads();
    float es[16]; bool fast = true;
    #pragma unroll
    for (int s = 0; s < 16; s++) {
        es[s] = expf(A_log[d * 16 + s]);
        fast = fast && (fabsf(es[s] - (float)(s + 1)) < 1e-3f);
    }
    float h[16];
    {
        size_t o = (((size_t)b * NCH + ch) * DI_ + d) * 16;
        #pragma unroll
        for (int s = 0; s < 16; s++) h[s] = g_hin[o + s];
    }
    const float Dp = D_p[d];
    const float* pdt = g_dt + (size_t)(b * TT + t0) * DI_ + d;
    const float* pu  = g_u  + (size_t)(b * TT + t0) * DI_ + d;
    const float* pz  = g_xz + (size_t)(b * TT + t0) * 2048 + DI_ + d;
    __half* pyh = g_yh + (size_t)(b * TT + t0) * DI_ + d;
    for (int t = 0; t < TC; t++) {
        float dt = pdt[t * DI_], u = pu[t * DI_], z = pz[t * 2048];
        float x = dt * u;
        float p[16];
        if (fast) powers16(__expf(-dt), p);
        else {
            #pragma unroll
            for (int s = 0; s < 16; s++) p[s] = __expf(-dt * es[s]);
        }
        #pragma unroll
        for (int s = 0; s < 16; s++) h[s] = p[s] * h[s] + x * sB[t][s];
        float q[8];
        #pragma unroll
        for (int i = 0; i < 8; i++)
            q[i] = fmaf(h[2 * i], sC[t][2 * i], h[2 * i + 1] * sC[t][2 * i + 1]);
        float yp = ((q[0] + q[1]) + (q[2] + q[3])) + ((q[4] + q[5]) + (q[6] + q[7]));
        float yv = yp + u * Dp;
        float ov = yv * (z / (1.0f + __expf(-z)));
        pyh[t * DI_] = __float2half_rn(ov);
    }
}

// ===================== HMMA fp16 2-term GEMM (multi-stage) ================
// C[M,N] = (A_fp16 @ (Wh + Wl)^T) / 32, fp32 accum.
#define F_BIAS 1
#define F_RELU 2
#define F_SOFT 4
#define F_RES  8
#define F_WF32 16
#define F_WHALF 32

template <int BM, int BN, int WGM, int WGN, int NWARP, int STAGES, int FLAGS>
__global__ __launch_bounds__(NWARP * 32) void tgemm(
    int M, int N, int K, int lda, int ldb,
    const __half* __restrict__ A,
    const __half* __restrict__ Bh, const __half* __restrict__ Bl,
    const float* __restrict__ bias, const float* __restrict__ res,
    float* __restrict__ Cf, __half* __restrict__ Ch) {
    extern __shared__ char smem[];
    constexpr int NT = NWARP * 32;
    constexpr int PITCH = 80;
    constexpr int ASZ = BM * PITCH;
    constexpr int BSZ = BN * PITCH;
    constexpr int STAGE = ASZ + 2 * BSZ;
    constexpr int WROWS = BM / WGM, WCOLS = BN / WGN;
    constexpr int MI = WROWS / 16, NI = WCOLS / 8, NP = NI / 2;
    const int tid = threadIdx.x, lane = tid & 31, wid = tid >> 5;
    const int wm = wid / WGN, wn = wid % WGN;
    const int bm = blockIdx.y * BM, bn = blockIdx.x * BN;
    const uint32_t sb = smem_u32(smem);
    const int nc = K / 32;

    float acc[MI][NI][4];
    #pragma unroll
    for (int i = 0; i < MI; i++)
        #pragma unroll
        for (int j = 0; j < NI; j++)
            #pragma unroll
            for (int q = 0; q < 4; q++) acc[i][j][q] = 0.0f;

    auto prefetch = [&](int c, int slot) {
        if (c >= nc) return;
        const uint32_t sbase = sb + slot * STAGE;
        const int k0 = c * 32;
        #pragma unroll
        for (int i = 0; i < (BM * 4 + NT - 1) / NT; i++) {
            int ch = tid + i * NT;
            if ((BM * 4 % NT == 0) || ch < BM * 4) {
                int row = ch >> 2, kc = ch & 3;
                uint32_t doff = row * PITCH + kc * 16;
                size_t goff = (size_t)(bm + row) * lda + k0 + kc * 8;
                CP16(sbase + doff, (const char*)(A + goff));
            }
        }
        #pragma unroll
        for (int i = 0; i < (BN * 4 + NT - 1) / NT; i++) {
            int ch = tid + i * NT;
            if ((BN * 4 % NT == 0) || ch < BN * 4) {
                int row = ch >> 2, kc = ch & 3;
                uint32_t doff = row * PITCH + kc * 16;
                size_t goff = (size_t)(bn + row) * ldb + k0 + kc * 8;
                CP16(sbase + ASZ + doff, (const char*)(Bh + goff));
                CP16(sbase + ASZ + BSZ + doff, (const char*)(Bl + goff));
            }
        }
    };

    auto compute = [&](int s) {
        const uint32_t sbase = sb + s * STAGE;
        const uint32_t arow = (uint32_t)(lane & 15);
        const uint32_t asel = (uint32_t)((lane >> 4) * 16);
        #pragma unroll
        for (int kk = 0; kk < 2; kk++) {
            const uint32_t kb = kk * 32;
            uint32_t a[MI][4];
            #pragma unroll
            for (int mi = 0; mi < MI; mi++) {
                uint32_t ad = sbase + (wm * WROWS + mi * 16 + arow) * PITCH + kb + asel;
                ldsm4(a[mi], ad);
            }
            #pragma unroll
            for (int p = 0; p < NP; p++) {
                uint32_t bd = sbase + ASZ +
                              (wn * WCOLS + p * 16 + arow) * PITCH + kb + asel;
                uint32_t th[4], tl[4];
                ldsm4(th, bd);
                ldsm4(tl, bd + BSZ);
                uint32_t bh0[2] = {th[0], th[2]}, bh1[2] = {th[1], th[3]};
                uint32_t bl0[2] = {tl[0], tl[2]}, bl1[2] = {tl[1], tl[3]};
                #pragma unroll
                for (int mi = 0; mi < MI; mi++) {
                    mma16816(acc[mi][2 * p], a[mi], bh0);
                    mma16816(acc[mi][2 * p], a[mi], bl0);
                    mma16816(acc[mi][2 * p + 1], a[mi], bh1);
                    mma16816(acc[mi][2 * p + 1], a[mi], bl1);
                }
            }
        }
    };

    #pragma unroll
    for (int c = 0; c < STAGES - 1; c++) { prefetch(c, c); CP_COMMIT(); }
    int ps = (STAGES - 1) % STAGES, cs = 0;
    for (int c = 0; c < nc; c++) {
        cp_wait<STAGES - 2>();
        __syncthreads();
        prefetch(c + STAGES - 1, ps); CP_COMMIT();
        compute(cs);
        ps = (ps + 1 == STAGES) ? 0 : ps + 1;
        cs = (cs + 1 == STAGES) ? 0 : cs + 1;
    }

    // ---- epilogue: unscale + fused ops + direct fragment stores ----
    #pragma unroll
    for (int mi = 0; mi < MI; mi++) {
        #pragma unroll
        for (int ni = 0; ni < NI; ni++) {
            const int r0 = bm + wm * WROWS + mi * 16 + (lane >> 2);
            const int c0 = bn + wn * WCOLS + ni * 8 + (lane & 3) * 2;
            #pragma unroll
            for (int hh = 0; hh < 2; hh++) {
                const int r = r0 + hh * 8;
                float v0 = acc[mi][ni][hh * 2 + 0] * WSCALE_INV;
                float v1 = acc[mi][ni][hh * 2 + 1] * WSCALE_INV;
                if (FLAGS & F_BIAS) { v0 += bias[c0]; v1 += bias[c0 + 1]; }
                if (FLAGS & F_RELU) { v0 = fmaxf(v0, 0.f); v1 = fmaxf(v1, 0.f); }
                if (FLAGS & F_SOFT) {
                    v0 = (v0 > 20.f) ? v0 : log1pf(expf(v0));
                    v1 = (v1 > 20.f) ? v1 : log1pf(expf(v1));
                }
                if (FLAGS & F_RES) {
                    float2 rr = *(const float2*)(res + (size_t)r * N + c0);
                    v0 += rr.x; v1 += rr.y;
                }
                if (FLAGS & F_WF32) {
                    *(float2*)(Cf + (size_t)r * N + c0) = make_float2(v0, v1);
                }
                if (FLAGS & F_WHALF) {
                    *(__half2*)(Ch + (size_t)r * N + c0) =
                        __half2{__float2half_rn(v0), __float2half_rn(v1)};
                }
            }
        }
    }
}

// ===================== host orchestration =================================
template <int BM, int BN, int WGM, int WGN, int NWARP, int STAGES, int FLAGS>
static void launch_tgemm(int M, int N, int K, int lda, int ldb,
                         const __half* A, const __half* Bh, const __half* Bl,
                         const float* bias, const float* res,
                         float* Cf, __half* Ch) {
    constexpr int PITCH = 80;
    constexpr int STAGE = BM * PITCH + 2 * BN * PITCH;
    const int smem_bytes = STAGES * STAGE;
    cudaFuncSetAttribute(tgemm<BM, BN, WGM, WGN, NWARP, STAGES, FLAGS>,
                         cudaFuncAttributeMaxDynamicSharedMemorySize, smem_bytes);
    dim3 grid(N / BN, M / BM);
    tgemm<BM, BN, WGM, WGN, NWARP, STAGES, FLAGS>
        <<<grid, NWARP * 32, smem_bytes>>>(M, N, K, lda, ldb,
        A, Bh, Bl, bias, res, Cf, Ch);
}

extern "C" void kernel_launch(void* const* d_in, const int* in_sizes, int n_in,
                              void* d_out, int out_size) {
    const int*   idx   = (const int*)d_in[0];
    const float* tok   = (const float*)d_in[1];
    const float* pos   = (const float*)d_in[2];
    const float* ln1g  = (const float*)d_in[3];
    const float* ln1b  = (const float*)d_in[4];
    const float* W_in  = (const float*)d_in[5];
    const float* convw = (const float*)d_in[6];
    const float* convb = (const float*)d_in[7];
    const float* W_xp  = (const float*)d_in[8];
    const float* W_dt  = (const float*)d_in[9];
    const float* b_dt  = (const float*)d_in[10];
    const float* A_log = (const float*)d_in[11];
    const float* D_p   = (const float*)d_in[12];
    const float* W_out = (const float*)d_in[13];
    const float* ln2g  = (const float*)d_in[14];
    const float* ln2b  = (const float*)d_in[15];
    const float* W_f1  = (const float*)d_in[16];
    const float* b_f1  = (const float*)d_in[17];
    const float* W_f2  = (const float*)d_in[18];
    const float* b_f2  = (const float*)d_in[19];
    const float* lm_w  = (const float*)d_in[20];
    const float* lm_b  = (const float*)d_in[21];
    float* out = (float*)d_out;

    float *px, *pxz, *pu, *pxd, *pdt;
    __half *phh, *puh, *pxdh, *pyh, *phidh, *pxh;
    __half *wInh, *wInl, *wXph, *wXpl, *wDth, *wDtl, *wOuth, *wOutl;
    __half *wF1h, *wF1l, *wF2h, *wF2l, *wLmh, *wLml;

    cudaGetSymbolAddress((void**)&px,   g_x);
    cudaGetSymbolAddress((void**)&pxz,  g_xz);
    cudaGetSymbolAddress((void**)&pu,   g_u);
    cudaGetSymbolAddress((void**)&pxd,  g_xdbl);
    cudaGetSymbolAddress((void**)&pdt,  g_dt);
    cudaGetSymbolAddress((void**)&phh,  g_hh);
    cudaGetSymbolAddress((void**)&puh,  g_uh);
    cudaGetSymbolAddress((void**)&pxdh, g_xdh);
    cudaGetSymbolAddress((void**)&pyh,  g_yh);
    cudaGetSymbolAddress((void**)&phidh,g_hidh);
    cudaGetSymbolAddress((void**)&pxh,  g_xh);
    cudaGetSymbolAddress((void**)&wInh, g_Winh); cudaGetSymbolAddress((void**)&wInl, g_Winl);
    cudaGetSymbolAddress((void**)&wXph, g_Wxph); cudaGetSymbolAddress((void**)&wXpl, g_Wxpl);
    cudaGetSymbolAddress((void**)&wDth, g_Wdth); cudaGetSymbolAddress((void**)&wDtl, g_Wdtl);
    cudaGetSymbolAddress((void**)&wOuth,g_Wouth);cudaGetSymbolAddress((void**)&wOutl,g_Woutl);
    cudaGetSymbolAddress((void**)&wF1h, g_Wf1h); cudaGetSymbolAddress((void**)&wF1l, g_Wf1l);
    cudaGetSymbolAddress((void**)&wF2h, g_Wf2h); cudaGetSymbolAddress((void**)&wF2l, g_Wf2l);
    cudaGetSymbolAddress((void**)&wLmh, g_lmh);  cudaGetSymbolAddress((void**)&wLml, g_lml);

    auto split = [&](const float* src, __half* h, __half* l, long n) {
        int n4 = (int)(n / 4);
        wsplit_kernel<<<(n4 + 255) / 256, 256>>>(src, h, l, n4);
    };

    split(W_in,  wInh,  wInl,  (long)LYR * 2048 * DD);
    split(W_xp,  wXph,  wXpl,  (long)LYR * 64 * DI_);
    split(W_dt,  wDth,  wDtl,  (long)LYR * DI_ * 32);
    split(W_out, wOuth, wOutl, (long)LYR * DD * DI_);
    split(W_f1,  wF1h,  wF1l,  (long)LYR * 2048 * DD);
    split(W_f2,  wF2h,  wF2l,  (long)LYR * DD * 2048);
    split(lm_w,  wLmh,  wLml,  (long)VOC * DD);

    embed_kernel<<<1024, 256>>>(idx, tok, pos);

    for (int l = 0; l < LYR; l++) {
        ln_kernel<<<MTOK, 128>>>(px, ln1g + l * DD, ln1b + l * DD, phh);
        // xz = h @ W_in^T  [2048,2048]
        launch_tgemm<128, 256, 4, 4, 16, 3, F_WF32>(MTOK, 2048, DD, DD, DD,
            phh, wInh + (long)l * 2048 * DD, wInl + (long)l * 2048 * DD,
            nullptr, nullptr, pxz, nullptr);
        conv_silu_kernel<<<MTOK * DI_ / 256, 256>>>(convw + l * DI_ * 4, convb + l * DI_);
        launch_tgemm<64, 64, 4, 4, 16, 4, F_WF32 | F_WHALF>(MTOK, 64, DI_, DI_, DI_,
            puh, wXph + (long)l * 64 * DI_, wXpl + (long)l * 64 * DI_,
            nullptr, nullptr, pxd, pxdh);
        launch_tgemm<128, 128, 4, 4, 16, 4, F_BIAS | F_SOFT | F_WF32>(
            MTOK, DI_, 32, 64, 32,
            pxdh, wDth + (long)l * DI_ * 32, wDtl + (long)l * DI_ * 32,
            b_dt + l * DI_, nullptr, pdt, nullptr);
        scan_p1<<<dim3(8, NCH, 2), 128>>>(A_log + (long)l * DI_ * DS_);
        scan_p2<<<dim3(8, 2), 128>>>();
        scan_p3<<<dim3(8, NCH, 2), 128>>>(A_log + (long)l * DI_ * DS_, D_p + l * DI_);
        launch_tgemm<64, 128, 2, 8, 16, 4, F_RES | F_WF32>(MTOK, DD, DI_, DI_, DI_,
            pyh, wOuth + (long)l * DD * DI_, wOutl + (long)l * DD * DI_,
            nullptr, px, px, nullptr);
        ln_kernel<<<MTOK, 128>>>(px, ln2g + l * DD, ln2b + l * DD, phh);
        // hidden = relu(h @ W_f1^T + b_f1)  [2048,2048]
        launch_tgemm<128, 256, 4, 4, 16, 3, F_BIAS | F_RELU | F_WHALF>(
            MTOK, 2048, DD, DD, DD,
            phh, wF1h + (long)l * 2048 * DD, wF1l + (long)l * 2048 * DD,
            b_f1 + l * 2048, nullptr, nullptr, phidh);
        launch_tgemm<64, 128, 2, 8, 16, 4, F_BIAS | F_RES | F_WF32 | F_WHALF>(
            MTOK, DD, 2048, 2048, 2048,
            phidh, wF2h + (long)l * DD * 2048, wF2l + (long)l * DD * 2048,
            b_f2 + l * DD, px, px, pxh);
    }

    // logits = x @ lm_w^T + lm_b  [2048,32000]
    launch_tgemm<128, 256, 4, 4, 16, 3, F_BIAS | F_WF32>(MTOK, VOC, DD, DD, DD,
        pxh, wLmh, wLml, lm_b, nullptr, out, nullptr);
}

// round 11
// speedup vs baseline: 6.1891x; 1.3908x over previous
#include <cuda_runtime.h>
#include <cuda_fp16.h>
#include <math.h>
#include <stdint.h>

#define MTOK 2048
#define TT   1024
#define DD   512
#define DI_  1024
#define DS_  16
#define LYR  4
#define VOC  32000
#define TC   64
#define NCH  16

// Weights stored pre-scaled by 32 (keeps small weights in fp16 normal range);
// GEMM epilogue multiplies the fp32 accumulator by 1/32.
#define WSCALE 32.0f
#define WSCALE_INV 0.03125f

// ===================== PTX helpers (plain sm_103-safe) =====================
__device__ __forceinline__ uint32_t smem_u32(const void* p) {
    uint32_t a;
    asm("{ .reg .u64 t; cvta.to.shared.u64 t, %1; cvt.u32.u64 %0, t; }"
        : "=r"(a) : "l"(p));
    return a;
}
#define CP16(dst, src) \
    asm volatile("cp.async.cg.shared.global [%0], [%1], 16;" \
                 :: "r"(dst), "l"(src) : "memory")
#define CP_COMMIT() asm volatile("cp.async.commit_group;" ::: "memory")
template <int n>
__device__ __forceinline__ void cp_wait() {
    asm volatile("cp.async.wait_group %0;" :: "n"(n) : "memory");
}

__device__ __forceinline__ void ldsm4(uint32_t* r, uint32_t addr) {
    asm volatile("ldmatrix.sync.aligned.m8n8.x4.shared.b16 {%0,%1,%2,%3}, [%4];"
                 : "=r"(r[0]), "=r"(r[1]), "=r"(r[2]), "=r"(r[3]) : "r"(addr));
}
__device__ __forceinline__ void mma16816(float* d, const uint32_t* a,
                                         const uint32_t* b) {
    asm volatile(
        "mma.sync.aligned.m16n8k16.row.col.f32.f16.f16.f32 "
        "{%0,%1,%2,%3}, {%4,%5,%6,%7}, {%8,%9}, {%0,%1,%2,%3};"
        : "+f"(d[0]), "+f"(d[1]), "+f"(d[2]), "+f"(d[3])
        : "r"(a[0]), "r"(a[1]), "r"(a[2]), "r"(a[3]), "r"(b[0]), "r"(b[1]));
}

// ===================== device-global scratch ==============================
__device__ __align__(256) float g_x   [MTOK * DD];
__device__ __align__(256) float g_xz  [MTOK * 2048];
__device__ __align__(256) float g_u   [MTOK * DI_];
__device__ __align__(256) float g_xdbl[MTOK * 64];
__device__ __align__(256) float g_dt  [MTOK * DI_];

__device__ __align__(256) float g_sD [2 * NCH * DI_ * DS_];
__device__ __align__(256) float g_sV [2 * NCH * DI_ * DS_];
__device__ __align__(256) float g_hin[2 * NCH * DI_ * DS_];

// fp16 activations
__device__ __align__(256) __half g_hh  [MTOK * DD];
__device__ __align__(256) __half g_uh  [MTOK * DI_];
__device__ __align__(256) __half g_xdh [MTOK * 64];
__device__ __align__(256) __half g_yh  [MTOK * DI_];
__device__ __align__(256) __half g_hidh[MTOK * 2048];
__device__ __align__(256) __half g_xh  [MTOK * DD];

// fp16 weights (pre-scaled by 32)
__device__ __align__(256) __half g_Winh [LYR * 2048 * DD];
__device__ __align__(256) __half g_Wxph [LYR * 64 * DI_];
__device__ __align__(256) __half g_Wdth [LYR * DI_ * 32];
__device__ __align__(256) __half g_Wouth[LYR * DD * DI_];
__device__ __align__(256) __half g_Wf1h [LYR * 2048 * DD];
__device__ __align__(256) __half g_Wf2h [LYR * DD * 2048];
__device__ __align__(256) __half g_lmh  [VOC * DD];

// ===================== small kernels ======================================
__global__ void embed_kernel(const int* __restrict__ idx,
                             const float* __restrict__ tok,
                             const float* __restrict__ pos) {
    int i = blockIdx.x * 256 + threadIdx.x;
    int token = i >> 7;
    int c = i & 127;
    int t = token & (TT - 1);
    int row = idx[token];
    float4 a = ((const float4*)tok)[row * 128 + c];
    float4 p = ((const float4*)pos)[t * 128 + c];
    a.x += p.x; a.y += p.y; a.z += p.z; a.w += p.w;
    ((float4*)g_x)[i] = a;
}

__global__ void wconv_kernel(const float* __restrict__ in,
                             __half* __restrict__ hi, int n4) {
    int i = blockIdx.x * 256 + threadIdx.x;
    if (i >= n4) return;
    float4 v = ((const float4*)in)[i];
    ((__half2*)hi)[i * 2 + 0] =
        __half2{__float2half_rn(v.x * WSCALE), __float2half_rn(v.y * WSCALE)};
    ((__half2*)hi)[i * 2 + 1] =
        __half2{__float2half_rn(v.z * WSCALE), __float2half_rn(v.w * WSCALE)};
}

__global__ void ln_kernel(const float* __restrict__ x,
                          const float* __restrict__ g,
                          const float* __restrict__ bta,
                          __half* __restrict__ oh) {
    int token = blockIdx.x;
    int tid = threadIdx.x;
    float4 v = ((const float4*)(x + token * DD))[tid];
    float s = v.x + v.y + v.z + v.w;
    __shared__ float red[8];
    #pragma unroll
    for (int o = 16; o > 0; o >>= 1) s += __shfl_xor_sync(0xffffffffu, s, o);
    if ((tid & 31) == 0) red[tid >> 5] = s;
    __syncthreads();
    float mean = (red[0] + red[1] + red[2] + red[3]) * (1.0f / 512.0f);
    float dx = v.x - mean, dy = v.y - mean, dz = v.z - mean, dw = v.w - mean;
    float q = dx * dx + dy * dy + dz * dz + dw * dw;
    #pragma unroll
    for (int o = 16; o > 0; o >>= 1) q += __shfl_xor_sync(0xffffffffu, q, o);
    if ((tid & 31) == 0) red[4 + (tid >> 5)] = q;
    __syncthreads();
    float var = (red[4] + red[5] + red[6] + red[7]) * (1.0f / 512.0f);
    float r = rsqrtf(var + 1e-5f);
    float4 gg = ((const float4*)g)[tid];
    float4 bb = ((const float4*)bta)[tid];
    float o0 = dx * r * gg.x + bb.x, o1 = dy * r * gg.y + bb.y;
    float o2 = dz * r * gg.z + bb.z, o3 = dw * r * gg.w + bb.w;
    ((__half2*)(oh + token * DD))[tid * 2 + 0] =
        __half2{__float2half_rn(o0), __float2half_rn(o1)};
    ((__half2*)(oh + token * DD))[tid * 2 + 1] =
        __half2{__float2half_rn(o2), __float2half_rn(o3)};
}

__global__ void conv_silu_kernel(const float* __restrict__ w,
                                 const float* __restrict__ cb) {
    int i = blockIdx.x * 256 + threadIdx.x;
    int token = i >> 10;
    int d = i & (DI_ - 1);
    int t = token & (TT - 1);
    float acc = cb[d];
    #pragma unroll
    for (int j = 0; j < 4; j++) {
        int tt = t - 3 + j;
        if (tt >= 0) acc += g_xz[(token - 3 + j) * 2048 + d] * w[d * 4 + j];
    }
    float sg = 1.0f / (1.0f + __expf(-acc));
    float uv = acc * sg;
    g_u[i] = uv;
    g_uh[i] = __float2half_rn(uv);
}

// ======== chunked selective scan (3 phases) ===============================
__device__ __forceinline__ void powers16(float r, float* p) {
    float r2 = r * r, r4 = r2 * r2, r8 = r4 * r4;
    p[0] = r;        p[1] = r2;       p[2] = r2 * r;   p[3] = r4;
    p[4] = r4 * r;   p[5] = r4 * r2;  p[6] = r4 * p[2]; p[7] = r8;
    p[8] = r8 * r;   p[9] = r8 * r2;  p[10] = r8 * p[2]; p[11] = r8 * r4;
    p[12] = r8 * p[4]; p[13] = r8 * p[5]; p[14] = r8 * p[6]; p[15] = r8 * r8;
}

__global__ void scan_p1(const float* __restrict__ A_log) {
    __shared__ float sB[TC][16];
    const int d = blockIdx.x * 128 + threadIdx.x;
    const int ch = blockIdx.y, b = blockIdx.z;
    const int t0 = ch * TC;
    for (int i = threadIdx.x; i < TC * 16; i += 128) {
        int tt = i >> 4, s = i & 15;
        sB[tt][s] = g_xdbl[(size_t)(b * TT + t0 + tt) * 64 + 32 + s];
    }
    __syncthreads();
    float es[16]; bool fast = true;
    #pragma unroll
    for (int s = 0; s < 16; s++) {
        es[s] = expf(A_log[d * 16 + s]);
        fast = fast && (fabsf(es[s] - (float)(s + 1)) < 1e-3f);
    }
    float h[16];
    #pragma unroll
    for (int s = 0; s < 16; s++) h[s] = 0.0f;
    float S = 0.0f;
    const float* pdt = g_dt + (size_t)(b * TT + t0) * DI_ + d;
    const float* pu  = g_u  + (size_t)(b * TT + t0) * DI_ + d;
    if (fast) {
        for (int t = 0; t < TC; t++) {
            float dt = pdt[t * DI_], u = pu[t * DI_];
            S += dt;
            float x = dt * u;
            float p[16]; powers16(__expf(-dt), p);
            #pragma unroll
            for (int s = 0; s < 16; s++) h[s] = p[s] * h[s] + x * sB[t][s];
        }
    } else {
        for (int t = 0; t < TC; t++) {
            float dt = pdt[t * DI_], u = pu[t * DI_];
            S += dt;
            float x = dt * u;
            #pragma unroll
            for (int s = 0; s < 16; s++)
                h[s] = __expf(-dt * es[s]) * h[s] + x * sB[t][s];
        }
    }
    size_t o = (((size_t)b * NCH + ch) * DI_ + d) * 16;
    #pragma unroll
    for (int s = 0; s < 16; s++) {
        g_sV[o + s] = h[s];
        g_sD[o + s] = __expf(-S * es[s]);
    }
}

__global__ void scan_p2() {
    const int d = blockIdx.x * 128 + threadIdx.x;
    const int b = blockIdx.y;
    float h[16];
    #pragma unroll
    for (int s = 0; s < 16; s++) h[s] = 0.0f;
    for (int ch = 0; ch < NCH; ch++) {
        size_t o = (((size_t)b * NCH + ch) * DI_ + d) * 16;
        #pragma unroll
        for (int s = 0; s < 16; s++) g_hin[o + s] = h[s];
        #pragma unroll
        for (int s = 0; s < 16; s++) h[s] = g_sD[o + s] * h[s] + g_sV[o + s];
    }
}

__global__ void scan_p3(const float* __restrict__ A_log,
                        const float* __restrict__ D_p) {
    __shared__ float sB[TC][16], sC[TC][16];
    const int d = blockIdx.x * 128 + threadIdx.x;
    const int ch = blockIdx.y, b = blockIdx.z;
    const int t0 = ch * TC;
    for (int i = threadIdx.x; i < TC * 16; i += 128) {
        int tt = i >> 4, s = i & 15;
        size_t base = (size_t)(b * TT + t0 + tt) * 64;
        sB[tt][s] = g_xdbl[base + 32 + s];
        sC[tt][s] = g_xdbl[base + 48 + s];
    }
    __syncthreads();
    float es[16]; bool fast = true;
    #pragma unroll
    for (int s = 0; s < 16; s++) {
        es[s] = expf(A_log[d * 16 + s]);
        fast = fast && (fabsf(es[s] - (float)(s + 1)) < 1e-3f);
    }
    float h[16];
    {
        size_t o = (((size_t)b * NCH + ch) * DI_ + d) * 16;
        #pragma unroll
        for (int s = 0; s < 16; s++) h[s] = g_hin[o + s];
    }
    const float Dp = D_p[d];
    const float* pdt = g_dt + (size_t)(b * TT + t0) * DI_ + d;
    const float* pu  = g_u  + (size_t)(b * TT + t0) * DI_ + d;
    const float* pz  = g_xz + (size_t)(b * TT + t0) * 2048 + DI_ + d;
    __half* pyh = g_yh + (size_t)(b * TT + t0) * DI_ + d;
    for (int t = 0; t < TC; t++) {
        float dt = pdt[t * DI_], u = pu[t * DI_], z = pz[t * 2048];
        float x = dt * u;
        float p[16];
        if (fast) powers16(__expf(-dt), p);
        else {
            #pragma unroll
            for (int s = 0; s < 16; s++) p[s] = __expf(-dt * es[s]);
        }
        #pragma unroll
        for (int s = 0; s < 16; s++) h[s] = p[s] * h[s] + x * sB[t][s];
        float q[8];
        #pragma unroll
        for (int i = 0; i < 8; i++)
            q[i] = fmaf(h[2 * i], sC[t][2 * i], h[2 * i + 1] * sC[t][2 * i + 1]);
        float yp = ((q[0] + q[1]) + (q[2] + q[3])) + ((q[4] + q[5]) + (q[6] + q[7]));
        float yv = yp + u * Dp;
        float ov = yv * (z / (1.0f + __expf(-z)));
        pyh[t * DI_] = __float2half_rn(ov);
    }
}

// ===================== HMMA fp16 GEMM (multi-stage) =======================
// C[M,N] = (A_fp16 @ W_fp16^T) / 32, fp32 accum.
#define F_BIAS 1
#define F_RELU 2
#define F_SOFT 4
#define F_RES  8
#define F_WF32 16
#define F_WHALF 32

template <int BM, int BN, int WGM, int WGN, int NWARP, int STAGES, int FLAGS>
__global__ __launch_bounds__(NWARP * 32) void tgemm(
    int M, int N, int K, int lda, int ldb,
    const __half* __restrict__ A, const __half* __restrict__ Bw,
    const float* __restrict__ bias, const float* __restrict__ res,
    float* __restrict__ Cf, __half* __restrict__ Ch) {
    extern __shared__ char smem[];
    constexpr int NT = NWARP * 32;
    constexpr int PITCH = 80;
    constexpr int ASZ = BM * PITCH;
    constexpr int BSZ = BN * PITCH;
    constexpr int STAGE = ASZ + BSZ;
    constexpr int WROWS = BM / WGM, WCOLS = BN / WGN;
    constexpr int MI = WROWS / 16, NI = WCOLS / 8, NP = NI / 2;
    const int tid = threadIdx.x, lane = tid & 31, wid = tid >> 5;
    const int wm = wid / WGN, wn = wid % WGN;
    const int bm = blockIdx.y * BM, bn = blockIdx.x * BN;
    const uint32_t sb = smem_u32(smem);
    const int nc = K / 32;

    float acc[MI][NI][4];
    #pragma unroll
    for (int i = 0; i < MI; i++)
        #pragma unroll
        for (int j = 0; j < NI; j++)
            #pragma unroll
            for (int q = 0; q < 4; q++) acc[i][j][q] = 0.0f;

    auto prefetch = [&](int c, int slot) {
        if (c >= nc) return;
        const uint32_t sbase = sb + slot * STAGE;
        const int k0 = c * 32;
        #pragma unroll
        for (int i = 0; i < (BM * 4 + NT - 1) / NT; i++) {
            int ch = tid + i * NT;
            if ((BM * 4 % NT == 0) || ch < BM * 4) {
                int row = ch >> 2, kc = ch & 3;
                uint32_t doff = row * PITCH + kc * 16;
                size_t goff = (size_t)(bm + row) * lda + k0 + kc * 8;
                CP16(sbase + doff, (const char*)(A + goff));
            }
        }
        #pragma unroll
        for (int i = 0; i < (BN * 4 + NT - 1) / NT; i++) {
            int ch = tid + i * NT;
            if ((BN * 4 % NT == 0) || ch < BN * 4) {
                int row = ch >> 2, kc = ch & 3;
                uint32_t doff = row * PITCH + kc * 16;
                size_t goff = (size_t)(bn + row) * ldb + k0 + kc * 8;
                CP16(sbase + ASZ + doff, (const char*)(Bw + goff));
            }
        }
    };

    auto compute = [&](int s) {
        const uint32_t sbase = sb + s * STAGE;
        const uint32_t arow = (uint32_t)(lane & 15);
        const uint32_t asel = (uint32_t)((lane >> 4) * 16);
        #pragma unroll
        for (int kk = 0; kk < 2; kk++) {
            const uint32_t kb = kk * 32;
            uint32_t a[MI][4];
            #pragma unroll
            for (int mi = 0; mi < MI; mi++) {
                uint32_t ad = sbase + (wm * WROWS + mi * 16 + arow) * PITCH + kb + asel;
                ldsm4(a[mi], ad);
            }
            #pragma unroll
            for (int p = 0; p < NP; p++) {
                uint32_t bd = sbase + ASZ +
                              (wn * WCOLS + p * 16 + arow) * PITCH + kb + asel;
                uint32_t t4[4];
                ldsm4(t4, bd);
                uint32_t b0[2] = {t4[0], t4[2]}, b1[2] = {t4[1], t4[3]};
                #pragma unroll
                for (int mi = 0; mi < MI; mi++) {
                    mma16816(acc[mi][2 * p], a[mi], b0);
                    mma16816(acc[mi][2 * p + 1], a[mi], b1);
                }
            }
        }
    };

    #pragma unroll
    for (int c = 0; c < STAGES - 1; c++) { prefetch(c, c); CP_COMMIT(); }
    int ps = (STAGES - 1) % STAGES, cs = 0;
    for (int c = 0; c < nc; c++) {
        cp_wait<STAGES - 2>();
        __syncthreads();
        prefetch(c + STAGES - 1, ps); CP_COMMIT();
        compute(cs);
        ps = (ps + 1 == STAGES) ? 0 : ps + 1;
        cs = (cs + 1 == STAGES) ? 0 : cs + 1;
    }

    // ---- epilogue: unscale + fused ops + direct fragment stores ----
    #pragma unroll
    for (int mi = 0; mi < MI; mi++) {
        #pragma unroll
        for (int ni = 0; ni < NI; ni++) {
            const int r0 = bm + wm * WROWS + mi * 16 + (lane >> 2);
            const int c0 = bn + wn * WCOLS + ni * 8 + (lane & 3) * 2;
            #pragma unroll
            for (int hh = 0; hh < 2; hh++) {
                const int r = r0 + hh * 8;
                float v0 = acc[mi][ni][hh * 2 + 0] * WSCALE_INV;
                float v1 = acc[mi][ni][hh * 2 + 1] * WSCALE_INV;
                if (FLAGS & F_BIAS) { v0 += bias[c0]; v1 += bias[c0 + 1]; }
                if (FLAGS & F_RELU) { v0 = fmaxf(v0, 0.f); v1 = fmaxf(v1, 0.f); }
                if (FLAGS & F_SOFT) {
                    v0 = (v0 > 20.f) ? v0 : log1pf(expf(v0));
                    v1 = (v1 > 20.f) ? v1 : log1pf(expf(v1));
                }
                if (FLAGS & F_RES) {
                    float2 rr = *(const float2*)(res + (size_t)r * N + c0);
                    v0 += rr.x; v1 += rr.y;
                }
                if (FLAGS & F_WF32) {
                    *(float2*)(Cf + (size_t)r * N + c0) = make_float2(v0, v1);
                }
                if (FLAGS & F_WHALF) {
                    *(__half2*)(Ch + (size_t)r * N + c0) =
                        __half2{__float2half_rn(v0), __float2half_rn(v1)};
                }
            }
        }
    }
}

// ===================== host orchestration =================================
template <int BM, int BN, int WGM, int WGN, int NWARP, int STAGES, int FLAGS>
static void launch_tgemm(int M, int N, int K, int lda, int ldb,
                         const __half* A, const __half* Bw,
                         const float* bias, const float* res,
                         float* Cf, __half* Ch) {
    constexpr int PITCH = 80;
    constexpr int STAGE = BM * PITCH + BN * PITCH;
    const int smem_bytes = STAGES * STAGE;
    cudaFuncSetAttribute(tgemm<BM, BN, WGM, WGN, NWARP, STAGES, FLAGS>,
                         cudaFuncAttributeMaxDynamicSharedMemorySize, smem_bytes);
    dim3 grid(N / BN, M / BM);
    tgemm<BM, BN, WGM, WGN, NWARP, STAGES, FLAGS>
        <<<grid, NWARP * 32, smem_bytes>>>(M, N, K, lda, ldb,
        A, Bw, bias, res, Cf, Ch);
}

extern "C" void kernel_launch(void* const* d_in, const int* in_sizes, int n_in,
                              void* d_out, int out_size) {
    const int*   idx   = (const int*)d_in[0];
    const float* tok   = (const float*)d_in[1];
    const float* pos   = (const float*)d_in[2];
    const float* ln1g  = (const float*)d_in[3];
    const float* ln1b  = (const float*)d_in[4];
    const float* W_in  = (const float*)d_in[5];
    const float* convw = (const float*)d_in[6];
    const float* convb = (const float*)d_in[7];
    const float* W_xp  = (const float*)d_in[8];
    const float* W_dt  = (const float*)d_in[9];
    const float* b_dt  = (const float*)d_in[10];
    const float* A_log = (const float*)d_in[11];
    const float* D_p   = (const float*)d_in[12];
    const float* W_out = (const float*)d_in[13];
    const float* ln2g  = (const float*)d_in[14];
    const float* ln2b  = (const float*)d_in[15];
    const float* W_f1  = (const float*)d_in[16];
    const float* b_f1  = (const float*)d_in[17];
    const float* W_f2  = (const float*)d_in[18];
    const float* b_f2  = (const float*)d_in[19];
    const float* lm_w  = (const float*)d_in[20];
    const float* lm_b  = (const float*)d_in[21];
    float* out = (float*)d_out;

    float *px, *pxz, *pu, *pxd, *pdt;
    __half *phh, *puh, *pxdh, *pyh, *phidh, *pxh;
    __half *wIn, *wXp, *wDt, *wOut, *wF1, *wF2, *wLm;

    cudaGetSymbolAddress((void**)&px,   g_x);
    cudaGetSymbolAddress((void**)&pxz,  g_xz);
    cudaGetSymbolAddress((void**)&pu,   g_u);
    cudaGetSymbolAddress((void**)&pxd,  g_xdbl);
    cudaGetSymbolAddress((void**)&pdt,  g_dt);
    cudaGetSymbolAddress((void**)&phh,  g_hh);
    cudaGetSymbolAddress((void**)&puh,  g_uh);
    cudaGetSymbolAddress((void**)&pxdh, g_xdh);
    cudaGetSymbolAddress((void**)&pyh,  g_yh);
    cudaGetSymbolAddress((void**)&phidh,g_hidh);
    cudaGetSymbolAddress((void**)&pxh,  g_xh);
    cudaGetSymbolAddress((void**)&wIn,  g_Winh);
    cudaGetSymbolAddress((void**)&wXp,  g_Wxph);
    cudaGetSymbolAddress((void**)&wDt,  g_Wdth);
    cudaGetSymbolAddress((void**)&wOut, g_Wouth);
    cudaGetSymbolAddress((void**)&wF1,  g_Wf1h);
    cudaGetSymbolAddress((void**)&wF2,  g_Wf2h);
    cudaGetSymbolAddress((void**)&wLm,  g_lmh);

    auto wconv = [&](const float* src, __half* h, long n) {
        int n4 = (int)(n / 4);
        wconv_kernel<<<(n4 + 255) / 256, 256>>>(src, h, n4);
    };

    wconv(W_in,  wIn,  (long)LYR * 2048 * DD);
    wconv(W_xp,  wXp,  (long)LYR * 64 * DI_);
    wconv(W_dt,  wDt,  (long)LYR * DI_ * 32);
    wconv(W_out, wOut, (long)LYR * DD * DI_);
    wconv(W_f1,  wF1,  (long)LYR * 2048 * DD);
    wconv(W_f2,  wF2,  (long)LYR * DD * 2048);
    wconv(lm_w,  wLm,  (long)VOC * DD);

    embed_kernel<<<1024, 256>>>(idx, tok, pos);

    for (int l = 0; l < LYR; l++) {
        ln_kernel<<<MTOK, 128>>>(px, ln1g + l * DD, ln1b + l * DD, phh);
        // xz = h @ W_in^T  [2048,2048]
        launch_tgemm<128, 256, 4, 4, 16, 4, F_WF32>(MTOK, 2048, DD, DD, DD,
            phh, wIn + (long)l * 2048 * DD, nullptr, nullptr, pxz, nullptr);
        conv_silu_kernel<<<MTOK * DI_ / 256, 256>>>(convw + l * DI_ * 4, convb + l * DI_);
        launch_tgemm<64, 64, 4, 4, 16, 4, F_WF32 | F_WHALF>(MTOK, 64, DI_, DI_, DI_,
            puh, wXp + (long)l * 64 * DI_, nullptr, nullptr, pxd, pxdh);
        launch_tgemm<128, 128, 4, 4, 16, 4, F_BIAS | F_SOFT | F_WF32>(
            MTOK, DI_, 32, 64, 32,
            pxdh, wDt + (long)l * DI_ * 32, b_dt + l * DI_, nullptr, pdt, nullptr);
        scan_p1<<<dim3(8, NCH, 2), 128>>>(A_log + (long)l * DI_ * DS_);
        scan_p2<<<dim3(8, 2), 128>>>();
        scan_p3<<<dim3(8, NCH, 2), 128>>>(A_log + (long)l * DI_ * DS_, D_p + l * DI_);
        launch_tgemm<64, 128, 2, 8, 16, 4, F_RES | F_WF32>(MTOK, DD, DI_, DI_, DI_,
            pyh, wOut + (long)l * DD * DI_, nullptr, px, px, nullptr);
        ln_kernel<<<MTOK, 128>>>(px, ln2g + l * DD, ln2b + l * DD, phh);
        // hidden = relu(h @ W_f1^T + b_f1)  [2048,2048]
        launch_tgemm<128, 256, 4, 4, 16, 4, F_BIAS | F_RELU | F_WHALF>(
            MTOK, 2048, DD, DD, DD,
            phh, wF1 + (long)l * 2048 * DD, b_f1 + l * 2048, nullptr, nullptr, phidh);
        launch_tgemm<64, 128, 2, 8, 16, 4, F_BIAS | F_RES | F_WF32 | F_WHALF>(
            MTOK, DD, 2048, 2048, 2048,
            phidh, wF2 + (long)l * DD * 2048, b_f2 + l * DD, px, px, pxh);
    }

    // logits = x @ lm_w^T + lm_b  [2048,32000]
    launch_tgemm<128, 256, 4, 4, 16, 4, F_BIAS | F_WF32>(MTOK, VOC, DD, DD, DD,
        pxh, wLm, lm_b, nullptr, out, nullptr);
}

// round 12
// speedup vs baseline: 6.9272x; 1.1193x over previous
#include <cuda_runtime.h>
#include <cuda_fp16.h>
#include <math.h>
#include <stdint.h>

#define MTOK 2048
#define TT   1024
#define DD   512
#define DI_  1024
#define DS_  16
#define LYR  4
#define VOC  32000
#define TC   32
#define NCH  32

// Weights stored pre-scaled by 32 (keeps small weights in fp16 normal range);
// GEMM epilogue multiplies the fp32 accumulator by 1/32.
#define WSCALE 32.0f
#define WSCALE_INV 0.03125f

// ===================== PTX helpers (plain sm_103-safe) =====================
__device__ __forceinline__ uint32_t smem_u32(const void* p) {
    uint32_t a;
    asm("{ .reg .u64 t; cvta.to.shared.u64 t, %1; cvt.u32.u64 %0, t; }"
        : "=r"(a) : "l"(p));
    return a;
}
#define CP16(dst, src) \
    asm volatile("cp.async.cg.shared.global [%0], [%1], 16;" \
                 :: "r"(dst), "l"(src) : "memory")
#define CP_COMMIT() asm volatile("cp.async.commit_group;" ::: "memory")
template <int n>
__device__ __forceinline__ void cp_wait() {
    asm volatile("cp.async.wait_group %0;" :: "n"(n) : "memory");
}

__device__ __forceinline__ void ldsm4(uint32_t* r, uint32_t addr) {
    asm volatile("ldmatrix.sync.aligned.m8n8.x4.shared.b16 {%0,%1,%2,%3}, [%4];"
                 : "=r"(r[0]), "=r"(r[1]), "=r"(r[2]), "=r"(r[3]) : "r"(addr));
}
__device__ __forceinline__ void mma16816(float* d, const uint32_t* a,
                                         const uint32_t* b) {
    asm volatile(
        "mma.sync.aligned.m16n8k16.row.col.f32.f16.f16.f32 "
        "{%0,%1,%2,%3}, {%4,%5,%6,%7}, {%8,%9}, {%0,%1,%2,%3};"
        : "+f"(d[0]), "+f"(d[1]), "+f"(d[2]), "+f"(d[3])
        : "r"(a[0]), "r"(a[1]), "r"(a[2]), "r"(a[3]), "r"(b[0]), "r"(b[1]));
}

// ===================== device-global scratch ==============================
__device__ __align__(256) float g_x   [MTOK * DD];
__device__ __align__(256) float g_xz  [MTOK * 2048];
__device__ __align__(256) float g_u   [MTOK * DI_];
__device__ __align__(256) float g_xdbl[MTOK * 64];
__device__ __align__(256) float g_dt  [MTOK * DI_];
__device__ __align__(256) float g_xpart[4 * MTOK * 64];   // split-K partials

__device__ __align__(256) float g_sD [2 * NCH * DI_ * DS_];
__device__ __align__(256) float g_sV [2 * NCH * DI_ * DS_];

// fp16 activations
__device__ __align__(256) __half g_hh  [MTOK * DD];
__device__ __align__(256) __half g_uh  [MTOK * DI_];
__device__ __align__(256) __half g_xdh [MTOK * 64];
__device__ __align__(256) __half g_yh  [MTOK * DI_];
__device__ __align__(256) __half g_hidh[MTOK * 2048];
__device__ __align__(256) __half g_xh  [MTOK * DD];

// fp16 weights (pre-scaled by 32)
__device__ __align__(256) __half g_Winh [LYR * 2048 * DD];
__device__ __align__(256) __half g_Wxph [LYR * 64 * DI_];
__device__ __align__(256) __half g_Wdth [LYR * DI_ * 32];
__device__ __align__(256) __half g_Wouth[LYR * DD * DI_];
__device__ __align__(256) __half g_Wf1h [LYR * 2048 * DD];
__device__ __align__(256) __half g_Wf2h [LYR * DD * 2048];
__device__ __align__(256) __half g_lmh  [VOC * DD];

// ===================== small kernels ======================================
__global__ void embed_kernel(const int* __restrict__ idx,
                             const float* __restrict__ tok,
                             const float* __restrict__ pos) {
    int i = blockIdx.x * 256 + threadIdx.x;
    int token = i >> 7;
    int c = i & 127;
    int t = token & (TT - 1);
    int row = idx[token];
    float4 a = ((const float4*)tok)[row * 128 + c];
    float4 p = ((const float4*)pos)[t * 128 + c];
    a.x += p.x; a.y += p.y; a.z += p.z; a.w += p.w;
    ((float4*)g_x)[i] = a;
}

__global__ void wconv_kernel(const float* __restrict__ in,
                             __half* __restrict__ hi, int n4) {
    int i = blockIdx.x * 256 + threadIdx.x;
    if (i >= n4) return;
    float4 v = ((const float4*)in)[i];
    ((__half2*)hi)[i * 2 + 0] =
        __half2{__float2half_rn(v.x * WSCALE), __float2half_rn(v.y * WSCALE)};
    ((__half2*)hi)[i * 2 + 1] =
        __half2{__float2half_rn(v.z * WSCALE), __float2half_rn(v.w * WSCALE)};
}

__global__ void ln_kernel(const float* __restrict__ x,
                          const float* __restrict__ g,
                          const float* __restrict__ bta,
                          __half* __restrict__ oh) {
    int token = blockIdx.x;
    int tid = threadIdx.x;
    float4 v = ((const float4*)(x + token * DD))[tid];
    float s = v.x + v.y + v.z + v.w;
    __shared__ float red[8];
    #pragma unroll
    for (int o = 16; o > 0; o >>= 1) s += __shfl_xor_sync(0xffffffffu, s, o);
    if ((tid & 31) == 0) red[tid >> 5] = s;
    __syncthreads();
    float mean = (red[0] + red[1] + red[2] + red[3]) * (1.0f / 512.0f);
    float dx = v.x - mean, dy = v.y - mean, dz = v.z - mean, dw = v.w - mean;
    float q = dx * dx + dy * dy + dz * dz + dw * dw;
    #pragma unroll
    for (int o = 16; o > 0; o >>= 1) q += __shfl_xor_sync(0xffffffffu, q, o);
    if ((tid & 31) == 0) red[4 + (tid >> 5)] = q;
    __syncthreads();
    float var = (red[4] + red[5] + red[6] + red[7]) * (1.0f / 512.0f);
    float r = rsqrtf(var + 1e-5f);
    float4 gg = ((const float4*)g)[tid];
    float4 bb = ((const float4*)bta)[tid];
    float o0 = dx * r * gg.x + bb.x, o1 = dy * r * gg.y + bb.y;
    float o2 = dz * r * gg.z + bb.z, o3 = dw * r * gg.w + bb.w;
    ((__half2*)(oh + token * DD))[tid * 2 + 0] =
        __half2{__float2half_rn(o0), __float2half_rn(o1)};
    ((__half2*)(oh + token * DD))[tid * 2 + 1] =
        __half2{__float2half_rn(o2), __float2half_rn(o3)};
}

// conv: one thread = 4 consecutive tokens x 1 channel (MLP-7 loads)
__global__ void conv_silu_kernel(const float* __restrict__ w,
                                 const float* __restrict__ cb) {
    int i = blockIdx.x * 256 + threadIdx.x;   // (token_group, d)
    int tg = i >> 10;
    int d = i & (DI_ - 1);
    int token0 = tg << 2;
    int t0 = token0 & (TT - 1);
    const float* col = g_xz + d;
    float4 wv = *(const float4*)(w + d * 4);
    float bias = cb[d];
    float xm3 = 0.f, xm2 = 0.f, xm1 = 0.f;
    if (t0 != 0) {
        xm3 = col[(size_t)(token0 - 3) * 2048];
        xm2 = col[(size_t)(token0 - 2) * 2048];
        xm1 = col[(size_t)(token0 - 1) * 2048];
    }
    float x0 = col[(size_t)(token0 + 0) * 2048];
    float x1 = col[(size_t)(token0 + 1) * 2048];
    float x2 = col[(size_t)(token0 + 2) * 2048];
    float x3 = col[(size_t)(token0 + 3) * 2048];
    float o0 = bias + wv.x * xm3 + wv.y * xm2 + wv.z * xm1 + wv.w * x0;
    float o1 = bias + wv.x * xm2 + wv.y * xm1 + wv.z * x0 + wv.w * x1;
    float o2 = bias + wv.x * xm1 + wv.y * x0 + wv.z * x1 + wv.w * x2;
    float o3 = bias + wv.x * x0 + wv.y * x1 + wv.z * x2 + wv.w * x3;
    float u0 = o0 / (1.0f + __expf(-o0));
    float u1 = o1 / (1.0f + __expf(-o1));
    float u2 = o2 / (1.0f + __expf(-o2));
    float u3 = o3 / (1.0f + __expf(-o3));
    size_t base = (size_t)token0 * DI_ + d;
    g_u[base + 0 * DI_] = u0; g_u[base + 1 * DI_] = u1;
    g_u[base + 2 * DI_] = u2; g_u[base + 3 * DI_] = u3;
    g_uh[base + 0 * DI_] = __float2half_rn(u0);
    g_uh[base + 1 * DI_] = __float2half_rn(u1);
    g_uh[base + 2 * DI_] = __float2half_rn(u2);
    g_uh[base + 3 * DI_] = __float2half_rn(u3);
}

// split-K reduce for x_dbl: sum 4 partials -> fp32 + fp16
__global__ void xdbl_reduce_kernel() {
    int i = blockIdx.x * 256 + threadIdx.x;   // float4 index, 32768 total
    const float4* p = (const float4*)g_xpart;
    float4 a = p[i], b = p[i + 32768], c = p[i + 65536], e = p[i + 98304];
    float4 s;
    s.x = (a.x + b.x) + (c.x + e.x);
    s.y = (a.y + b.y) + (c.y + e.y);
    s.z = (a.z + b.z) + (c.z + e.z);
    s.w = (a.w + b.w) + (c.w + e.w);
    ((float4*)g_xdbl)[i] = s;
    ((__half2*)g_xdh)[i * 2 + 0] = __half2{__float2half_rn(s.x), __float2half_rn(s.y)};
    ((__half2*)g_xdh)[i * 2 + 1] = __half2{__float2half_rn(s.z), __float2half_rn(s.w)};
}

// ======== chunked selective scan (2 phases; p2 folded into p3) ============
__device__ __forceinline__ void powers16(float r, float* p) {
    float r2 = r * r, r4 = r2 * r2, r8 = r4 * r4;
    p[0] = r;        p[1] = r2;       p[2] = r2 * r;   p[3] = r4;
    p[4] = r4 * r;   p[5] = r4 * r2;  p[6] = r4 * p[2]; p[7] = r8;
    p[8] = r8 * r;   p[9] = r8 * r2;  p[10] = r8 * p[2]; p[11] = r8 * r4;
    p[12] = r8 * p[4]; p[13] = r8 * p[5]; p[14] = r8 * p[6]; p[15] = r8 * r8;
}

__global__ void scan_p1(const float* __restrict__ A_log) {
    __shared__ float sB[TC][16];
    const int d = blockIdx.x * 128 + threadIdx.x;
    const int ch = blockIdx.y, b = blockIdx.z;
    const int t0 = ch * TC;
    for (int i = threadIdx.x; i < TC * 16; i += 128) {
        int tt = i >> 4, s = i & 15;
        sB[tt][s] = g_xdbl[(size_t)(b * TT + t0 + tt) * 64 + 32 + s];
    }
    __syncthreads();
    float es[16]; bool fast = true;
    #pragma unroll
    for (int s = 0; s < 16; s++) {
        es[s] = expf(A_log[d * 16 + s]);
        fast = fast && (fabsf(es[s] - (float)(s + 1)) < 1e-3f);
    }
    float h[16];
    #pragma unroll
    for (int s = 0; s < 16; s++) h[s] = 0.0f;
    float S = 0.0f;
    const float* pdt = g_dt + (size_t)(b * TT + t0) * DI_ + d;
    const float* pu  = g_u  + (size_t)(b * TT + t0) * DI_ + d;

    float cd[4], cu[4];
    #pragma unroll
    for (int j = 0; j < 4; j++) { cd[j] = pdt[j * DI_]; cu[j] = pu[j * DI_]; }
    for (int tg = 0; tg < TC / 4; tg++) {
        float nd[4], nu[4];
        if (tg + 1 < TC / 4) {
            int t1 = (tg + 1) * 4;
            #pragma unroll
            for (int j = 0; j < 4; j++) {
                nd[j] = pdt[(t1 + j) * DI_]; nu[j] = pu[(t1 + j) * DI_];
            }
        }
        #pragma unroll
        for (int j = 0; j < 4; j++) {
            int t = tg * 4 + j;
            float dt = cd[j];
            S += dt;
            float x = dt * cu[j];
            float p[16];
            if (fast) powers16(__expf(-dt), p);
            else {
                #pragma unroll
                for (int s = 0; s < 16; s++) p[s] = __expf(-dt * es[s]);
            }
            #pragma unroll
            for (int s = 0; s < 16; s++) h[s] = p[s] * h[s] + x * sB[t][s];
        }
        if (tg + 1 < TC / 4) {
            #pragma unroll
            for (int j = 0; j < 4; j++) { cd[j] = nd[j]; cu[j] = nu[j]; }
        }
    }
    size_t o = (((size_t)b * NCH + ch) * DI_ + d) * 16;
    #pragma unroll
    for (int s = 0; s < 16; s++) {
        g_sV[o + s] = h[s];
        g_sD[o + s] = __expf(-S * es[s]);
    }
}

__global__ void scan_p3(const float* __restrict__ A_log,
                        const float* __restrict__ D_p) {
    __shared__ float sB[TC][16], sC[TC][16];
    const int d = blockIdx.x * 128 + threadIdx.x;
    const int ch = blockIdx.y, b = blockIdx.z;
    const int t0 = ch * TC;
    for (int i = threadIdx.x; i < TC * 16; i += 128) {
        int tt = i >> 4, s = i & 15;
        size_t base = (size_t)(b * TT + t0 + tt) * 64;
        sB[tt][s] = g_xdbl[base + 32 + s];
        sC[tt][s] = g_xdbl[base + 48 + s];
    }
    __syncthreads();
    float es[16]; bool fast = true;
    #pragma unroll
    for (int s = 0; s < 16; s++) {
        es[s] = expf(A_log[d * 16 + s]);
        fast = fast && (fabsf(es[s] - (float)(s + 1)) < 1e-3f);
    }
    // h_in: combine chunk summaries 0..ch-1 (was scan_p2)
    float h[16];
    #pragma unroll
    for (int s = 0; s < 16; s++) h[s] = 0.0f;
    for (int c = 0; c < ch; c++) {
        size_t o = (((size_t)b * NCH + c) * DI_ + d) * 16;
        #pragma unroll
        for (int s = 0; s < 16; s++) h[s] = g_sD[o + s] * h[s] + g_sV[o + s];
    }
    const float Dp = D_p[d];
    const float* pdt = g_dt + (size_t)(b * TT + t0) * DI_ + d;
    const float* pu  = g_u  + (size_t)(b * TT + t0) * DI_ + d;
    const float* pz  = g_xz + (size_t)(b * TT + t0) * 2048 + DI_ + d;
    __half* pyh = g_yh + (size_t)(b * TT + t0) * DI_ + d;

    float cd[4], cu[4], cz[4];
    #pragma unroll
    for (int j = 0; j < 4; j++) {
        cd[j] = pdt[j * DI_]; cu[j] = pu[j * DI_]; cz[j] = pz[j * 2048];
    }
    for (int tg = 0; tg < TC / 4; tg++) {
        float nd[4], nu[4], nz[4];
        if (tg + 1 < TC / 4) {
            int t1 = (tg + 1) * 4;
            #pragma unroll
            for (int j = 0; j < 4; j++) {
                nd[j] = pdt[(t1 + j) * DI_]; nu[j] = pu[(t1 + j) * DI_];
                nz[j] = pz[(t1 + j) * 2048];
            }
        }
        #pragma unroll
        for (int j = 0; j < 4; j++) {
            int t = tg * 4 + j;
            float dt = cd[j], u = cu[j], z = cz[j];
            float x = dt * u;
            float p[16];
            if (fast) powers16(__expf(-dt), p);
            else {
                #pragma unroll
                for (int s = 0; s < 16; s++) p[s] = __expf(-dt * es[s]);
            }
            #pragma unroll
            for (int s = 0; s < 16; s++) h[s] = p[s] * h[s] + x * sB[t][s];
            float q[8];
            #pragma unroll
            for (int i = 0; i < 8; i++)
                q[i] = fmaf(h[2 * i], sC[t][2 * i], h[2 * i + 1] * sC[t][2 * i + 1]);
            float yp = ((q[0] + q[1]) + (q[2] + q[3])) + ((q[4] + q[5]) + (q[6] + q[7]));
            float yv = yp + u * Dp;
            float ov = yv * (z / (1.0f + __expf(-z)));
            pyh[t * DI_] = __float2half_rn(ov);
        }
        if (tg + 1 < TC / 4) {
            #pragma unroll
            for (int j = 0; j < 4; j++) { cd[j] = nd[j]; cu[j] = nu[j]; cz[j] = nz[j]; }
        }
    }
}

// ===================== HMMA fp16 GEMM (multi-stage, optional split-K) =====
#define F_BIAS 1
#define F_RELU 2
#define F_SOFT 4
#define F_RES  8
#define F_WF32 16
#define F_WHALF 32

template <int BM, int BN, int WGM, int WGN, int NWARP, int STAGES, int FLAGS>
__global__ __launch_bounds__(NWARP * 32) void tgemm(
    int M, int N, int K, int lda, int ldb,
    const __half* __restrict__ A, const __half* __restrict__ Bw,
    const float* __restrict__ bias, const float* __restrict__ res,
    float* __restrict__ Cf, __half* __restrict__ Ch) {
    extern __shared__ char smem[];
    constexpr int NT = NWARP * 32;
    constexpr int PITCH = 80;
    constexpr int ASZ = BM * PITCH;
    constexpr int BSZ = BN * PITCH;
    constexpr int STAGE = ASZ + BSZ;
    constexpr int WROWS = BM / WGM, WCOLS = BN / WGN;
    constexpr int MI = WROWS / 16, NI = WCOLS / 8, NP = NI / 2;
    const int tid = threadIdx.x, lane = tid & 31, wid = tid >> 5;
    const int wm = wid / WGN, wn = wid % WGN;
    const int bm = blockIdx.y * BM, bn = blockIdx.x * BN;
    const int kbase = blockIdx.z * K;          // split-K offset (0 if grid.z==1)
    const uint32_t sb = smem_u32(smem);
    const int nc = K / 32;
    if (FLAGS & F_WF32) Cf += (size_t)blockIdx.z * M * N;

    float acc[MI][NI][4];
    #pragma unroll
    for (int i = 0; i < MI; i++)
        #pragma unroll
        for (int j = 0; j < NI; j++)
            #pragma unroll
            for (int q = 0; q < 4; q++) acc[i][j][q] = 0.0f;

    auto prefetch = [&](int c, int slot) {
        if (c >= nc) return;
        const uint32_t sbase = sb + slot * STAGE;
        const int k0 = kbase + c * 32;
        #pragma unroll
        for (int i = 0; i < (BM * 4 + NT - 1) / NT; i++) {
            int ch = tid + i * NT;
            if ((BM * 4 % NT == 0) || ch < BM * 4) {
                int row = ch >> 2, kc = ch & 3;
                uint32_t doff = row * PITCH + kc * 16;
                size_t goff = (size_t)(bm + row) * lda + k0 + kc * 8;
                CP16(sbase + doff, (const char*)(A + goff));
            }
        }
        #pragma unroll
        for (int i = 0; i < (BN * 4 + NT - 1) / NT; i++) {
            int ch = tid + i * NT;
            if ((BN * 4 % NT == 0) || ch < BN * 4) {
                int row = ch >> 2, kc = ch & 3;
                uint32_t doff = row * PITCH + kc * 16;
                size_t goff = (size_t)(bn + row) * ldb + k0 + kc * 8;
                CP16(sbase + ASZ + doff, (const char*)(Bw + goff));
            }
        }
    };

    auto compute = [&](int s) {
        const uint32_t sbase = sb + s * STAGE;
        const uint32_t arow = (uint32_t)(lane & 15);
        const uint32_t asel = (uint32_t)((lane >> 4) * 16);
        #pragma unroll
        for (int kk = 0; kk < 2; kk++) {
            const uint32_t kb = kk * 32;
            uint32_t a[MI][4];
            #pragma unroll
            for (int mi = 0; mi < MI; mi++) {
                uint32_t ad = sbase + (wm * WROWS + mi * 16 + arow) * PITCH + kb + asel;
                ldsm4(a[mi], ad);
            }
            #pragma unroll
            for (int p = 0; p < NP; p++) {
                uint32_t bd = sbase + ASZ +
                              (wn * WCOLS + p * 16 + arow) * PITCH + kb + asel;
                uint32_t t4[4];
                ldsm4(t4, bd);
                uint32_t b0[2] = {t4[0], t4[2]}, b1[2] = {t4[1], t4[3]};
                #pragma unroll
                for (int mi = 0; mi < MI; mi++) {
                    mma16816(acc[mi][2 * p], a[mi], b0);
                    mma16816(acc[mi][2 * p + 1], a[mi], b1);
                }
            }
        }
    };

    #pragma unroll
    for (int c = 0; c < STAGES - 1; c++) { prefetch(c, c); CP_COMMIT(); }
    int ps = (STAGES - 1) % STAGES, cs = 0;
    for (int c = 0; c < nc; c++) {
        cp_wait<STAGES - 2>();
        __syncthreads();
        prefetch(c + STAGES - 1, ps); CP_COMMIT();
        compute(cs);
        ps = (ps + 1 == STAGES) ? 0 : ps + 1;
        cs = (cs + 1 == STAGES) ? 0 : cs + 1;
    }

    // ---- epilogue: unscale + fused ops + direct fragment stores ----
    #pragma unroll
    for (int mi = 0; mi < MI; mi++) {
        #pragma unroll
        for (int ni = 0; ni < NI; ni++) {
            const int r0 = bm + wm * WROWS + mi * 16 + (lane >> 2);
            const int c0 = bn + wn * WCOLS + ni * 8 + (lane & 3) * 2;
            #pragma unroll
            for (int hh = 0; hh < 2; hh++) {
                const int r = r0 + hh * 8;
                float v0 = acc[mi][ni][hh * 2 + 0] * WSCALE_INV;
                float v1 = acc[mi][ni][hh * 2 + 1] * WSCALE_INV;
                if (FLAGS & F_BIAS) { v0 += bias[c0]; v1 += bias[c0 + 1]; }
                if (FLAGS & F_RELU) { v0 = fmaxf(v0, 0.f); v1 = fmaxf(v1, 0.f); }
                if (FLAGS & F_SOFT) {
                    v0 = (v0 > 20.f) ? v0 : log1pf(expf(v0));
                    v1 = (v1 > 20.f) ? v1 : log1pf(expf(v1));
                }
                if (FLAGS & F_RES) {
                    float2 rr = *(const float2*)(res + (size_t)r * N + c0);
                    v0 += rr.x; v1 += rr.y;
                }
                if (FLAGS & F_WF32) {
                    *(float2*)(Cf + (size_t)r * N + c0) = make_float2(v0, v1);
                }
                if (FLAGS & F_WHALF) {
                    *(__half2*)(Ch + (size_t)r * N + c0) =
                        __half2{__float2half_rn(v0), __float2half_rn(v1)};
                }
            }
        }
    }
}

// ===================== host orchestration =================================
template <int BM, int BN, int WGM, int WGN, int NWARP, int STAGES, int FLAGS>
static void launch_tgemm(int M, int N, int K, int lda, int ldb,
                         const __half* A, const __half* Bw,
                         const float* bias, const float* res,
                         float* Cf, __half* Ch, int KS = 1) {
    constexpr int PITCH = 80;
    constexpr int STAGE = BM * PITCH + BN * PITCH;
    const int smem_bytes = STAGES * STAGE;
    cudaFuncSetAttribute(tgemm<BM, BN, WGM, WGN, NWARP, STAGES, FLAGS>,
                         cudaFuncAttributeMaxDynamicSharedMemorySize, smem_bytes);
    dim3 grid(N / BN, M / BM, KS);
    tgemm<BM, BN, WGM, WGN, NWARP, STAGES, FLAGS>
        <<<grid, NWARP * 32, smem_bytes>>>(M, N, K / KS, lda, ldb,
        A, Bw, bias, res, Cf, Ch);
}

extern "C" void kernel_launch(void* const* d_in, const int* in_sizes, int n_in,
                              void* d_out, int out_size) {
    const int*   idx   = (const int*)d_in[0];
    const float* tok   = (const float*)d_in[1];
    const float* pos   = (const float*)d_in[2];
    const float* ln1g  = (const float*)d_in[3];
    const float* ln1b  = (const float*)d_in[4];
    const float* W_in  = (const float*)d_in[5];
    const float* convw = (const float*)d_in[6];
    const float* convb = (const float*)d_in[7];
    const float* W_xp  = (const float*)d_in[8];
    const float* W_dt  = (const float*)d_in[9];
    const float* b_dt  = (const float*)d_in[10];
    const float* A_log = (const float*)d_in[11];
    const float* D_p   = (const float*)d_in[12];
    const float* W_out = (const float*)d_in[13];
    const float* ln2g  = (const float*)d_in[14];
    const float* ln2b  = (const float*)d_in[15];
    const float* W_f1  = (const float*)d_in[16];
    const float* b_f1  = (const float*)d_in[17];
    const float* W_f2  = (const float*)d_in[18];
    const float* b_f2  = (const float*)d_in[19];
    const float* lm_w  = (const float*)d_in[20];
    const float* lm_b  = (const float*)d_in[21];
    float* out = (float*)d_out;

    float *px, *pxz, *pu, *pxd, *pdt, *pxpart;
    __half *phh, *puh, *pxdh, *pyh, *phidh, *pxh;
    __half *wIn, *wXp, *wDt, *wOut, *wF1, *wF2, *wLm;

    cudaGetSymbolAddress((void**)&px,   g_x);
    cudaGetSymbolAddress((void**)&pxz,  g_xz);
    cudaGetSymbolAddress((void**)&pu,   g_u);
    cudaGetSymbolAddress((void**)&pxd,  g_xdbl);
    cudaGetSymbolAddress((void**)&pdt,  g_dt);
    cudaGetSymbolAddress((void**)&pxpart, g_xpart);
    cudaGetSymbolAddress((void**)&phh,  g_hh);
    cudaGetSymbolAddress((void**)&puh,  g_uh);
    cudaGetSymbolAddress((void**)&pxdh, g_xdh);
    cudaGetSymbolAddress((void**)&pyh,  g_yh);
    cudaGetSymbolAddress((void**)&phidh,g_hidh);
    cudaGetSymbolAddress((void**)&pxh,  g_xh);
    cudaGetSymbolAddress((void**)&wIn,  g_Winh);
    cudaGetSymbolAddress((void**)&wXp,  g_Wxph);
    cudaGetSymbolAddress((void**)&wDt,  g_Wdth);
    cudaGetSymbolAddress((void**)&wOut, g_Wouth);
    cudaGetSymbolAddress((void**)&wF1,  g_Wf1h);
    cudaGetSymbolAddress((void**)&wF2,  g_Wf2h);
    cudaGetSymbolAddress((void**)&wLm,  g_lmh);

    auto wconv = [&](const float* src, __half* h, long n) {
        int n4 = (int)(n / 4);
        wconv_kernel<<<(n4 + 255) / 256, 256>>>(src, h, n4);
    };

    wconv(W_in,  wIn,  (long)LYR * 2048 * DD);
    wconv(W_xp,  wXp,  (long)LYR * 64 * DI_);
    wconv(W_dt,  wDt,  (long)LYR * DI_ * 32);
    wconv(W_out, wOut, (long)LYR * DD * DI_);
    wconv(W_f1,  wF1,  (long)LYR * 2048 * DD);
    wconv(W_f2,  wF2,  (long)LYR * DD * 2048);
    wconv(lm_w,  wLm,  (long)VOC * DD);

    embed_kernel<<<1024, 256>>>(idx, tok, pos);

    for (int l = 0; l < LYR; l++) {
        ln_kernel<<<MTOK, 128>>>(px, ln1g + l * DD, ln1b + l * DD, phh);
        // xz = h @ W_in^T  [2048,2048]
        launch_tgemm<128, 256, 4, 4, 16, 4, F_WF32>(MTOK, 2048, DD, DD, DD,
            phh, wIn + (long)l * 2048 * DD, nullptr, nullptr, pxz, nullptr);
        conv_silu_kernel<<<2048, 256>>>(convw + l * DI_ * 4, convb + l * DI_);
        // x_dbl = u @ W_xp^T  [2048,64]  — split-K=4 + reduce
        launch_tgemm<64, 64, 4, 4, 16, 4, F_WF32>(MTOK, 64, DI_, DI_, DI_,
            puh, wXp + (long)l * 64 * DI_, nullptr, nullptr, pxpart, nullptr, 4);
        xdbl_reduce_kernel<<<128, 256>>>();
        launch_tgemm<128, 128, 4, 4, 16, 4, F_BIAS | F_SOFT | F_WF32>(
            MTOK, DI_, 32, 64, 32,
            pxdh, wDt + (long)l * DI_ * 32, b_dt + l * DI_, nullptr, pdt, nullptr);
        scan_p1<<<dim3(8, NCH, 2), 128>>>(A_log + (long)l * DI_ * DS_);
        scan_p3<<<dim3(8, NCH, 2), 128>>>(A_log + (long)l * DI_ * DS_, D_p + l * DI_);
        launch_tgemm<64, 128, 2, 8, 16, 4, F_RES | F_WF32>(MTOK, DD, DI_, DI_, DI_,
            pyh, wOut + (long)l * DD * DI_, nullptr, px, px, nullptr);
        ln_kernel<<<MTOK, 128>>>(px, ln2g + l * DD, ln2b + l * DD, phh);
        // hidden = relu(h @ W_f1^T + b_f1)  [2048,2048]
        launch_tgemm<128, 256, 4, 4, 16, 4, F_BIAS | F_RELU | F_WHALF>(
            MTOK, 2048, DD, DD, DD,
            phh, wF1 + (long)l * 2048 * DD, b_f1 + l * 2048, nullptr, nullptr, phidh);
        launch_tgemm<64, 128, 2, 8, 16, 4, F_BIAS | F_RES | F_WF32 | F_WHALF>(
            MTOK, DD, 2048, 2048, 2048,
            phidh, wF2 + (long)l * DD * 2048, b_f2 + l * DD, px, px, pxh);
    }

    // logits = x @ lm_w^T + lm_b  [2048,32000]
    launch_tgemm<128, 256, 4, 4, 16, 4, F_BIAS | F_WF32>(MTOK, VOC, DD, DD, DD,
        pxh, wLm, lm_b, nullptr, out, nullptr);
}